// round 1
// baseline (speedup 1.0000x reference)
#include <cuda_runtime.h>
#include <math.h>

// Problem dimensions (fixed for this problem instance)
constexpr int Bc  = 2;
constexpr int TQc = 512;
constexpr int TKc = 8192;
constexpr int Dc  = 1024;
constexpr int NHc = 16;
constexpr int HDc = 64;

// Scratch buffers (allocation-free: __device__ globals)
__device__ float g_Qp[(size_t)Bc * TQc * Dc];   // projected Q   [B*TQ, D]
__device__ float g_Kp[(size_t)Bc * TKc * Dc];   // projected K   [B*TK, D]
__device__ float g_Vp[(size_t)Bc * TKc * Dc];   // projected V   [B*TK, D]
__device__ float g_At[(size_t)Bc * TQc * Dc];   // attention out [B*TQ, D]

// ---------------------------------------------------------------------------
// Tiled SGEMM (NT): C[M,N] = A'[M,K] * W[N,K]^T + bias[N]
//   A'[m,k] = A[m,k] (+ group additive bias per row, if HAS_ABIAS)
// BM=BN=128, BK=16, 256 threads, 8x8 per-thread microtile.
// ---------------------------------------------------------------------------
template <bool HAS_ABIAS>
__global__ __launch_bounds__(256, 2)
void gemm_nt_kernel(const float* __restrict__ A, const float* __restrict__ W,
                    const float* __restrict__ bias, float* __restrict__ C,
                    int M, int N, int K,
                    const float* __restrict__ abA, const float* __restrict__ abI,
                    const int* __restrict__ pNA, int Tk)
{
    constexpr int BM = 128, BN = 128, BK = 16;
    constexpr int LDA = BM + 4, LDB = BN + 4;
    __shared__ float As[BK * LDA];
    __shared__ float Bs[BK * LDB];

    const int tid = threadIdx.x;
    const int m0 = blockIdx.y * BM;
    const int n0 = blockIdx.x * BN;

    int na = 0;
    if (HAS_ABIAS) na = *pNA;

    const int ty = tid >> 4;   // 0..15
    const int tx = tid & 15;   // 0..15

    float acc[8][8];
#pragma unroll
    for (int i = 0; i < 8; i++)
#pragma unroll
        for (int j = 0; j < 8; j++) acc[i][j] = 0.f;

    for (int k0 = 0; k0 < K; k0 += BK) {
        // Load A tile (128 x 16) transposed into As[k][m]
#pragma unroll
        for (int l = 0; l < 2; l++) {
            int s  = tid + l * 256;   // 0..511
            int r  = s >> 2;          // row within tile 0..127
            int cg = s & 3;           // 4-col group 0..3
            int gm = m0 + r;
            int gk = k0 + cg * 4;
            float4 v = *reinterpret_cast<const float4*>(A + (size_t)gm * K + gk);
            if (HAS_ABIAS) {
                const float* ab = ((gm % Tk) < na) ? abA : abI;
                float4 bv = *reinterpret_cast<const float4*>(ab + gk);
                v.x += bv.x; v.y += bv.y; v.z += bv.z; v.w += bv.w;
            }
            As[(cg * 4 + 0) * LDA + r] = v.x;
            As[(cg * 4 + 1) * LDA + r] = v.y;
            As[(cg * 4 + 2) * LDA + r] = v.z;
            As[(cg * 4 + 3) * LDA + r] = v.w;
        }
        // Load W tile (128 x 16) transposed into Bs[k][n]
#pragma unroll
        for (int l = 0; l < 2; l++) {
            int s  = tid + l * 256;
            int r  = s >> 2;
            int cg = s & 3;
            int gn = n0 + r;
            int gk = k0 + cg * 4;
            float4 v = *reinterpret_cast<const float4*>(W + (size_t)gn * K + gk);
            Bs[(cg * 4 + 0) * LDB + r] = v.x;
            Bs[(cg * 4 + 1) * LDB + r] = v.y;
            Bs[(cg * 4 + 2) * LDB + r] = v.z;
            Bs[(cg * 4 + 3) * LDB + r] = v.w;
        }
        __syncthreads();

#pragma unroll
        for (int kk = 0; kk < BK; kk++) {
            float af[8], bf[8];
            float4 a0 = *reinterpret_cast<const float4*>(&As[kk * LDA + ty * 8]);
            float4 a1 = *reinterpret_cast<const float4*>(&As[kk * LDA + ty * 8 + 4]);
            af[0] = a0.x; af[1] = a0.y; af[2] = a0.z; af[3] = a0.w;
            af[4] = a1.x; af[5] = a1.y; af[6] = a1.z; af[7] = a1.w;
            float4 b0 = *reinterpret_cast<const float4*>(&Bs[kk * LDB + tx * 8]);
            float4 b1 = *reinterpret_cast<const float4*>(&Bs[kk * LDB + tx * 8 + 4]);
            bf[0] = b0.x; bf[1] = b0.y; bf[2] = b0.z; bf[3] = b0.w;
            bf[4] = b1.x; bf[5] = b1.y; bf[6] = b1.z; bf[7] = b1.w;
#pragma unroll
            for (int i = 0; i < 8; i++)
#pragma unroll
                for (int j = 0; j < 8; j++)
                    acc[i][j] = fmaf(af[i], bf[j], acc[i][j]);
        }
        __syncthreads();
    }

    // Epilogue: add output bias, write coalesced float4s
    float bb[8];
#pragma unroll
    for (int j = 0; j < 8; j++) bb[j] = bias[n0 + tx * 8 + j];
#pragma unroll
    for (int i = 0; i < 8; i++) {
        float* cp = C + (size_t)(m0 + ty * 8 + i) * N + n0 + tx * 8;
        *reinterpret_cast<float4*>(cp) =
            make_float4(acc[i][0] + bb[0], acc[i][1] + bb[1],
                        acc[i][2] + bb[2], acc[i][3] + bb[3]);
        *reinterpret_cast<float4*>(cp + 4) =
            make_float4(acc[i][4] + bb[4], acc[i][5] + bb[5],
                        acc[i][6] + bb[6], acc[i][7] + bb[7]);
    }
}

// ---------------------------------------------------------------------------
// Two-segment flash attention.
// Block: 256 threads = 64 q-rows x 4 lanes (16 head-dims per lane).
// K/V tiles 64x64 in smem; online softmax in 16-key chunks, scores in
// registers, 4-lane butterfly-shfl reduction for each dot product.
// out = softmax(qs K_a^T) V_a / sqrt(Na)  -  softmax(qs K_i^T) V_i / sqrt(Ni)
// ---------------------------------------------------------------------------
__global__ __launch_bounds__(256, 2)
void attn_kernel(const float* __restrict__ Qp, const float* __restrict__ Kp,
                 const float* __restrict__ Vp, float* __restrict__ At,
                 const float* __restrict__ p_log_temp, const int* __restrict__ pNA)
{
    constexpr int ROWS = 64, TS = 64;
    __shared__ float ks[TS][HDc];   // 16 KB
    __shared__ float vs[TS][HDc];   // 16 KB

    const int b  = blockIdx.z;
    const int h  = blockIdx.y;
    const int t0 = blockIdx.x * ROWS;
    const int tid = threadIdx.x;
    const int rl = tid >> 2;       // local q-row 0..63
    const int l4 = tid & 3;        // lane within 4-lane group
    const int d0 = l4 * 16;        // head-dim offset handled by this lane

    const int na = *pNA;
    float temp = __expf(*p_log_temp);
    temp = fminf(fmaxf(temp, 0.1f), 10.0f);
    const float scale = 1.0f / ((float)HDc * temp);

    const int row = t0 + rl;
    const float* qptr = Qp + ((size_t)(b * TQc + row)) * Dc + h * HDc + d0;
    float qreg[16];
#pragma unroll
    for (int i = 0; i < 16; i++) qreg[i] = qptr[i] * scale;

    float outc[16];
#pragma unroll
    for (int i = 0; i < 16; i++) outc[i] = 0.f;

    for (int seg = 0; seg < 2; seg++) {
        const int s_begin = seg ? na : 0;
        const int s_cnt   = seg ? (TKc - na) : na;
        if (s_cnt <= 0) continue;
        const float sign = seg ? -1.f : 1.f;
        const float coef = sign / sqrtf((float)s_cnt);

        float m = -INFINITY, l = 0.f;
        float o[16];
#pragma unroll
        for (int i = 0; i < 16; i++) o[i] = 0.f;

        const int ntiles = (s_cnt + TS - 1) / TS;
        for (int tile = 0; tile < ntiles; tile++) {
            const int kbase = s_begin + tile * TS;
            const int valid = min(TS, s_begin + s_cnt - kbase);

            __syncthreads();   // previous tile fully consumed
            // Cooperative load of K/V tiles (64x64 each), coalesced float4
#pragma unroll
            for (int l2 = 0; l2 < 4; l2++) {
                int s  = tid + l2 * 256;   // 0..1023
                int r  = s >> 4;           // key row 0..63
                int c4 = s & 15;           // float4 col
                float4 kv4 = make_float4(0.f, 0.f, 0.f, 0.f);
                float4 vv4 = make_float4(0.f, 0.f, 0.f, 0.f);
                if (r < valid) {
                    size_t base = ((size_t)(b * TKc + kbase + r)) * Dc + h * HDc + c4 * 4;
                    kv4 = *reinterpret_cast<const float4*>(Kp + base);
                    vv4 = *reinterpret_cast<const float4*>(Vp + base);
                }
                *reinterpret_cast<float4*>(&ks[r][c4 * 4]) = kv4;
                *reinterpret_cast<float4*>(&vs[r][c4 * 4]) = vv4;
            }
            __syncthreads();

#pragma unroll 1
            for (int ch = 0; ch < TS / 16; ch++) {
                float s16[16];
#pragma unroll
                for (int j = 0; j < 16; j++) {
                    const int jj = ch * 16 + j;
                    float p = 0.f;
#pragma unroll
                    for (int i = 0; i < 16; i += 4) {
                        float4 kk4 = *reinterpret_cast<const float4*>(&ks[jj][d0 + i]);
                        p = fmaf(qreg[i + 0], kk4.x, p);
                        p = fmaf(qreg[i + 1], kk4.y, p);
                        p = fmaf(qreg[i + 2], kk4.z, p);
                        p = fmaf(qreg[i + 3], kk4.w, p);
                    }
                    // reduce across the 4 lanes owning this q-row
                    p += __shfl_xor_sync(0xffffffffu, p, 1);
                    p += __shfl_xor_sync(0xffffffffu, p, 2);
                    s16[j] = (jj < valid) ? p : -INFINITY;
                }
                float cm = s16[0];
#pragma unroll
                for (int j = 1; j < 16; j++) cm = fmaxf(cm, s16[j]);
                const float nm = fmaxf(m, cm);
                const float corr = __expf(m - nm);   // m=-inf -> 0 (safe)
                m = nm;
                l *= corr;
#pragma unroll
                for (int i = 0; i < 16; i++) o[i] *= corr;
#pragma unroll
                for (int j = 0; j < 16; j++) {
                    const int jj = ch * 16 + j;
                    const float p = __expf(s16[j] - m);
                    l += p;
#pragma unroll
                    for (int i = 0; i < 16; i += 4) {
                        float4 vv = *reinterpret_cast<const float4*>(&vs[jj][d0 + i]);
                        o[i + 0] = fmaf(p, vv.x, o[i + 0]);
                        o[i + 1] = fmaf(p, vv.y, o[i + 1]);
                        o[i + 2] = fmaf(p, vv.z, o[i + 2]);
                        o[i + 3] = fmaf(p, vv.w, o[i + 3]);
                    }
                }
            }
        }
        const float inv = coef / l;
#pragma unroll
        for (int i = 0; i < 16; i++) outc[i] = fmaf(o[i], inv, outc[i]);
    }

    float* op = At + ((size_t)(b * TQc + row)) * Dc + h * HDc + d0;
#pragma unroll
    for (int i = 0; i < 16; i += 4)
        *reinterpret_cast<float4*>(op + i) =
            make_float4(outc[i], outc[i + 1], outc[i + 2], outc[i + 3]);
}

// ---------------------------------------------------------------------------
// kernel_launch: 5 graph-capturable kernel launches, no allocs, no syncs.
// Input order (metadata): q, kv, Wq, bq, Wk, bk, Wv, bv, Wo, bo,
//                         active_bias, inactive_bias, log_temp, n_actives
// ---------------------------------------------------------------------------
extern "C" void kernel_launch(void* const* d_in, const int* in_sizes, int n_in,
                              void* d_out, int out_size)
{
    const float* q    = (const float*)d_in[0];
    const float* kv   = (const float*)d_in[1];
    const float* Wq   = (const float*)d_in[2];
    const float* bq   = (const float*)d_in[3];
    const float* Wk   = (const float*)d_in[4];
    const float* bk   = (const float*)d_in[5];
    const float* Wv   = (const float*)d_in[6];
    const float* bv   = (const float*)d_in[7];
    const float* Wo   = (const float*)d_in[8];
    const float* bo   = (const float*)d_in[9];
    const float* abA  = (const float*)d_in[10];
    const float* abI  = (const float*)d_in[11];
    const float* logt = (const float*)d_in[12];
    const int*   pNA  = (const int*)d_in[13];
    float* out = (float*)d_out;

    void *pQp, *pKp, *pVp, *pAt;
    cudaGetSymbolAddress(&pQp, g_Qp);
    cudaGetSymbolAddress(&pKp, g_Kp);
    cudaGetSymbolAddress(&pVp, g_Vp);
    cudaGetSymbolAddress(&pAt, g_At);

    const dim3 blk(256);

    // Q projection: [1024,1024] = q[1024,1024] * Wq^T + bq
    gemm_nt_kernel<false><<<dim3(Dc / 128, (Bc * TQc) / 128), blk>>>(
        q, Wq, bq, (float*)pQp, Bc * TQc, Dc, Dc, nullptr, nullptr, nullptr, 0);

    // K projection with fused group bias on kv rows
    gemm_nt_kernel<true><<<dim3(Dc / 128, (Bc * TKc) / 128), blk>>>(
        kv, Wk, bk, (float*)pKp, Bc * TKc, Dc, Dc, abA, abI, pNA, TKc);

    // V projection with fused group bias on kv rows
    gemm_nt_kernel<true><<<dim3(Dc / 128, (Bc * TKc) / 128), blk>>>(
        kv, Wv, bv, (float*)pVp, Bc * TKc, Dc, Dc, abA, abI, pNA, TKc);

    // Two-segment attention
    attn_kernel<<<dim3(TQc / 64, NHc, Bc), blk>>>(
        (const float*)pQp, (const float*)pKp, (const float*)pVp, (float*)pAt,
        logt, pNA);

    // Output projection into d_out
    gemm_nt_kernel<false><<<dim3(Dc / 128, (Bc * TQc) / 128), blk>>>(
        (const float*)pAt, Wo, bo, out, Bc * TQc, Dc, Dc, nullptr, nullptr, nullptr, 0);
}

// round 2
// speedup vs baseline: 5.2680x; 5.2680x over previous
#include <cuda_runtime.h>
#include <cstdint>
#include <math.h>

// Problem dimensions (fixed)
constexpr int Bc  = 2;
constexpr int TQc = 512;
constexpr int TKc = 8192;
constexpr int Dc  = 1024;
constexpr int NHc = 16;
constexpr int HDc = 64;

// Scratch (allocation-free)
__device__ float g_Qp[(size_t)Bc * TQc * Dc];
__device__ float g_Kp[(size_t)Bc * TKc * Dc];
__device__ float g_Vp[(size_t)Bc * TKc * Dc];
__device__ float g_At[(size_t)Bc * TQc * Dc];

// ---------------------------------------------------------------------------
// tf32 helpers
// ---------------------------------------------------------------------------
__device__ __forceinline__ uint32_t f2tf(float x) {
    uint32_t u;
    asm("cvt.rna.tf32.f32 %0, %1;" : "=r"(u) : "f"(x));
    return u;
}
__device__ __forceinline__ uint32_t fb(float x) { return __float_as_uint(x); }

__device__ __forceinline__ void mma_tf32(float& c0, float& c1, float& c2, float& c3,
                                         uint32_t a0, uint32_t a1, uint32_t a2, uint32_t a3,
                                         uint32_t b0, uint32_t b1)
{
    asm volatile(
        "mma.sync.aligned.m16n8k8.row.col.f32.tf32.tf32.f32 "
        "{%0,%1,%2,%3}, {%4,%5,%6,%7}, {%8,%9}, {%0,%1,%2,%3};"
        : "+f"(c0), "+f"(c1), "+f"(c2), "+f"(c3)
        : "r"(a0), "r"(a1), "r"(a2), "r"(a3), "r"(b0), "r"(b1));
}

// ---------------------------------------------------------------------------
// tf32 tensor-core SGEMM (NT): C[M,N] = A'[M,K] * W[N,K]^T + bias[N]
// BM=BN=128, BK=16, 128 threads (4 warps), warp tile 64x64 (m16n8k8 tiles).
// smem ld=20 words -> conflict-free fragment loads.
// ---------------------------------------------------------------------------
template <bool HAS_ABIAS>
__global__ __launch_bounds__(128, 2)
void gemm_tf32(const float* __restrict__ A, const float* __restrict__ W,
               const float* __restrict__ bias, float* __restrict__ C,
               int M, int N, int K,
               const float* __restrict__ abA, const float* __restrict__ abI,
               const int* __restrict__ pNA, int Tk)
{
    constexpr int BM = 128, BN = 128, BK = 16, LD = 20;
    __shared__ float As[BM * LD];
    __shared__ float Bs[BN * LD];

    const int tid  = threadIdx.x;
    const int warp = tid >> 5;
    const int lane = tid & 31;
    const int gr   = lane >> 2;   // 0..7
    const int cc   = lane & 3;    // 0..3
    const int wm   = (warp >> 1) * 64;
    const int wn   = (warp & 1) * 64;
    const int m0   = blockIdx.y * BM;
    const int n0   = blockIdx.x * BN;

    int na = 0;
    if (HAS_ABIAS) na = *pNA;

    float acc[4][8][4];
#pragma unroll
    for (int mt = 0; mt < 4; mt++)
#pragma unroll
        for (int nt = 0; nt < 8; nt++)
#pragma unroll
            for (int r = 0; r < 4; r++) acc[mt][nt][r] = 0.f;

    // global load mapping: 512 float4 per tile side, 4 per thread
    float4 rA[4], rB[4];
    auto load_tiles = [&](int k0, float4* ra, float4* rb) {
#pragma unroll
        for (int i = 0; i < 4; i++) {
            int idx = i * 128 + tid;
            int r = idx >> 2, cg = idx & 3;
            int gm = m0 + r, gk = k0 + cg * 4;
            float4 v = *reinterpret_cast<const float4*>(A + (size_t)gm * K + gk);
            if (HAS_ABIAS) {
                const float* ab = ((gm % Tk) < na) ? abA : abI;
                float4 bv = *reinterpret_cast<const float4*>(ab + gk);
                v.x += bv.x; v.y += bv.y; v.z += bv.z; v.w += bv.w;
            }
            ra[i] = v;
            int gn = n0 + r;
            rb[i] = *reinterpret_cast<const float4*>(W + (size_t)gn * K + gk);
        }
    };

    load_tiles(0, rA, rB);

    for (int k0 = 0; k0 < K; k0 += BK) {
        // store current regs to smem (tf32-converted)
#pragma unroll
        for (int i = 0; i < 4; i++) {
            int idx = i * 128 + tid;
            int r = idx >> 2, cg = idx & 3;
            float4 va = rA[i], vb = rB[i];
            float4 ta = make_float4(__uint_as_float(f2tf(va.x)), __uint_as_float(f2tf(va.y)),
                                    __uint_as_float(f2tf(va.z)), __uint_as_float(f2tf(va.w)));
            float4 tb = make_float4(__uint_as_float(f2tf(vb.x)), __uint_as_float(f2tf(vb.y)),
                                    __uint_as_float(f2tf(vb.z)), __uint_as_float(f2tf(vb.w)));
            *reinterpret_cast<float4*>(&As[r * LD + cg * 4]) = ta;
            *reinterpret_cast<float4*>(&Bs[r * LD + cg * 4]) = tb;
        }
        __syncthreads();

        if (k0 + BK < K) load_tiles(k0 + BK, rA, rB);

#pragma unroll
        for (int kst = 0; kst < 2; kst++) {
            const int kk = kst * 8;
            uint32_t af[4][4];
#pragma unroll
            for (int mt = 0; mt < 4; mt++) {
                const int rbase = (wm + mt * 16 + gr) * LD + kk + cc;
                af[mt][0] = fb(As[rbase]);
                af[mt][1] = fb(As[rbase + 8 * LD]);
                af[mt][2] = fb(As[rbase + 4]);
                af[mt][3] = fb(As[rbase + 8 * LD + 4]);
            }
#pragma unroll
            for (int nt = 0; nt < 8; nt++) {
                const int rbase = (wn + nt * 8 + gr) * LD + kk + cc;
                uint32_t b0 = fb(Bs[rbase]);
                uint32_t b1 = fb(Bs[rbase + 4]);
#pragma unroll
                for (int mt = 0; mt < 4; mt++)
                    mma_tf32(acc[mt][nt][0], acc[mt][nt][1], acc[mt][nt][2], acc[mt][nt][3],
                             af[mt][0], af[mt][1], af[mt][2], af[mt][3], b0, b1);
            }
        }
        __syncthreads();
    }

    // epilogue
#pragma unroll
    for (int mt = 0; mt < 4; mt++) {
#pragma unroll
        for (int nt = 0; nt < 8; nt++) {
            int row = m0 + wm + mt * 16 + gr;
            int col = n0 + wn + nt * 8 + 2 * cc;
            float b0v = bias[col], b1v = bias[col + 1];
            *reinterpret_cast<float2*>(C + (size_t)row * N + col) =
                make_float2(acc[mt][nt][0] + b0v, acc[mt][nt][1] + b1v);
            *reinterpret_cast<float2*>(C + (size_t)(row + 8) * N + col) =
                make_float2(acc[mt][nt][2] + b0v, acc[mt][nt][3] + b1v);
        }
    }
}

// ---------------------------------------------------------------------------
// tf32 MMA flash attention, two segments.
// Block: 128 threads (4 warps), 64 q-rows, TS=128 keys/tile.
// Q lives as A-fragments in registers. S via HMMA (K in smem), online softmax
// on C-fragments, P via smem (layout fix), PV via HMMA (V in smem).
// ---------------------------------------------------------------------------
constexpr int TSa  = 128;
constexpr int LDK  = 68;   // Ks [128][68]
constexpr int LDV  = 72;   // Vs [128][72]
constexpr int LDP  = 132;  // Ps [64][132]
constexpr int ATTN_SMEM_BYTES = (128 * LDK + 128 * LDV + 64 * LDP) * 4;

__global__ __launch_bounds__(128, 2)
void attn_mma(const float* __restrict__ Qp, const float* __restrict__ Kp,
              const float* __restrict__ Vp, float* __restrict__ At,
              const float* __restrict__ p_log_temp, const int* __restrict__ pNA)
{
    extern __shared__ float sm[];
    float* Ks = sm;                       // [128][LDK]
    float* Vs = sm + 128 * LDK;           // [128][LDV]
    float* Ps = Vs + 128 * LDV;           // [64][LDP]

    const int b    = blockIdx.z;
    const int h    = blockIdx.y;
    const int q0   = blockIdx.x * 64;
    const int tid  = threadIdx.x;
    const int warp = tid >> 5;
    const int lane = tid & 31;
    const int gr   = lane >> 2;
    const int cc   = lane & 3;
    const int rl   = warp * 16 + gr;      // local q row (and rl+8)
    const int row0 = q0 + rl;

    const int na = *pNA;
    float temp = __expf(*p_log_temp);
    temp = fminf(fmaxf(temp, 0.1f), 10.0f);
    const float scale = 1.0f / ((float)HDc * temp);

    // Q fragments (held entire kernel): 8 k-steps x 4 regs
    uint32_t qf[8][4];
    {
        const float* qr0 = Qp + ((size_t)(b * TQc + row0)) * Dc + h * HDc;
        const float* qr1 = qr0 + 8 * (size_t)Dc;
#pragma unroll
        for (int ks = 0; ks < 8; ks++) {
            int k = ks * 8;
            qf[ks][0] = f2tf(qr0[k + cc] * scale);
            qf[ks][1] = f2tf(qr1[k + cc] * scale);
            qf[ks][2] = f2tf(qr0[k + cc + 4] * scale);
            qf[ks][3] = f2tf(qr1[k + cc + 4] * scale);
        }
    }

    float outc[8][4];
#pragma unroll
    for (int nt = 0; nt < 8; nt++)
#pragma unroll
        for (int r = 0; r < 4; r++) outc[nt][r] = 0.f;

    const int krow = tid >> 4;   // 0..7
    const int cg   = tid & 15;   // float4 col group

    for (int seg = 0; seg < 2; seg++) {
        const int s_begin = seg ? na : 0;
        const int s_end   = seg ? TKc : na;
        const int s_cnt   = s_end - s_begin;
        if (s_cnt <= 0) continue;
        const float coef = (seg ? -1.f : 1.f) / sqrtf((float)s_cnt);

        float m0v = -INFINITY, m1v = -INFINITY;
        float l0 = 0.f, l1 = 0.f;
        float o[8][4];
#pragma unroll
        for (int nt = 0; nt < 8; nt++)
#pragma unroll
            for (int r = 0; r < 4; r++) o[nt][r] = 0.f;

        const int ntiles = (s_cnt + TSa - 1) / TSa;
        for (int tile = 0; tile < ntiles; tile++) {
            const int kbase = s_begin + tile * TSa;
            const int valid = min(TSa, s_end - kbase);
            const bool partial = (valid < TSa);

            __syncthreads();
            // load K/V tiles (tf32-converted), zero-pad invalid rows
#pragma unroll
            for (int it = 0; it < 16; it++) {
                int r = krow + it * 8;
                float4 kv4 = make_float4(0.f, 0.f, 0.f, 0.f);
                float4 vv4 = kv4;
                if (r < valid) {
                    size_t base = ((size_t)(b * TKc + kbase + r)) * Dc + h * HDc + cg * 4;
                    kv4 = *reinterpret_cast<const float4*>(Kp + base);
                    vv4 = *reinterpret_cast<const float4*>(Vp + base);
                }
                float4 tk = make_float4(__uint_as_float(f2tf(kv4.x)), __uint_as_float(f2tf(kv4.y)),
                                        __uint_as_float(f2tf(kv4.z)), __uint_as_float(f2tf(kv4.w)));
                float4 tv = make_float4(__uint_as_float(f2tf(vv4.x)), __uint_as_float(f2tf(vv4.y)),
                                        __uint_as_float(f2tf(vv4.z)), __uint_as_float(f2tf(vv4.w)));
                *reinterpret_cast<float4*>(&Ks[r * LDK + cg * 4]) = tk;
                *reinterpret_cast<float4*>(&Vs[r * LDV + cg * 4]) = tv;
            }
            __syncthreads();

            // S = Q K^T : 16 n-tiles (keys) x 8 k-steps
            float sacc[16][4];
#pragma unroll
            for (int nt = 0; nt < 16; nt++)
#pragma unroll
                for (int r = 0; r < 4; r++) sacc[nt][r] = 0.f;
#pragma unroll
            for (int ks = 0; ks < 8; ks++) {
                const int kk = ks * 8;
#pragma unroll
                for (int nt = 0; nt < 16; nt++) {
                    const int rbase = (nt * 8 + gr) * LDK + kk + cc;
                    uint32_t b0 = fb(Ks[rbase]);
                    uint32_t b1 = fb(Ks[rbase + 4]);
                    mma_tf32(sacc[nt][0], sacc[nt][1], sacc[nt][2], sacc[nt][3],
                             qf[ks][0], qf[ks][1], qf[ks][2], qf[ks][3], b0, b1);
                }
            }

            // mask out-of-segment columns
            if (partial) {
#pragma unroll
                for (int nt = 0; nt < 16; nt++) {
                    int col = nt * 8 + 2 * cc;
                    if (col     >= valid) { sacc[nt][0] = -INFINITY; sacc[nt][2] = -INFINITY; }
                    if (col + 1 >= valid) { sacc[nt][1] = -INFINITY; sacc[nt][3] = -INFINITY; }
                }
            }

            // online softmax
            float rm0 = -INFINITY, rm1 = -INFINITY;
#pragma unroll
            for (int nt = 0; nt < 16; nt++) {
                rm0 = fmaxf(rm0, fmaxf(sacc[nt][0], sacc[nt][1]));
                rm1 = fmaxf(rm1, fmaxf(sacc[nt][2], sacc[nt][3]));
            }
            rm0 = fmaxf(rm0, __shfl_xor_sync(0xffffffffu, rm0, 1));
            rm0 = fmaxf(rm0, __shfl_xor_sync(0xffffffffu, rm0, 2));
            rm1 = fmaxf(rm1, __shfl_xor_sync(0xffffffffu, rm1, 1));
            rm1 = fmaxf(rm1, __shfl_xor_sync(0xffffffffu, rm1, 2));
            const float nm0 = fmaxf(m0v, rm0);
            const float nm1 = fmaxf(m1v, rm1);
            const float corr0 = __expf(m0v - nm0);
            const float corr1 = __expf(m1v - nm1);
            m0v = nm0; m1v = nm1;
            l0 *= corr0; l1 *= corr1;
#pragma unroll
            for (int nt = 0; nt < 8; nt++) {
                o[nt][0] *= corr0; o[nt][1] *= corr0;
                o[nt][2] *= corr1; o[nt][3] *= corr1;
            }

            // exp -> P (store to smem in tf32)
#pragma unroll
            for (int nt = 0; nt < 16; nt++) {
                float p0 = __expf(sacc[nt][0] - nm0);
                float p1 = __expf(sacc[nt][1] - nm0);
                float p2 = __expf(sacc[nt][2] - nm1);
                float p3 = __expf(sacc[nt][3] - nm1);
                l0 += p0 + p1;
                l1 += p2 + p3;
                const int colw = nt * 8 + 2 * cc;
                *reinterpret_cast<float2*>(&Ps[rl * LDP + colw]) =
                    make_float2(__uint_as_float(f2tf(p0)), __uint_as_float(f2tf(p1)));
                *reinterpret_cast<float2*>(&Ps[(rl + 8) * LDP + colw]) =
                    make_float2(__uint_as_float(f2tf(p2)), __uint_as_float(f2tf(p3)));
            }
            __syncwarp();

            // O += P V : 16 k-tiles (keys) x 8 n-tiles (dims)
#pragma unroll
            for (int kt = 0; kt < 16; kt++) {
                const int kk = kt * 8;
                uint32_t a0 = fb(Ps[rl * LDP + kk + cc]);
                uint32_t a1 = fb(Ps[(rl + 8) * LDP + kk + cc]);
                uint32_t a2 = fb(Ps[rl * LDP + kk + cc + 4]);
                uint32_t a3 = fb(Ps[(rl + 8) * LDP + kk + cc + 4]);
#pragma unroll
                for (int nt = 0; nt < 8; nt++) {
                    uint32_t b0 = fb(Vs[(kk + cc) * LDV + nt * 8 + gr]);
                    uint32_t b1 = fb(Vs[(kk + cc + 4) * LDV + nt * 8 + gr]);
                    mma_tf32(o[nt][0], o[nt][1], o[nt][2], o[nt][3], a0, a1, a2, a3, b0, b1);
                }
            }
        }

        // finalize segment
        l0 += __shfl_xor_sync(0xffffffffu, l0, 1);
        l0 += __shfl_xor_sync(0xffffffffu, l0, 2);
        l1 += __shfl_xor_sync(0xffffffffu, l1, 1);
        l1 += __shfl_xor_sync(0xffffffffu, l1, 2);
        const float inv0 = coef / l0;
        const float inv1 = coef / l1;
#pragma unroll
        for (int nt = 0; nt < 8; nt++) {
            outc[nt][0] += o[nt][0] * inv0;
            outc[nt][1] += o[nt][1] * inv0;
            outc[nt][2] += o[nt][2] * inv1;
            outc[nt][3] += o[nt][3] * inv1;
        }
    }

    // write output tile
    float* ob = At + ((size_t)(b * TQc + row0)) * Dc + h * HDc;
#pragma unroll
    for (int nt = 0; nt < 8; nt++) {
        int col = nt * 8 + 2 * cc;
        *reinterpret_cast<float2*>(ob + col) = make_float2(outc[nt][0], outc[nt][1]);
        *reinterpret_cast<float2*>(ob + 8 * (size_t)Dc + col) = make_float2(outc[nt][2], outc[nt][3]);
    }
}

// ---------------------------------------------------------------------------
// kernel_launch
// ---------------------------------------------------------------------------
extern "C" void kernel_launch(void* const* d_in, const int* in_sizes, int n_in,
                              void* d_out, int out_size)
{
    const float* q    = (const float*)d_in[0];
    const float* kv   = (const float*)d_in[1];
    const float* Wq   = (const float*)d_in[2];
    const float* bq   = (const float*)d_in[3];
    const float* Wk   = (const float*)d_in[4];
    const float* bk   = (const float*)d_in[5];
    const float* Wv   = (const float*)d_in[6];
    const float* bv   = (const float*)d_in[7];
    const float* Wo   = (const float*)d_in[8];
    const float* bo   = (const float*)d_in[9];
    const float* abA  = (const float*)d_in[10];
    const float* abI  = (const float*)d_in[11];
    const float* logt = (const float*)d_in[12];
    const int*   pNA  = (const int*)d_in[13];
    float* out = (float*)d_out;

    void *pQp, *pKp, *pVp, *pAt;
    cudaGetSymbolAddress(&pQp, g_Qp);
    cudaGetSymbolAddress(&pKp, g_Kp);
    cudaGetSymbolAddress(&pVp, g_Vp);
    cudaGetSymbolAddress(&pAt, g_At);

    static bool attr_set = false;
    if (!attr_set) {
        cudaFuncSetAttribute(attn_mma, cudaFuncAttributeMaxDynamicSharedMemorySize,
                             ATTN_SMEM_BYTES);
        attr_set = true;
    }

    const dim3 blk(128);

    gemm_tf32<false><<<dim3(Dc / 128, (Bc * TQc) / 128), blk>>>(
        q, Wq, bq, (float*)pQp, Bc * TQc, Dc, Dc, nullptr, nullptr, nullptr, 0);

    gemm_tf32<true><<<dim3(Dc / 128, (Bc * TKc) / 128), blk>>>(
        kv, Wk, bk, (float*)pKp, Bc * TKc, Dc, Dc, abA, abI, pNA, TKc);

    gemm_tf32<true><<<dim3(Dc / 128, (Bc * TKc) / 128), blk>>>(
        kv, Wv, bv, (float*)pVp, Bc * TKc, Dc, Dc, abA, abI, pNA, TKc);

    attn_mma<<<dim3(TQc / 64, NHc, Bc), blk, ATTN_SMEM_BYTES>>>(
        (const float*)pQp, (const float*)pKp, (const float*)pVp, (float*)pAt,
        logt, pNA);

    gemm_tf32<false><<<dim3(Dc / 128, (Bc * TQc) / 128), blk>>>(
        (const float*)pAt, Wo, bo, out, Bc * TQc, Dc, Dc, nullptr, nullptr, nullptr, 0);
}

// round 3
// speedup vs baseline: 7.7347x; 1.4683x over previous
#include <cuda_runtime.h>
#include <cuda_fp16.h>
#include <cstdint>
#include <math.h>

// Problem dimensions (fixed)
constexpr int Bc  = 2;
constexpr int TQc = 512;
constexpr int TKc = 8192;
constexpr int Dc  = 1024;
constexpr int NHc = 16;
constexpr int HDc = 64;

// Scratch (allocation-free)
__device__ float  g_Qp[(size_t)Bc * TQc * Dc];            // Q projected, fp32
__device__ __half g_Kh[(size_t)Bc * TKc * Dc];            // K projected, fp16 [key][dim]
__device__ __half g_Vh[(size_t)Bc * TKc * Dc];            // V projected, fp16 [key][dim]
__device__ __half g_Vt[(size_t)Bc * NHc * HDc * TKc];     // V transposed  [b,h,dim][key]
__device__ float  g_At[(size_t)Bc * TQc * Dc];            // attention out, fp32

// ---------------------------------------------------------------------------
// helpers
// ---------------------------------------------------------------------------
__device__ __forceinline__ uint32_t pack_h2(float lo, float hi) {
    __half2 h = __floats2half2_rn(lo, hi);
    return *reinterpret_cast<uint32_t*>(&h);
}

__device__ __forceinline__ void mma_f16(float& c0, float& c1, float& c2, float& c3,
                                        uint32_t a0, uint32_t a1, uint32_t a2, uint32_t a3,
                                        uint32_t b0, uint32_t b1)
{
    asm volatile(
        "mma.sync.aligned.m16n8k16.row.col.f32.f16.f16.f32 "
        "{%0,%1,%2,%3}, {%4,%5,%6,%7}, {%8,%9}, {%0,%1,%2,%3};"
        : "+f"(c0), "+f"(c1), "+f"(c2), "+f"(c3)
        : "r"(a0), "r"(a1), "r"(a2), "r"(a3), "r"(b0), "r"(b1));
}

// smem u32 index for a swizzled fp16 tile with row stride 64 halves (32 u32):
// granule (8 halves) index gbase is XORed with (row & 7). cc in [0,4).
__device__ __forceinline__ int sw_idx64(int row, int gbase, int cc) {
    return row * 32 + ((gbase ^ (row & 7)) << 2) + cc;
}
// same for row stride 128 halves (64 u32), 16 granules per row.
__device__ __forceinline__ int sw_idx128(int row, int gbase, int cc) {
    return row * 64 + ((gbase ^ (row & 7)) << 2) + cc;
}

// ---------------------------------------------------------------------------
// fp16 tensor-core GEMM (NT): C[M,N] = A'[M,K] * W[N,K]^T + bias[N]
// A', W are fp32 in global; converted to fp16 on the fly.
// BM=BN=128, BK=64, 256 threads (8 warps), warp tile 64x32.
// EPI: 0 -> fp32 output, 1 -> fp16 output.
// ---------------------------------------------------------------------------
template <int EPI, bool HAS_ABIAS>
__global__ __launch_bounds__(256)
void gemm16(const float* __restrict__ A, const float* __restrict__ W,
            const float* __restrict__ bias, void* __restrict__ Cout,
            int M, int N, int K,
            const float* __restrict__ abA, const float* __restrict__ abI,
            const int* __restrict__ pNA, int Tk)
{
    constexpr int BK = 64;
    __shared__ __half As[128 * 64];   // 16 KB, swizzled
    __shared__ __half Bs[128 * 64];   // 16 KB, swizzled
    uint32_t* As32 = reinterpret_cast<uint32_t*>(As);
    uint32_t* Bs32 = reinterpret_cast<uint32_t*>(Bs);

    const int tid  = threadIdx.x;
    const int warp = tid >> 5;
    const int lane = tid & 31;
    const int gr   = lane >> 2;
    const int cc   = lane & 3;
    const int wm   = (warp >> 2) * 64;   // 2 warp rows
    const int wn   = (warp & 3) * 32;    // 4 warp cols
    const int m0   = blockIdx.y * 128;
    const int n0   = blockIdx.x * 128;

    int na = 0;
    if (HAS_ABIAS) na = *pNA;

    const int lrow = tid >> 3;   // 0..31 (row within 32-row pass group)
    const int seg  = tid & 7;    // granule / 8-float segment

    float acc[4][4][4];
#pragma unroll
    for (int mt = 0; mt < 4; mt++)
#pragma unroll
        for (int nt = 0; nt < 4; nt++)
#pragma unroll
            for (int r = 0; r < 4; r++) acc[mt][nt][r] = 0.f;

    float4 rA[8], rB[8];
    auto load_tiles = [&](int k0) {
#pragma unroll
        for (int p = 0; p < 4; p++) {
            const int r  = lrow + p * 32;
            const int gm = m0 + r;
            const int gn = n0 + r;
            const int gk = k0 + seg * 8;
            const float* ap = A + (size_t)gm * K + gk;
            float4 v0 = *reinterpret_cast<const float4*>(ap);
            float4 v1 = *reinterpret_cast<const float4*>(ap + 4);
            if (HAS_ABIAS) {
                const float* ab = ((gm % Tk) < na) ? abA : abI;
                float4 b0 = *reinterpret_cast<const float4*>(ab + gk);
                float4 b1 = *reinterpret_cast<const float4*>(ab + gk + 4);
                v0.x += b0.x; v0.y += b0.y; v0.z += b0.z; v0.w += b0.w;
                v1.x += b1.x; v1.y += b1.y; v1.z += b1.z; v1.w += b1.w;
            }
            rA[p * 2] = v0; rA[p * 2 + 1] = v1;
            const float* wp = W + (size_t)gn * K + gk;
            rB[p * 2]     = *reinterpret_cast<const float4*>(wp);
            rB[p * 2 + 1] = *reinterpret_cast<const float4*>(wp + 4);
        }
    };

    auto store_tiles = [&]() {
#pragma unroll
        for (int p = 0; p < 4; p++) {
            const int r  = lrow + p * 32;
            const int g  = seg ^ (r & 7);
            uint4 ua, ub;
            float4 a0 = rA[p * 2], a1 = rA[p * 2 + 1];
            float4 b0 = rB[p * 2], b1 = rB[p * 2 + 1];
            ua.x = pack_h2(a0.x, a0.y); ua.y = pack_h2(a0.z, a0.w);
            ua.z = pack_h2(a1.x, a1.y); ua.w = pack_h2(a1.z, a1.w);
            ub.x = pack_h2(b0.x, b0.y); ub.y = pack_h2(b0.z, b0.w);
            ub.z = pack_h2(b1.x, b1.y); ub.w = pack_h2(b1.z, b1.w);
            *reinterpret_cast<uint4*>(&As[r * 64 + g * 8]) = ua;
            *reinterpret_cast<uint4*>(&Bs[r * 64 + g * 8]) = ub;
        }
    };

    load_tiles(0);

    for (int k0 = 0; k0 < K; k0 += BK) {
        store_tiles();
        __syncthreads();
        if (k0 + BK < K) load_tiles(k0 + BK);

#pragma unroll
        for (int ks = 0; ks < 4; ks++) {
            uint32_t af[4][4];
#pragma unroll
            for (int mt = 0; mt < 4; mt++) {
                const int r = wm + mt * 16 + gr;
                af[mt][0] = As32[sw_idx64(r,     2 * ks,     cc)];
                af[mt][1] = As32[sw_idx64(r + 8, 2 * ks,     cc)];
                af[mt][2] = As32[sw_idx64(r,     2 * ks + 1, cc)];
                af[mt][3] = As32[sw_idx64(r + 8, 2 * ks + 1, cc)];
            }
#pragma unroll
            for (int nt = 0; nt < 4; nt++) {
                const int n = wn + nt * 8 + gr;
                uint32_t b0 = Bs32[sw_idx64(n, 2 * ks,     cc)];
                uint32_t b1 = Bs32[sw_idx64(n, 2 * ks + 1, cc)];
#pragma unroll
                for (int mt = 0; mt < 4; mt++)
                    mma_f16(acc[mt][nt][0], acc[mt][nt][1], acc[mt][nt][2], acc[mt][nt][3],
                            af[mt][0], af[mt][1], af[mt][2], af[mt][3], b0, b1);
            }
        }
        __syncthreads();
    }

    // epilogue
#pragma unroll
    for (int mt = 0; mt < 4; mt++) {
#pragma unroll
        for (int nt = 0; nt < 4; nt++) {
            const int row = m0 + wm + mt * 16 + gr;
            const int col = n0 + wn + nt * 8 + 2 * cc;
            const float b0v = bias[col], b1v = bias[col + 1];
            if (EPI == 0) {
                float* C = (float*)Cout;
                *reinterpret_cast<float2*>(C + (size_t)row * N + col) =
                    make_float2(acc[mt][nt][0] + b0v, acc[mt][nt][1] + b1v);
                *reinterpret_cast<float2*>(C + (size_t)(row + 8) * N + col) =
                    make_float2(acc[mt][nt][2] + b0v, acc[mt][nt][3] + b1v);
            } else {
                __half2* C = (__half2*)Cout;
                C[((size_t)row * N + col) >> 1] =
                    __floats2half2_rn(acc[mt][nt][0] + b0v, acc[mt][nt][1] + b1v);
                C[((size_t)(row + 8) * N + col) >> 1] =
                    __floats2half2_rn(acc[mt][nt][2] + b0v, acc[mt][nt][3] + b1v);
            }
        }
    }
}

// ---------------------------------------------------------------------------
// V transpose: Vh[b*TK+key][h*64+d] -> Vt[((b*16+h)*64+d)*TK + key]   (fp16)
// Block 256 threads, tile 64 keys x 64 dims per (b,h).
// ---------------------------------------------------------------------------
__global__ __launch_bounds__(256)
void vtrans(const __half* __restrict__ Vh, __half* __restrict__ Vt)
{
    __shared__ __half s[64][66];
    const int tid = threadIdx.x;
    const int bh  = blockIdx.y;          // b*16 + h
    const int b   = bh >> 4;
    const int h   = bh & 15;
    const int k0  = blockIdx.x * 64;

    // load 64 keys x 64 dims (half2 over dims)
    const int d2 = tid & 31;             // half2 col
    const int kr = tid >> 5;             // 0..7
#pragma unroll
    for (int p = 0; p < 8; p++) {
        const int key = kr + p * 8;
        __half2 v = *reinterpret_cast<const __half2*>(
            Vh + ((size_t)(b * TKc + k0 + key)) * Dc + h * HDc + 2 * d2);
        *reinterpret_cast<__half2*>(&s[key][2 * d2]) = v;
    }
    __syncthreads();

    // write transposed: rows = dims, cols = keys (coalesced half2 over keys)
    const int k2 = tid & 31;             // half2 key col
    const int dr = tid >> 5;
#pragma unroll
    for (int p = 0; p < 8; p++) {
        const int d = dr + p * 8;
        __half2 v = __halves2half2(s[2 * k2][d], s[2 * k2 + 1][d]);
        *reinterpret_cast<__half2*>(
            Vt + ((size_t)(bh * HDc + d)) * TKc + k0 + 2 * k2) = v;
    }
}

// ---------------------------------------------------------------------------
// fp16 MMA flash attention, two segments.
// 128 threads (4 warps), 64 q-rows/block, TS=128 keys per tile.
// Ks [128 keys][64 dims] fp16 swizzled; VtS [64 dims][128 keys]; Ps [64][128].
// ---------------------------------------------------------------------------
constexpr int TSa = 128;
constexpr int ATTN_SMEM_BYTES = (128 * 64 + 64 * 128 + 64 * 128) * 2;  // 48 KB

__global__ __launch_bounds__(128, 2)
void attn_f16(const float* __restrict__ Qp, const __half* __restrict__ Kh,
              const __half* __restrict__ Vt, float* __restrict__ At,
              const float* __restrict__ p_log_temp, const int* __restrict__ pNA)
{
    extern __shared__ __half smh[];
    __half* Ks  = smh;                  // [128][64]
    __half* VtS = smh + 128 * 64;       // [64][128]
    __half* Ps  = VtS + 64 * 128;       // [64][128]
    uint32_t* Ks32  = reinterpret_cast<uint32_t*>(Ks);
    uint32_t* VtS32 = reinterpret_cast<uint32_t*>(VtS);
    uint32_t* Ps32  = reinterpret_cast<uint32_t*>(Ps);

    const int b    = blockIdx.z;
    const int h    = blockIdx.y;
    const int q0   = blockIdx.x * 64;
    const int tid  = threadIdx.x;
    const int warp = tid >> 5;
    const int lane = tid & 31;
    const int gr   = lane >> 2;
    const int cc   = lane & 3;
    const int rl   = warp * 16 + gr;
    const int row0 = q0 + rl;

    const int na = *pNA;
    float temp = __expf(*p_log_temp);
    temp = fminf(fmaxf(temp, 0.1f), 10.0f);
    const float scale = 1.0f / ((float)HDc * temp);

    // Q fragments (fp16, whole kernel): 4 k-steps x 4 regs
    uint32_t qf[4][4];
    {
        const float* qr0 = Qp + ((size_t)(b * TQc + row0)) * Dc + h * HDc;
        const float* qr1 = qr0 + 8 * (size_t)Dc;
#pragma unroll
        for (int ks = 0; ks < 4; ks++) {
            const int k = ks * 16;
            float2 a = *reinterpret_cast<const float2*>(qr0 + k + 2 * cc);
            float2 bv = *reinterpret_cast<const float2*>(qr1 + k + 2 * cc);
            float2 c2 = *reinterpret_cast<const float2*>(qr0 + k + 8 + 2 * cc);
            float2 d2 = *reinterpret_cast<const float2*>(qr1 + k + 8 + 2 * cc);
            qf[ks][0] = pack_h2(a.x * scale, a.y * scale);
            qf[ks][1] = pack_h2(bv.x * scale, bv.y * scale);
            qf[ks][2] = pack_h2(c2.x * scale, c2.y * scale);
            qf[ks][3] = pack_h2(d2.x * scale, d2.y * scale);
        }
    }

    float outc[8][4];
#pragma unroll
    for (int nt = 0; nt < 8; nt++)
#pragma unroll
        for (int r = 0; r < 4; r++) outc[nt][r] = 0.f;

    const int lrow = tid >> 3;  // 0..15
    const int seg  = tid & 7;

    for (int segi = 0; segi < 2; segi++) {
        const int s_begin = segi ? na : 0;
        const int s_end   = segi ? TKc : na;
        const int s_cnt   = s_end - s_begin;
        if (s_cnt <= 0) continue;
        const float coef = (segi ? -1.f : 1.f) / sqrtf((float)s_cnt);

        float m0v = -INFINITY, m1v = -INFINITY;
        float l0 = 0.f, l1 = 0.f;
        float o[8][4];
#pragma unroll
        for (int nt = 0; nt < 8; nt++)
#pragma unroll
            for (int r = 0; r < 4; r++) o[nt][r] = 0.f;

        const int ntiles = (s_cnt + TSa - 1) / TSa;
        for (int tile = 0; tile < ntiles; tile++) {
            const int kbase = s_begin + tile * TSa;
            const int valid = min(TSa, s_end - kbase);
            const bool partial = (valid < TSa);

            __syncthreads();
            // K tile: 128 keys x 64 dims (8 granules/row), 8 passes
#pragma unroll
            for (int p = 0; p < 8; p++) {
                const int r = lrow + p * 16;
                const int g = seg ^ (r & 7);
                uint4 v = make_uint4(0, 0, 0, 0);
                if (r < valid)
                    v = *reinterpret_cast<const uint4*>(
                        Kh + ((size_t)(b * TKc + kbase + r)) * Dc + h * HDc + seg * 8);
                *reinterpret_cast<uint4*>(&Ks[r * 64 + g * 8]) = v;
            }
            // Vt tile: 64 dims x 128 keys (16 granules/row), 4 passes x 2
#pragma unroll
            for (int p = 0; p < 4; p++) {
                const int r = lrow + p * 16;
                const __half* src = Vt + ((size_t)((b * NHc + h) * HDc + r)) * TKc + kbase;
                uint4 v0 = *reinterpret_cast<const uint4*>(src + seg * 8);
                uint4 v1 = *reinterpret_cast<const uint4*>(src + (seg + 8) * 8);
                const int g0 = seg ^ (r & 7);
                *reinterpret_cast<uint4*>(&VtS[r * 128 + g0 * 8]) = v0;
                *reinterpret_cast<uint4*>(&VtS[r * 128 + (g0 + 8) * 8]) = v1;
            }
            __syncthreads();

            // S = Q K^T : 16 n-tiles x 4 k-steps
            float sacc[16][4];
#pragma unroll
            for (int nt = 0; nt < 16; nt++)
#pragma unroll
                for (int r = 0; r < 4; r++) sacc[nt][r] = 0.f;
#pragma unroll
            for (int ks = 0; ks < 4; ks++) {
#pragma unroll
                for (int nt = 0; nt < 16; nt++) {
                    const int n = nt * 8 + gr;
                    uint32_t b0 = Ks32[sw_idx64(n, 2 * ks,     cc)];
                    uint32_t b1 = Ks32[sw_idx64(n, 2 * ks + 1, cc)];
                    mma_f16(sacc[nt][0], sacc[nt][1], sacc[nt][2], sacc[nt][3],
                            qf[ks][0], qf[ks][1], qf[ks][2], qf[ks][3], b0, b1);
                }
            }

            if (partial) {
#pragma unroll
                for (int nt = 0; nt < 16; nt++) {
                    const int col = nt * 8 + 2 * cc;
                    if (col     >= valid) { sacc[nt][0] = -INFINITY; sacc[nt][2] = -INFINITY; }
                    if (col + 1 >= valid) { sacc[nt][1] = -INFINITY; sacc[nt][3] = -INFINITY; }
                }
            }

            // online softmax
            float rm0 = -INFINITY, rm1 = -INFINITY;
#pragma unroll
            for (int nt = 0; nt < 16; nt++) {
                rm0 = fmaxf(rm0, fmaxf(sacc[nt][0], sacc[nt][1]));
                rm1 = fmaxf(rm1, fmaxf(sacc[nt][2], sacc[nt][3]));
            }
            rm0 = fmaxf(rm0, __shfl_xor_sync(0xffffffffu, rm0, 1));
            rm0 = fmaxf(rm0, __shfl_xor_sync(0xffffffffu, rm0, 2));
            rm1 = fmaxf(rm1, __shfl_xor_sync(0xffffffffu, rm1, 1));
            rm1 = fmaxf(rm1, __shfl_xor_sync(0xffffffffu, rm1, 2));
            const float nm0 = fmaxf(m0v, rm0);
            const float nm1 = fmaxf(m1v, rm1);
            const float corr0 = __expf(m0v - nm0);
            const float corr1 = __expf(m1v - nm1);
            m0v = nm0; m1v = nm1;
            l0 *= corr0; l1 *= corr1;
#pragma unroll
            for (int nt = 0; nt < 8; nt++) {
                o[nt][0] *= corr0; o[nt][1] *= corr0;
                o[nt][2] *= corr1; o[nt][3] *= corr1;
            }

            // exp -> P (fp16 in smem, swizzled)
#pragma unroll
            for (int nt = 0; nt < 16; nt++) {
                float p0 = __expf(sacc[nt][0] - nm0);
                float p1 = __expf(sacc[nt][1] - nm0);
                float p2 = __expf(sacc[nt][2] - nm1);
                float p3 = __expf(sacc[nt][3] - nm1);
                l0 += p0 + p1;
                l1 += p2 + p3;
                Ps32[sw_idx128(rl,     nt, cc)] = pack_h2(p0, p1);
                Ps32[sw_idx128(rl + 8, nt, cc)] = pack_h2(p2, p3);
            }
            __syncwarp();

            // O += P V : 8 k-tiles x 8 n-tiles
#pragma unroll
            for (int kt = 0; kt < 8; kt++) {
                uint32_t a0 = Ps32[sw_idx128(rl,     2 * kt,     cc)];
                uint32_t a1 = Ps32[sw_idx128(rl + 8, 2 * kt,     cc)];
                uint32_t a2 = Ps32[sw_idx128(rl,     2 * kt + 1, cc)];
                uint32_t a3 = Ps32[sw_idx128(rl + 8, 2 * kt + 1, cc)];
#pragma unroll
                for (int nt = 0; nt < 8; nt++) {
                    const int n = nt * 8 + gr;
                    uint32_t b0 = VtS32[sw_idx128(n, 2 * kt,     cc)];
                    uint32_t b1 = VtS32[sw_idx128(n, 2 * kt + 1, cc)];
                    mma_f16(o[nt][0], o[nt][1], o[nt][2], o[nt][3],
                            a0, a1, a2, a3, b0, b1);
                }
            }
        }

        l0 += __shfl_xor_sync(0xffffffffu, l0, 1);
        l0 += __shfl_xor_sync(0xffffffffu, l0, 2);
        l1 += __shfl_xor_sync(0xffffffffu, l1, 1);
        l1 += __shfl_xor_sync(0xffffffffu, l1, 2);
        const float inv0 = coef / l0;
        const float inv1 = coef / l1;
#pragma unroll
        for (int nt = 0; nt < 8; nt++) {
            outc[nt][0] += o[nt][0] * inv0;
            outc[nt][1] += o[nt][1] * inv0;
            outc[nt][2] += o[nt][2] * inv1;
            outc[nt][3] += o[nt][3] * inv1;
        }
    }

    float* ob = At + ((size_t)(b * TQc + row0)) * Dc + h * HDc;
#pragma unroll
    for (int nt = 0; nt < 8; nt++) {
        const int col = nt * 8 + 2 * cc;
        *reinterpret_cast<float2*>(ob + col) = make_float2(outc[nt][0], outc[nt][1]);
        *reinterpret_cast<float2*>(ob + 8 * (size_t)Dc + col) = make_float2(outc[nt][2], outc[nt][3]);
    }
}

// ---------------------------------------------------------------------------
// kernel_launch
// ---------------------------------------------------------------------------
extern "C" void kernel_launch(void* const* d_in, const int* in_sizes, int n_in,
                              void* d_out, int out_size)
{
    const float* q    = (const float*)d_in[0];
    const float* kv   = (const float*)d_in[1];
    const float* Wq   = (const float*)d_in[2];
    const float* bq   = (const float*)d_in[3];
    const float* Wk   = (const float*)d_in[4];
    const float* bk   = (const float*)d_in[5];
    const float* Wv   = (const float*)d_in[6];
    const float* bv   = (const float*)d_in[7];
    const float* Wo   = (const float*)d_in[8];
    const float* bo   = (const float*)d_in[9];
    const float* abA  = (const float*)d_in[10];
    const float* abI  = (const float*)d_in[11];
    const float* logt = (const float*)d_in[12];
    const int*   pNA  = (const int*)d_in[13];
    float* out = (float*)d_out;

    void *pQp, *pKh, *pVh, *pVt, *pAt;
    cudaGetSymbolAddress(&pQp, g_Qp);
    cudaGetSymbolAddress(&pKh, g_Kh);
    cudaGetSymbolAddress(&pVh, g_Vh);
    cudaGetSymbolAddress(&pVt, g_Vt);
    cudaGetSymbolAddress(&pAt, g_At);

    static bool attr_set = false;
    if (!attr_set) {
        cudaFuncSetAttribute(attn_f16, cudaFuncAttributeMaxDynamicSharedMemorySize,
                             ATTN_SMEM_BYTES);
        attr_set = true;
    }

    const dim3 gblk(256);

    // Q projection -> fp32
    gemm16<0, false><<<dim3(Dc / 128, (Bc * TQc) / 128), gblk>>>(
        q, Wq, bq, pQp, Bc * TQc, Dc, Dc, nullptr, nullptr, nullptr, 0);

    // K projection -> fp16 (group bias fused)
    gemm16<1, true><<<dim3(Dc / 128, (Bc * TKc) / 128), gblk>>>(
        kv, Wk, bk, pKh, Bc * TKc, Dc, Dc, abA, abI, pNA, TKc);

    // V projection -> fp16 (group bias fused)
    gemm16<1, true><<<dim3(Dc / 128, (Bc * TKc) / 128), gblk>>>(
        kv, Wv, bv, pVh, Bc * TKc, Dc, Dc, abA, abI, pNA, TKc);

    // V transpose per (b,h): [key][dim] -> [dim][key]
    vtrans<<<dim3(TKc / 64, Bc * NHc), gblk>>>((const __half*)pVh, (__half*)pVt);

    // Two-segment attention
    attn_f16<<<dim3(TQc / 64, NHc, Bc), dim3(128), ATTN_SMEM_BYTES>>>(
        (const float*)pQp, (const __half*)pKh, (const __half*)pVt, (float*)pAt,
        logt, pNA);

    // Output projection -> fp32 d_out
    gemm16<0, false><<<dim3(Dc / 128, (Bc * TQc) / 128), gblk>>>(
        (const float*)pAt, Wo, bo, out, Bc * TQc, Dc, Dc, nullptr, nullptr, nullptr, 0);
}

// round 6
// speedup vs baseline: 10.3969x; 1.3442x over previous
#include <cuda_runtime.h>
#include <cuda_fp16.h>
#include <cstdint>
#include <math.h>

// Problem dimensions (fixed)
constexpr int Bc  = 2;
constexpr int TQc = 512;
constexpr int TKc = 8192;
constexpr int Dc  = 1024;
constexpr int NHc = 16;
constexpr int HDc = 64;

// Scratch (allocation-free)
__device__ float  g_Qp[(size_t)Bc * TQc * Dc];            // Q projected, fp32
__device__ __half g_A16[(size_t)Bc * TKc * Dc];           // kv + group bias, fp16
__device__ __half g_Wk16[(size_t)Dc * Dc];
__device__ __half g_Wv16[(size_t)Dc * Dc];
__device__ __half g_Kh[(size_t)Bc * TKc * Dc];            // K projected, fp16
__device__ __half g_Vh[(size_t)Bc * TKc * Dc];            // V projected, fp16
__device__ __half g_Vt[(size_t)Bc * NHc * HDc * TKc];     // V transposed [b,h,dim][key]
__device__ float  g_At[(size_t)Bc * TQc * Dc];            // attention out, fp32

// ---------------------------------------------------------------------------
// helpers
// ---------------------------------------------------------------------------
__device__ __forceinline__ uint32_t pack_h2(float lo, float hi) {
    __half2 h = __floats2half2_rn(lo, hi);
    return *reinterpret_cast<uint32_t*>(&h);
}

__device__ __forceinline__ void mma_f16(float& c0, float& c1, float& c2, float& c3,
                                        uint32_t a0, uint32_t a1, uint32_t a2, uint32_t a3,
                                        uint32_t b0, uint32_t b1)
{
    asm volatile(
        "mma.sync.aligned.m16n8k16.row.col.f32.f16.f16.f32 "
        "{%0,%1,%2,%3}, {%4,%5,%6,%7}, {%8,%9}, {%0,%1,%2,%3};"
        : "+f"(c0), "+f"(c1), "+f"(c2), "+f"(c3)
        : "r"(a0), "r"(a1), "r"(a2), "r"(a3), "r"(b0), "r"(b1));
}

// swizzled u32 index, fp16 tile, row stride 64 halves (32 u32)
__device__ __forceinline__ int sw_idx64(int row, int gbase, int cc) {
    return row * 32 + ((gbase ^ (row & 7)) << 2) + cc;
}
// row stride 128 halves (64 u32)
__device__ __forceinline__ int sw_idx128(int row, int gbase, int cc) {
    return row * 64 + ((gbase ^ (row & 7)) << 2) + cc;
}

// ---------------------------------------------------------------------------
// prep: kv(fp32) + group bias -> fp16 ; generic fp32 -> fp16 for weights
// ---------------------------------------------------------------------------
__global__ __launch_bounds__(256)
void prep_kv(const float* __restrict__ kv, const float* __restrict__ abA,
             const float* __restrict__ abI, const int* __restrict__ pNA,
             __half* __restrict__ dst)
{
    const int na = *pNA;
    const size_t i8 = (size_t)(blockIdx.x * 256 + threadIdx.x) * 8;  // 8 floats
    const int row = (int)(i8 >> 10);            // /Dc
    const int col = (int)(i8 & 1023);
    const float* ab = ((row % TKc) < na) ? abA : abI;
    float4 v0 = *reinterpret_cast<const float4*>(kv + i8);
    float4 v1 = *reinterpret_cast<const float4*>(kv + i8 + 4);
    float4 b0 = *reinterpret_cast<const float4*>(ab + col);
    float4 b1 = *reinterpret_cast<const float4*>(ab + col + 4);
    uint4 o;
    o.x = pack_h2(v0.x + b0.x, v0.y + b0.y);
    o.y = pack_h2(v0.z + b0.z, v0.w + b0.w);
    o.z = pack_h2(v1.x + b1.x, v1.y + b1.y);
    o.w = pack_h2(v1.z + b1.z, v1.w + b1.w);
    *reinterpret_cast<uint4*>(dst + i8) = o;
}

__global__ __launch_bounds__(256)
void prep_w(const float* __restrict__ src, __half* __restrict__ dst)
{
    const size_t i8 = (size_t)(blockIdx.x * 256 + threadIdx.x) * 8;
    float4 v0 = *reinterpret_cast<const float4*>(src + i8);
    float4 v1 = *reinterpret_cast<const float4*>(src + i8 + 4);
    uint4 o;
    o.x = pack_h2(v0.x, v0.y); o.y = pack_h2(v0.z, v0.w);
    o.z = pack_h2(v1.x, v1.y); o.w = pack_h2(v1.z, v1.w);
    *reinterpret_cast<uint4*>(dst + i8) = o;
}

// ---------------------------------------------------------------------------
// Fused K+V projection GEMM, all-fp16 inputs, register-prefetch pipelined.
// C_K = A @ Wk^T + bk ; C_V = A @ Wv^T + bv (fp16 outputs)
// BM=BN=128, BK=64, 512 threads (16 warps), warp tile 32x32 (x2 outputs).
// Static smem: A 16KB + Bk 16KB + Bv 16KB = 48KB (single stage).
// ---------------------------------------------------------------------------
__global__ __launch_bounds__(512)
void kvgemm(const __half* __restrict__ A, const __half* __restrict__ Wk,
            const __half* __restrict__ Wv, const float* __restrict__ bk,
            const float* __restrict__ bv, __half* __restrict__ CK,
            __half* __restrict__ CV)
{
    __shared__ __half As[128 * 64];
    __shared__ __half Bks[128 * 64];
    __shared__ __half Bvs[128 * 64];
    uint32_t* As32 = reinterpret_cast<uint32_t*>(As);
    uint32_t* Bk32 = reinterpret_cast<uint32_t*>(Bks);
    uint32_t* Bv32 = reinterpret_cast<uint32_t*>(Bvs);

    const int tid  = threadIdx.x;
    const int warp = tid >> 5;
    const int lane = tid & 31;
    const int gr   = lane >> 2;
    const int cc   = lane & 3;
    const int wm   = (warp >> 2) * 32;   // 4 warp rows (of 32)
    const int wn   = (warp & 3) * 32;    // 4 warp cols (of 32)
    const int m0   = blockIdx.y * 128;
    const int n0   = blockIdx.x * 128;

    float accK[2][4][4], accV[2][4][4];
#pragma unroll
    for (int mt = 0; mt < 2; mt++)
#pragma unroll
        for (int nt = 0; nt < 4; nt++)
#pragma unroll
            for (int r = 0; r < 4; r++) { accK[mt][nt][r] = 0.f; accV[mt][nt][r] = 0.f; }

    // staging: 2 uint4 per matrix per stage (1024 uint4 per tile / 512 thr)
    uint4 rA[2], rK[2], rV[2];
    auto load_tiles = [&](int k0) {
#pragma unroll
        for (int p = 0; p < 2; p++) {
            const int idx = tid + p * 512;      // 0..1023
            const int r   = idx >> 3;           // row 0..127
            const int g0  = idx & 7;            // granule
            const size_t goff = (size_t)g0 * 8 + k0;
            rA[p] = *reinterpret_cast<const uint4*>(A  + (size_t)(m0 + r) * Dc + goff);
            rK[p] = *reinterpret_cast<const uint4*>(Wk + (size_t)(n0 + r) * Dc + goff);
            rV[p] = *reinterpret_cast<const uint4*>(Wv + (size_t)(n0 + r) * Dc + goff);
        }
    };
    auto store_tiles = [&]() {
#pragma unroll
        for (int p = 0; p < 2; p++) {
            const int idx = tid + p * 512;
            const int r   = idx >> 3;
            const int g   = (idx & 7) ^ (r & 7);
            *reinterpret_cast<uint4*>(&As[r * 64 + g * 8])  = rA[p];
            *reinterpret_cast<uint4*>(&Bks[r * 64 + g * 8]) = rK[p];
            *reinterpret_cast<uint4*>(&Bvs[r * 64 + g * 8]) = rV[p];
        }
    };

    load_tiles(0);
    for (int k0 = 0; k0 < Dc; k0 += 64) {
        store_tiles();
        __syncthreads();
        if (k0 + 64 < Dc) load_tiles(k0 + 64);

#pragma unroll
        for (int ks = 0; ks < 4; ks++) {
            uint32_t af[2][4];
#pragma unroll
            for (int mt = 0; mt < 2; mt++) {
                const int r = wm + mt * 16 + gr;
                af[mt][0] = As32[sw_idx64(r,     2 * ks,     cc)];
                af[mt][1] = As32[sw_idx64(r + 8, 2 * ks,     cc)];
                af[mt][2] = As32[sw_idx64(r,     2 * ks + 1, cc)];
                af[mt][3] = As32[sw_idx64(r + 8, 2 * ks + 1, cc)];
            }
#pragma unroll
            for (int nt = 0; nt < 4; nt++) {
                const int n = wn + nt * 8 + gr;
                uint32_t k0r = Bk32[sw_idx64(n, 2 * ks,     cc)];
                uint32_t k1r = Bk32[sw_idx64(n, 2 * ks + 1, cc)];
                uint32_t v0r = Bv32[sw_idx64(n, 2 * ks,     cc)];
                uint32_t v1r = Bv32[sw_idx64(n, 2 * ks + 1, cc)];
#pragma unroll
                for (int mt = 0; mt < 2; mt++) {
                    mma_f16(accK[mt][nt][0], accK[mt][nt][1], accK[mt][nt][2], accK[mt][nt][3],
                            af[mt][0], af[mt][1], af[mt][2], af[mt][3], k0r, k1r);
                    mma_f16(accV[mt][nt][0], accV[mt][nt][1], accV[mt][nt][2], accV[mt][nt][3],
                            af[mt][0], af[mt][1], af[mt][2], af[mt][3], v0r, v1r);
                }
            }
        }
        __syncthreads();
    }

    // epilogue: bias + fp16 store
#pragma unroll
    for (int mt = 0; mt < 2; mt++) {
#pragma unroll
        for (int nt = 0; nt < 4; nt++) {
            const int row = m0 + wm + mt * 16 + gr;
            const int col = n0 + wn + nt * 8 + 2 * cc;
            const float bk0 = bk[col], bk1 = bk[col + 1];
            const float bv0 = bv[col], bv1 = bv[col + 1];
            __half2* CKp = (__half2*)CK;
            __half2* CVp = (__half2*)CV;
            CKp[((size_t)row * Dc + col) >> 1] =
                __floats2half2_rn(accK[mt][nt][0] + bk0, accK[mt][nt][1] + bk1);
            CKp[((size_t)(row + 8) * Dc + col) >> 1] =
                __floats2half2_rn(accK[mt][nt][2] + bk0, accK[mt][nt][3] + bk1);
            CVp[((size_t)row * Dc + col) >> 1] =
                __floats2half2_rn(accV[mt][nt][0] + bv0, accV[mt][nt][1] + bv1);
            CVp[((size_t)(row + 8) * Dc + col) >> 1] =
                __floats2half2_rn(accV[mt][nt][2] + bv0, accV[mt][nt][3] + bv1);
        }
    }
}

// ---------------------------------------------------------------------------
// fp16 GEMM for Q / O projections (fp32 A in global, fp32 out)
// BM=BN=128, BK=64, 256 threads, warp tile 64x32.
// ---------------------------------------------------------------------------
__global__ __launch_bounds__(256)
void gemm16(const float* __restrict__ A, const float* __restrict__ W,
            const float* __restrict__ bias, float* __restrict__ C,
            int M, int N, int K)
{
    __shared__ __half As[128 * 64];
    __shared__ __half Bs[128 * 64];
    uint32_t* As32 = reinterpret_cast<uint32_t*>(As);
    uint32_t* Bs32 = reinterpret_cast<uint32_t*>(Bs);

    const int tid  = threadIdx.x;
    const int warp = tid >> 5;
    const int lane = tid & 31;
    const int gr   = lane >> 2;
    const int cc   = lane & 3;
    const int wm   = (warp >> 2) * 64;
    const int wn   = (warp & 3) * 32;
    const int m0   = blockIdx.y * 128;
    const int n0   = blockIdx.x * 128;
    const int lrow = tid >> 3;
    const int seg  = tid & 7;

    float acc[4][4][4];
#pragma unroll
    for (int mt = 0; mt < 4; mt++)
#pragma unroll
        for (int nt = 0; nt < 4; nt++)
#pragma unroll
            for (int r = 0; r < 4; r++) acc[mt][nt][r] = 0.f;

    float4 rA[8], rB[8];
    auto load_tiles = [&](int k0) {
#pragma unroll
        for (int p = 0; p < 4; p++) {
            const int r  = lrow + p * 32;
            const int gk = k0 + seg * 8;
            const float* ap = A + (size_t)(m0 + r) * K + gk;
            rA[p * 2]     = *reinterpret_cast<const float4*>(ap);
            rA[p * 2 + 1] = *reinterpret_cast<const float4*>(ap + 4);
            const float* wp = W + (size_t)(n0 + r) * K + gk;
            rB[p * 2]     = *reinterpret_cast<const float4*>(wp);
            rB[p * 2 + 1] = *reinterpret_cast<const float4*>(wp + 4);
        }
    };
    auto store_tiles = [&]() {
#pragma unroll
        for (int p = 0; p < 4; p++) {
            const int r = lrow + p * 32;
            const int g = seg ^ (r & 7);
            uint4 ua, ub;
            float4 a0 = rA[p * 2], a1 = rA[p * 2 + 1];
            float4 b0 = rB[p * 2], b1 = rB[p * 2 + 1];
            ua.x = pack_h2(a0.x, a0.y); ua.y = pack_h2(a0.z, a0.w);
            ua.z = pack_h2(a1.x, a1.y); ua.w = pack_h2(a1.z, a1.w);
            ub.x = pack_h2(b0.x, b0.y); ub.y = pack_h2(b0.z, b0.w);
            ub.z = pack_h2(b1.x, b1.y); ub.w = pack_h2(b1.z, b1.w);
            *reinterpret_cast<uint4*>(&As[r * 64 + g * 8]) = ua;
            *reinterpret_cast<uint4*>(&Bs[r * 64 + g * 8]) = ub;
        }
    };

    load_tiles(0);
    for (int k0 = 0; k0 < K; k0 += 64) {
        store_tiles();
        __syncthreads();
        if (k0 + 64 < K) load_tiles(k0 + 64);
#pragma unroll
        for (int ks = 0; ks < 4; ks++) {
            uint32_t af[4][4];
#pragma unroll
            for (int mt = 0; mt < 4; mt++) {
                const int r = wm + mt * 16 + gr;
                af[mt][0] = As32[sw_idx64(r,     2 * ks,     cc)];
                af[mt][1] = As32[sw_idx64(r + 8, 2 * ks,     cc)];
                af[mt][2] = As32[sw_idx64(r,     2 * ks + 1, cc)];
                af[mt][3] = As32[sw_idx64(r + 8, 2 * ks + 1, cc)];
            }
#pragma unroll
            for (int nt = 0; nt < 4; nt++) {
                const int n = wn + nt * 8 + gr;
                uint32_t b0 = Bs32[sw_idx64(n, 2 * ks,     cc)];
                uint32_t b1 = Bs32[sw_idx64(n, 2 * ks + 1, cc)];
#pragma unroll
                for (int mt = 0; mt < 4; mt++)
                    mma_f16(acc[mt][nt][0], acc[mt][nt][1], acc[mt][nt][2], acc[mt][nt][3],
                            af[mt][0], af[mt][1], af[mt][2], af[mt][3], b0, b1);
            }
        }
        __syncthreads();
    }

#pragma unroll
    for (int mt = 0; mt < 4; mt++) {
#pragma unroll
        for (int nt = 0; nt < 4; nt++) {
            const int row = m0 + wm + mt * 16 + gr;
            const int col = n0 + wn + nt * 8 + 2 * cc;
            const float b0v = bias[col], b1v = bias[col + 1];
            *reinterpret_cast<float2*>(C + (size_t)row * N + col) =
                make_float2(acc[mt][nt][0] + b0v, acc[mt][nt][1] + b1v);
            *reinterpret_cast<float2*>(C + (size_t)(row + 8) * N + col) =
                make_float2(acc[mt][nt][2] + b0v, acc[mt][nt][3] + b1v);
        }
    }
}

// ---------------------------------------------------------------------------
// V transpose: Vh[b*TK+key][h*64+d] -> Vt[((b*16+h)*64+d)*TK + key]
// ---------------------------------------------------------------------------
__global__ __launch_bounds__(256)
void vtrans(const __half* __restrict__ Vh, __half* __restrict__ Vt)
{
    __shared__ __half s[64][66];
    const int tid = threadIdx.x;
    const int bh  = blockIdx.y;
    const int b   = bh >> 4;
    const int h   = bh & 15;
    const int k0  = blockIdx.x * 64;

    const int d2 = tid & 31;
    const int kr = tid >> 5;
#pragma unroll
    for (int p = 0; p < 8; p++) {
        const int key = kr + p * 8;
        __half2 v = *reinterpret_cast<const __half2*>(
            Vh + ((size_t)(b * TKc + k0 + key)) * Dc + h * HDc + 2 * d2);
        *reinterpret_cast<__half2*>(&s[key][2 * d2]) = v;
    }
    __syncthreads();

    const int k2 = tid & 31;
    const int dr = tid >> 5;
#pragma unroll
    for (int p = 0; p < 8; p++) {
        const int d = dr + p * 8;
        __half2 v = __halves2half2(s[2 * k2][d], s[2 * k2 + 1][d]);
        *reinterpret_cast<__half2*>(
            Vt + ((size_t)(bh * HDc + d)) * TKc + k0 + 2 * k2) = v;
    }
}

// ---------------------------------------------------------------------------
// fp16 MMA flash attention, two segments. Static smem (48 KB exactly).
// 128 threads (4 warps), 64 q-rows/block, TS=128 keys per tile.
// ---------------------------------------------------------------------------
constexpr int TSa = 128;

__global__ __launch_bounds__(128, 2)
void attn_f16(const float* __restrict__ Qp, const __half* __restrict__ Kh,
              const __half* __restrict__ Vt, float* __restrict__ At,
              const float* __restrict__ p_log_temp, const int* __restrict__ pNA)
{
    __shared__ __half Ks[128 * 64];
    __shared__ __half VtS[64 * 128];
    __shared__ __half Ps[64 * 128];
    uint32_t* Ks32  = reinterpret_cast<uint32_t*>(Ks);
    uint32_t* VtS32 = reinterpret_cast<uint32_t*>(VtS);
    uint32_t* Ps32  = reinterpret_cast<uint32_t*>(Ps);

    const int b    = blockIdx.z;
    const int h    = blockIdx.y;
    const int q0   = blockIdx.x * 64;
    const int tid  = threadIdx.x;
    const int warp = tid >> 5;
    const int lane = tid & 31;
    const int gr   = lane >> 2;
    const int cc   = lane & 3;
    const int rl   = warp * 16 + gr;
    const int row0 = q0 + rl;

    const int na = *pNA;
    float temp = __expf(*p_log_temp);
    temp = fminf(fmaxf(temp, 0.1f), 10.0f);
    const float scale = 1.0f / ((float)HDc * temp);

    uint32_t qf[4][4];
    {
        const float* qr0 = Qp + ((size_t)(b * TQc + row0)) * Dc + h * HDc;
        const float* qr1 = qr0 + 8 * (size_t)Dc;
#pragma unroll
        for (int ks = 0; ks < 4; ks++) {
            const int k = ks * 16;
            float2 a  = *reinterpret_cast<const float2*>(qr0 + k + 2 * cc);
            float2 bv = *reinterpret_cast<const float2*>(qr1 + k + 2 * cc);
            float2 c2 = *reinterpret_cast<const float2*>(qr0 + k + 8 + 2 * cc);
            float2 d2 = *reinterpret_cast<const float2*>(qr1 + k + 8 + 2 * cc);
            qf[ks][0] = pack_h2(a.x * scale, a.y * scale);
            qf[ks][1] = pack_h2(bv.x * scale, bv.y * scale);
            qf[ks][2] = pack_h2(c2.x * scale, c2.y * scale);
            qf[ks][3] = pack_h2(d2.x * scale, d2.y * scale);
        }
    }

    float outc[8][4];
#pragma unroll
    for (int nt = 0; nt < 8; nt++)
#pragma unroll
        for (int r = 0; r < 4; r++) outc[nt][r] = 0.f;

    const int lrow = tid >> 3;
    const int seg  = tid & 7;

    for (int segi = 0; segi < 2; segi++) {
        const int s_begin = segi ? na : 0;
        const int s_end   = segi ? TKc : na;
        const int s_cnt   = s_end - s_begin;
        if (s_cnt <= 0) continue;
        const float coef = (segi ? -1.f : 1.f) / sqrtf((float)s_cnt);

        float m0v = -INFINITY, m1v = -INFINITY;
        float l0 = 0.f, l1 = 0.f;
        float o[8][4];
#pragma unroll
        for (int nt = 0; nt < 8; nt++)
#pragma unroll
            for (int r = 0; r < 4; r++) o[nt][r] = 0.f;

        const int ntiles = (s_cnt + TSa - 1) / TSa;
        for (int tile = 0; tile < ntiles; tile++) {
            const int kbase = s_begin + tile * TSa;
            const int valid = min(TSa, s_end - kbase);
            const bool partial = (valid < TSa);

            __syncthreads();
#pragma unroll
            for (int p = 0; p < 8; p++) {
                const int r = lrow + p * 16;
                const int g = seg ^ (r & 7);
                uint4 v = make_uint4(0, 0, 0, 0);
                if (r < valid)
                    v = *reinterpret_cast<const uint4*>(
                        Kh + ((size_t)(b * TKc + kbase + r)) * Dc + h * HDc + seg * 8);
                *reinterpret_cast<uint4*>(&Ks[r * 64 + g * 8]) = v;
            }
#pragma unroll
            for (int p = 0; p < 4; p++) {
                const int r = lrow + p * 16;
                const __half* src = Vt + ((size_t)((b * NHc + h) * HDc + r)) * TKc + kbase;
                uint4 v0 = *reinterpret_cast<const uint4*>(src + seg * 8);
                uint4 v1 = *reinterpret_cast<const uint4*>(src + (seg + 8) * 8);
                const int g0 = seg ^ (r & 7);
                *reinterpret_cast<uint4*>(&VtS[r * 128 + g0 * 8]) = v0;
                *reinterpret_cast<uint4*>(&VtS[r * 128 + (g0 + 8) * 8]) = v1;
            }
            __syncthreads();

            float sacc[16][4];
#pragma unroll
            for (int nt = 0; nt < 16; nt++)
#pragma unroll
                for (int r = 0; r < 4; r++) sacc[nt][r] = 0.f;
#pragma unroll
            for (int ks = 0; ks < 4; ks++) {
#pragma unroll
                for (int nt = 0; nt < 16; nt++) {
                    const int n = nt * 8 + gr;
                    uint32_t b0 = Ks32[sw_idx64(n, 2 * ks,     cc)];
                    uint32_t b1 = Ks32[sw_idx64(n, 2 * ks + 1, cc)];
                    mma_f16(sacc[nt][0], sacc[nt][1], sacc[nt][2], sacc[nt][3],
                            qf[ks][0], qf[ks][1], qf[ks][2], qf[ks][3], b0, b1);
                }
            }

            if (partial) {
#pragma unroll
                for (int nt = 0; nt < 16; nt++) {
                    const int col = nt * 8 + 2 * cc;
                    if (col     >= valid) { sacc[nt][0] = -INFINITY; sacc[nt][2] = -INFINITY; }
                    if (col + 1 >= valid) { sacc[nt][1] = -INFINITY; sacc[nt][3] = -INFINITY; }
                }
            }

            float rm0 = -INFINITY, rm1 = -INFINITY;
#pragma unroll
            for (int nt = 0; nt < 16; nt++) {
                rm0 = fmaxf(rm0, fmaxf(sacc[nt][0], sacc[nt][1]));
                rm1 = fmaxf(rm1, fmaxf(sacc[nt][2], sacc[nt][3]));
            }
            rm0 = fmaxf(rm0, __shfl_xor_sync(0xffffffffu, rm0, 1));
            rm0 = fmaxf(rm0, __shfl_xor_sync(0xffffffffu, rm0, 2));
            rm1 = fmaxf(rm1, __shfl_xor_sync(0xffffffffu, rm1, 1));
            rm1 = fmaxf(rm1, __shfl_xor_sync(0xffffffffu, rm1, 2));
            const float nm0 = fmaxf(m0v, rm0);
            const float nm1 = fmaxf(m1v, rm1);
            const float corr0 = __expf(m0v - nm0);
            const float corr1 = __expf(m1v - nm1);
            m0v = nm0; m1v = nm1;
            l0 *= corr0; l1 *= corr1;
#pragma unroll
            for (int nt = 0; nt < 8; nt++) {
                o[nt][0] *= corr0; o[nt][1] *= corr0;
                o[nt][2] *= corr1; o[nt][3] *= corr1;
            }

#pragma unroll
            for (int nt = 0; nt < 16; nt++) {
                float p0 = __expf(sacc[nt][0] - nm0);
                float p1 = __expf(sacc[nt][1] - nm0);
                float p2 = __expf(sacc[nt][2] - nm1);
                float p3 = __expf(sacc[nt][3] - nm1);
                l0 += p0 + p1;
                l1 += p2 + p3;
                Ps32[sw_idx128(rl,     nt, cc)] = pack_h2(p0, p1);
                Ps32[sw_idx128(rl + 8, nt, cc)] = pack_h2(p2, p3);
            }
            __syncwarp();

#pragma unroll
            for (int kt = 0; kt < 8; kt++) {
                uint32_t a0 = Ps32[sw_idx128(rl,     2 * kt,     cc)];
                uint32_t a1 = Ps32[sw_idx128(rl + 8, 2 * kt,     cc)];
                uint32_t a2 = Ps32[sw_idx128(rl,     2 * kt + 1, cc)];
                uint32_t a3 = Ps32[sw_idx128(rl + 8, 2 * kt + 1, cc)];
#pragma unroll
                for (int nt = 0; nt < 8; nt++) {
                    const int n = nt * 8 + gr;
                    uint32_t b0 = VtS32[sw_idx128(n, 2 * kt,     cc)];
                    uint32_t b1 = VtS32[sw_idx128(n, 2 * kt + 1, cc)];
                    mma_f16(o[nt][0], o[nt][1], o[nt][2], o[nt][3],
                            a0, a1, a2, a3, b0, b1);
                }
            }
        }

        l0 += __shfl_xor_sync(0xffffffffu, l0, 1);
        l0 += __shfl_xor_sync(0xffffffffu, l0, 2);
        l1 += __shfl_xor_sync(0xffffffffu, l1, 1);
        l1 += __shfl_xor_sync(0xffffffffu, l1, 2);
        const float inv0 = coef / l0;
        const float inv1 = coef / l1;
#pragma unroll
        for (int nt = 0; nt < 8; nt++) {
            outc[nt][0] += o[nt][0] * inv0;
            outc[nt][1] += o[nt][1] * inv0;
            outc[nt][2] += o[nt][2] * inv1;
            outc[nt][3] += o[nt][3] * inv1;
        }
    }

    float* ob = At + ((size_t)(b * TQc + row0)) * Dc + h * HDc;
#pragma unroll
    for (int nt = 0; nt < 8; nt++) {
        const int col = nt * 8 + 2 * cc;
        *reinterpret_cast<float2*>(ob + col) = make_float2(outc[nt][0], outc[nt][1]);
        *reinterpret_cast<float2*>(ob + 8 * (size_t)Dc + col) = make_float2(outc[nt][2], outc[nt][3]);
    }
}

// ---------------------------------------------------------------------------
// kernel_launch: plain kernel launches only, no statics, no attribute calls.
// ---------------------------------------------------------------------------
extern "C" void kernel_launch(void* const* d_in, const int* in_sizes, int n_in,
                              void* d_out, int out_size)
{
    const float* q    = (const float*)d_in[0];
    const float* kv   = (const float*)d_in[1];
    const float* Wq   = (const float*)d_in[2];
    const float* bq   = (const float*)d_in[3];
    const float* Wk   = (const float*)d_in[4];
    const float* bk   = (const float*)d_in[5];
    const float* Wv   = (const float*)d_in[6];
    const float* bv   = (const float*)d_in[7];
    const float* Wo   = (const float*)d_in[8];
    const float* bo   = (const float*)d_in[9];
    const float* abA  = (const float*)d_in[10];
    const float* abI  = (const float*)d_in[11];
    const float* logt = (const float*)d_in[12];
    const int*   pNA  = (const int*)d_in[13];
    float* out = (float*)d_out;

    void *pQp, *pA16, *pWk16, *pWv16, *pKh, *pVh, *pVt, *pAt;
    cudaGetSymbolAddress(&pQp,   g_Qp);
    cudaGetSymbolAddress(&pA16,  g_A16);
    cudaGetSymbolAddress(&pWk16, g_Wk16);
    cudaGetSymbolAddress(&pWv16, g_Wv16);
    cudaGetSymbolAddress(&pKh,   g_Kh);
    cudaGetSymbolAddress(&pVh,   g_Vh);
    cudaGetSymbolAddress(&pVt,   g_Vt);
    cudaGetSymbolAddress(&pAt,   g_At);

    const dim3 gblk(256);

    // prep: kv + group bias -> fp16; Wk, Wv -> fp16
    prep_kv<<<(Bc * TKc * Dc) / (256 * 8), gblk>>>(kv, abA, abI, pNA, (__half*)pA16);
    prep_w<<<(Dc * Dc) / (256 * 8), gblk>>>(Wk, (__half*)pWk16);
    prep_w<<<(Dc * Dc) / (256 * 8), gblk>>>(Wv, (__half*)pWv16);

    // Q projection -> fp32 (small)
    gemm16<<<dim3(Dc / 128, (Bc * TQc) / 128), gblk>>>(
        q, Wq, bq, (float*)pQp, Bc * TQc, Dc, Dc);

    // Fused K+V projection (fp16 in / fp16 out), 512 threads, static smem
    kvgemm<<<dim3(Dc / 128, (Bc * TKc) / 128), dim3(512)>>>(
        (const __half*)pA16, (const __half*)pWk16, (const __half*)pWv16,
        bk, bv, (__half*)pKh, (__half*)pVh);

    // V transpose per (b,h)
    vtrans<<<dim3(TKc / 64, Bc * NHc), gblk>>>((const __half*)pVh, (__half*)pVt);

    // Two-segment attention (static 48KB smem)
    attn_f16<<<dim3(TQc / 64, NHc, Bc), dim3(128)>>>(
        (const float*)pQp, (const __half*)pKh, (const __half*)pVt, (float*)pAt,
        logt, pNA);

    // Output projection -> fp32 d_out
    gemm16<<<dim3(Dc / 128, (Bc * TQc) / 128), gblk>>>(
        (const float*)pAt, Wo, bo, out, Bc * TQc, Dc, Dc);
}

// round 8
// speedup vs baseline: 11.6292x; 1.1185x over previous
#include <cuda_runtime.h>
#include <cuda_fp16.h>
#include <cstdint>
#include <math.h>

// Problem dimensions (fixed)
constexpr int Bc  = 2;
constexpr int TQc = 512;
constexpr int TKc = 8192;
constexpr int Dc  = 1024;
constexpr int NHc = 16;
constexpr int HDc = 64;

// Scratch (allocation-free)
__device__ float  g_Qp[(size_t)Bc * TQc * Dc];            // Q projected, fp32
__device__ __half g_A16[(size_t)Bc * TKc * Dc];           // kv + group bias, fp16
__device__ __half g_Wk16[(size_t)Dc * Dc];
__device__ __half g_Wv16[(size_t)Dc * Dc];
__device__ __half g_Kh[(size_t)Bc * TKc * Dc];            // K projected, fp16
__device__ __half g_Vh[(size_t)Bc * TKc * Dc];            // V projected, fp16
__device__ __half g_Vt[(size_t)Bc * NHc * HDc * TKc];     // V transposed [b,h,dim][key]
__device__ float  g_At[(size_t)Bc * TQc * Dc];            // attention out, fp32

// ---------------------------------------------------------------------------
// helpers
// ---------------------------------------------------------------------------
__device__ __forceinline__ uint32_t pack_h2(float lo, float hi) {
    __half2 h = __floats2half2_rn(lo, hi);
    return *reinterpret_cast<uint32_t*>(&h);
}

__device__ __forceinline__ void mma_f16(float& c0, float& c1, float& c2, float& c3,
                                        uint32_t a0, uint32_t a1, uint32_t a2, uint32_t a3,
                                        uint32_t b0, uint32_t b1)
{
    asm volatile(
        "mma.sync.aligned.m16n8k16.row.col.f32.f16.f16.f32 "
        "{%0,%1,%2,%3}, {%4,%5,%6,%7}, {%8,%9}, {%0,%1,%2,%3};"
        : "+f"(c0), "+f"(c1), "+f"(c2), "+f"(c3)
        : "r"(a0), "r"(a1), "r"(a2), "r"(a3), "r"(b0), "r"(b1));
}

// swizzled u32 index, fp16 tile, row stride 64 halves (32 u32)
__device__ __forceinline__ int sw_idx64(int row, int gbase, int cc) {
    return row * 32 + ((gbase ^ (row & 7)) << 2) + cc;
}
// row stride 128 halves (64 u32)
__device__ __forceinline__ int sw_idx128(int row, int gbase, int cc) {
    return row * 64 + ((gbase ^ (row & 7)) << 2) + cc;
}

// ---------------------------------------------------------------------------
// prep: kv(fp32) + group bias -> fp16 ; generic fp32 -> fp16 for weights
// ---------------------------------------------------------------------------
__global__ __launch_bounds__(256)
void prep_kv(const float* __restrict__ kv, const float* __restrict__ abA,
             const float* __restrict__ abI, const int* __restrict__ pNA,
             __half* __restrict__ dst)
{
    const int na = *pNA;
    const size_t i8 = (size_t)(blockIdx.x * 256 + threadIdx.x) * 8;  // 8 floats
    const int row = (int)(i8 >> 10);            // /Dc
    const int col = (int)(i8 & 1023);
    const float* ab = ((row % TKc) < na) ? abA : abI;
    float4 v0 = *reinterpret_cast<const float4*>(kv + i8);
    float4 v1 = *reinterpret_cast<const float4*>(kv + i8 + 4);
    float4 b0 = *reinterpret_cast<const float4*>(ab + col);
    float4 b1 = *reinterpret_cast<const float4*>(ab + col + 4);
    uint4 o;
    o.x = pack_h2(v0.x + b0.x, v0.y + b0.y);
    o.y = pack_h2(v0.z + b0.z, v0.w + b0.w);
    o.z = pack_h2(v1.x + b1.x, v1.y + b1.y);
    o.w = pack_h2(v1.z + b1.z, v1.w + b1.w);
    *reinterpret_cast<uint4*>(dst + i8) = o;
}

__global__ __launch_bounds__(256)
void prep_w(const float* __restrict__ src, __half* __restrict__ dst)
{
    const size_t i8 = (size_t)(blockIdx.x * 256 + threadIdx.x) * 8;
    float4 v0 = *reinterpret_cast<const float4*>(src + i8);
    float4 v1 = *reinterpret_cast<const float4*>(src + i8 + 4);
    uint4 o;
    o.x = pack_h2(v0.x, v0.y); o.y = pack_h2(v0.z, v0.w);
    o.z = pack_h2(v1.x, v1.y); o.w = pack_h2(v1.z, v1.w);
    *reinterpret_cast<uint4*>(dst + i8) = o;
}

// ---------------------------------------------------------------------------
// Fused K+V projection GEMM (unchanged from R6 — proven).
// BM=BN=128, BK=64, 512 threads (16 warps), warp tile 32x32 (x2 outputs).
// Static smem 48KB, register-prefetch pipelined.
// ---------------------------------------------------------------------------
__global__ __launch_bounds__(512)
void kvgemm(const __half* __restrict__ A, const __half* __restrict__ Wk,
            const __half* __restrict__ Wv, const float* __restrict__ bk,
            const float* __restrict__ bv, __half* __restrict__ CK,
            __half* __restrict__ CV)
{
    __shared__ __half As[128 * 64];
    __shared__ __half Bks[128 * 64];
    __shared__ __half Bvs[128 * 64];
    uint32_t* As32 = reinterpret_cast<uint32_t*>(As);
    uint32_t* Bk32 = reinterpret_cast<uint32_t*>(Bks);
    uint32_t* Bv32 = reinterpret_cast<uint32_t*>(Bvs);

    const int tid  = threadIdx.x;
    const int warp = tid >> 5;
    const int lane = tid & 31;
    const int gr   = lane >> 2;
    const int cc   = lane & 3;
    const int wm   = (warp >> 2) * 32;
    const int wn   = (warp & 3) * 32;
    const int m0   = blockIdx.y * 128;
    const int n0   = blockIdx.x * 128;

    float accK[2][4][4], accV[2][4][4];
#pragma unroll
    for (int mt = 0; mt < 2; mt++)
#pragma unroll
        for (int nt = 0; nt < 4; nt++)
#pragma unroll
            for (int r = 0; r < 4; r++) { accK[mt][nt][r] = 0.f; accV[mt][nt][r] = 0.f; }

    uint4 rA[2], rK[2], rV[2];
    auto load_tiles = [&](int k0) {
#pragma unroll
        for (int p = 0; p < 2; p++) {
            const int idx = tid + p * 512;
            const int r   = idx >> 3;
            const int g0  = idx & 7;
            const size_t goff = (size_t)g0 * 8 + k0;
            rA[p] = *reinterpret_cast<const uint4*>(A  + (size_t)(m0 + r) * Dc + goff);
            rK[p] = *reinterpret_cast<const uint4*>(Wk + (size_t)(n0 + r) * Dc + goff);
            rV[p] = *reinterpret_cast<const uint4*>(Wv + (size_t)(n0 + r) * Dc + goff);
        }
    };
    auto store_tiles = [&]() {
#pragma unroll
        for (int p = 0; p < 2; p++) {
            const int idx = tid + p * 512;
            const int r   = idx >> 3;
            const int g   = (idx & 7) ^ (r & 7);
            *reinterpret_cast<uint4*>(&As[r * 64 + g * 8])  = rA[p];
            *reinterpret_cast<uint4*>(&Bks[r * 64 + g * 8]) = rK[p];
            *reinterpret_cast<uint4*>(&Bvs[r * 64 + g * 8]) = rV[p];
        }
    };

    load_tiles(0);
    for (int k0 = 0; k0 < Dc; k0 += 64) {
        store_tiles();
        __syncthreads();
        if (k0 + 64 < Dc) load_tiles(k0 + 64);

#pragma unroll
        for (int ks = 0; ks < 4; ks++) {
            uint32_t af[2][4];
#pragma unroll
            for (int mt = 0; mt < 2; mt++) {
                const int r = wm + mt * 16 + gr;
                af[mt][0] = As32[sw_idx64(r,     2 * ks,     cc)];
                af[mt][1] = As32[sw_idx64(r + 8, 2 * ks,     cc)];
                af[mt][2] = As32[sw_idx64(r,     2 * ks + 1, cc)];
                af[mt][3] = As32[sw_idx64(r + 8, 2 * ks + 1, cc)];
            }
#pragma unroll
            for (int nt = 0; nt < 4; nt++) {
                const int n = wn + nt * 8 + gr;
                uint32_t k0r = Bk32[sw_idx64(n, 2 * ks,     cc)];
                uint32_t k1r = Bk32[sw_idx64(n, 2 * ks + 1, cc)];
                uint32_t v0r = Bv32[sw_idx64(n, 2 * ks,     cc)];
                uint32_t v1r = Bv32[sw_idx64(n, 2 * ks + 1, cc)];
#pragma unroll
                for (int mt = 0; mt < 2; mt++) {
                    mma_f16(accK[mt][nt][0], accK[mt][nt][1], accK[mt][nt][2], accK[mt][nt][3],
                            af[mt][0], af[mt][1], af[mt][2], af[mt][3], k0r, k1r);
                    mma_f16(accV[mt][nt][0], accV[mt][nt][1], accV[mt][nt][2], accV[mt][nt][3],
                            af[mt][0], af[mt][1], af[mt][2], af[mt][3], v0r, v1r);
                }
            }
        }
        __syncthreads();
    }

#pragma unroll
    for (int mt = 0; mt < 2; mt++) {
#pragma unroll
        for (int nt = 0; nt < 4; nt++) {
            const int row = m0 + wm + mt * 16 + gr;
            const int col = n0 + wn + nt * 8 + 2 * cc;
            const float bk0 = bk[col], bk1 = bk[col + 1];
            const float bv0 = bv[col], bv1 = bv[col + 1];
            __half2* CKp = (__half2*)CK;
            __half2* CVp = (__half2*)CV;
            CKp[((size_t)row * Dc + col) >> 1] =
                __floats2half2_rn(accK[mt][nt][0] + bk0, accK[mt][nt][1] + bk1);
            CKp[((size_t)(row + 8) * Dc + col) >> 1] =
                __floats2half2_rn(accK[mt][nt][2] + bk0, accK[mt][nt][3] + bk1);
            CVp[((size_t)row * Dc + col) >> 1] =
                __floats2half2_rn(accV[mt][nt][0] + bv0, accV[mt][nt][1] + bv1);
            CVp[((size_t)(row + 8) * Dc + col) >> 1] =
                __floats2half2_rn(accV[mt][nt][2] + bv0, accV[mt][nt][3] + bv1);
        }
    }
}

// ---------------------------------------------------------------------------
// fp16 GEMM for Q / O projections, BM=64 x BN=128 (2x blocks vs R6 -> occupancy)
// 256 threads (8 warps), warp tile 32x32.
// ---------------------------------------------------------------------------
__global__ __launch_bounds__(256)
void gemm16b(const float* __restrict__ A, const float* __restrict__ W,
             const float* __restrict__ bias, float* __restrict__ C,
             int M, int N, int K)
{
    __shared__ __half As[64 * 64];     // 8 KB
    __shared__ __half Bs[128 * 64];    // 16 KB
    uint32_t* As32 = reinterpret_cast<uint32_t*>(As);
    uint32_t* Bs32 = reinterpret_cast<uint32_t*>(Bs);

    const int tid  = threadIdx.x;
    const int warp = tid >> 5;
    const int lane = tid & 31;
    const int gr   = lane >> 2;
    const int cc   = lane & 3;
    const int wm   = (warp >> 2) * 32;   // 2 warp rows
    const int wn   = (warp & 3) * 32;    // 4 warp cols
    const int m0   = blockIdx.y * 64;
    const int n0   = blockIdx.x * 128;

    float acc[2][4][4];
#pragma unroll
    for (int mt = 0; mt < 2; mt++)
#pragma unroll
        for (int nt = 0; nt < 4; nt++)
#pragma unroll
            for (int r = 0; r < 4; r++) acc[mt][nt][r] = 0.f;

    // A tile: 64 rows x 8 granules = 512 uint4 -> 2/thread
    // B tile: 128 rows x 8 granules = 1024 uint4 -> 4/thread
    float4 rA[4], rB[8];
    auto load_tiles = [&](int k0) {
#pragma unroll
        for (int p = 0; p < 2; p++) {
            const int idx = tid + p * 256;
            const int r   = idx >> 3;
            const int gk  = k0 + (idx & 7) * 8;
            const float* ap = A + (size_t)(m0 + r) * K + gk;
            rA[p * 2]     = *reinterpret_cast<const float4*>(ap);
            rA[p * 2 + 1] = *reinterpret_cast<const float4*>(ap + 4);
        }
#pragma unroll
        for (int p = 0; p < 4; p++) {
            const int idx = tid + p * 256;
            const int r   = idx >> 3;
            const int gk  = k0 + (idx & 7) * 8;
            const float* wp = W + (size_t)(n0 + r) * K + gk;
            rB[p * 2]     = *reinterpret_cast<const float4*>(wp);
            rB[p * 2 + 1] = *reinterpret_cast<const float4*>(wp + 4);
        }
    };
    auto store_tiles = [&]() {
#pragma unroll
        for (int p = 0; p < 2; p++) {
            const int idx = tid + p * 256;
            const int r   = idx >> 3;
            const int g   = (idx & 7) ^ (r & 7);
            float4 a0 = rA[p * 2], a1 = rA[p * 2 + 1];
            uint4 ua;
            ua.x = pack_h2(a0.x, a0.y); ua.y = pack_h2(a0.z, a0.w);
            ua.z = pack_h2(a1.x, a1.y); ua.w = pack_h2(a1.z, a1.w);
            *reinterpret_cast<uint4*>(&As[r * 64 + g * 8]) = ua;
        }
#pragma unroll
        for (int p = 0; p < 4; p++) {
            const int idx = tid + p * 256;
            const int r   = idx >> 3;
            const int g   = (idx & 7) ^ (r & 7);
            float4 b0 = rB[p * 2], b1 = rB[p * 2 + 1];
            uint4 ub;
            ub.x = pack_h2(b0.x, b0.y); ub.y = pack_h2(b0.z, b0.w);
            ub.z = pack_h2(b1.x, b1.y); ub.w = pack_h2(b1.z, b1.w);
            *reinterpret_cast<uint4*>(&Bs[r * 64 + g * 8]) = ub;
        }
    };

    load_tiles(0);
    for (int k0 = 0; k0 < K; k0 += 64) {
        store_tiles();
        __syncthreads();
        if (k0 + 64 < K) load_tiles(k0 + 64);
#pragma unroll
        for (int ks = 0; ks < 4; ks++) {
            uint32_t af[2][4];
#pragma unroll
            for (int mt = 0; mt < 2; mt++) {
                const int r = wm + mt * 16 + gr;
                af[mt][0] = As32[sw_idx64(r,     2 * ks,     cc)];
                af[mt][1] = As32[sw_idx64(r + 8, 2 * ks,     cc)];
                af[mt][2] = As32[sw_idx64(r,     2 * ks + 1, cc)];
                af[mt][3] = As32[sw_idx64(r + 8, 2 * ks + 1, cc)];
            }
#pragma unroll
            for (int nt = 0; nt < 4; nt++) {
                const int n = wn + nt * 8 + gr;
                uint32_t b0 = Bs32[sw_idx64(n, 2 * ks,     cc)];
                uint32_t b1 = Bs32[sw_idx64(n, 2 * ks + 1, cc)];
#pragma unroll
                for (int mt = 0; mt < 2; mt++)
                    mma_f16(acc[mt][nt][0], acc[mt][nt][1], acc[mt][nt][2], acc[mt][nt][3],
                            af[mt][0], af[mt][1], af[mt][2], af[mt][3], b0, b1);
            }
        }
        __syncthreads();
    }

#pragma unroll
    for (int mt = 0; mt < 2; mt++) {
#pragma unroll
        for (int nt = 0; nt < 4; nt++) {
            const int row = m0 + wm + mt * 16 + gr;
            const int col = n0 + wn + nt * 8 + 2 * cc;
            const float b0v = bias[col], b1v = bias[col + 1];
            *reinterpret_cast<float2*>(C + (size_t)row * N + col) =
                make_float2(acc[mt][nt][0] + b0v, acc[mt][nt][1] + b1v);
            *reinterpret_cast<float2*>(C + (size_t)(row + 8) * N + col) =
                make_float2(acc[mt][nt][2] + b0v, acc[mt][nt][3] + b1v);
        }
    }
}

// ---------------------------------------------------------------------------
// V transpose: Vh[b*TK+key][h*64+d] -> Vt[((b*16+h)*64+d)*TK + key]
// ---------------------------------------------------------------------------
__global__ __launch_bounds__(256)
void vtrans(const __half* __restrict__ Vh, __half* __restrict__ Vt)
{
    __shared__ __half s[64][66];
    const int tid = threadIdx.x;
    const int bh  = blockIdx.y;
    const int b   = bh >> 4;
    const int h   = bh & 15;
    const int k0  = blockIdx.x * 64;

    const int d2 = tid & 31;
    const int kr = tid >> 5;
#pragma unroll
    for (int p = 0; p < 8; p++) {
        const int key = kr + p * 8;
        __half2 v = *reinterpret_cast<const __half2*>(
            Vh + ((size_t)(b * TKc + k0 + key)) * Dc + h * HDc + 2 * d2);
        *reinterpret_cast<__half2*>(&s[key][2 * d2]) = v;
    }
    __syncthreads();

    const int k2 = tid & 31;
    const int dr = tid >> 5;
#pragma unroll
    for (int p = 0; p < 8; p++) {
        const int d = dr + p * 8;
        __half2 v = __halves2half2(s[2 * k2][d], s[2 * k2 + 1][d]);
        *reinterpret_cast<__half2*>(
            Vt + ((size_t)(bh * HDc + d)) * TKc + k0 + 2 * k2) = v;
    }
}

// ---------------------------------------------------------------------------
// fp16 MMA flash attention, two segments. P held in registers (no smem P).
// 256 threads (8 warps), 128 q-rows/block, TS=128 keys per tile.
// Static smem: Ks 16KB + VtS 16KB = 32KB.
// ---------------------------------------------------------------------------
constexpr int TSa = 128;

__global__ __launch_bounds__(256)
void attn_f16(const float* __restrict__ Qp, const __half* __restrict__ Kh,
              const __half* __restrict__ Vt, float* __restrict__ At,
              const float* __restrict__ p_log_temp, const int* __restrict__ pNA)
{
    __shared__ __half Ks[128 * 64];
    __shared__ __half VtS[64 * 128];
    uint32_t* Ks32  = reinterpret_cast<uint32_t*>(Ks);
    uint32_t* VtS32 = reinterpret_cast<uint32_t*>(VtS);

    const int b    = blockIdx.z;
    const int h    = blockIdx.y;
    const int q0   = blockIdx.x * 128;
    const int tid  = threadIdx.x;
    const int warp = tid >> 5;
    const int lane = tid & 31;
    const int gr   = lane >> 2;
    const int cc   = lane & 3;
    const int rl   = warp * 16 + gr;      // local q row (and rl+8), 0..127
    const int row0 = q0 + rl;

    const int na = *pNA;
    float temp = __expf(*p_log_temp);
    temp = fminf(fmaxf(temp, 0.1f), 10.0f);
    const float scale = 1.0f / ((float)HDc * temp);

    // Q fragments (fp16, whole kernel): 4 k-steps x 4 regs
    uint32_t qf[4][4];
    {
        const float* qr0 = Qp + ((size_t)(b * TQc + row0)) * Dc + h * HDc;
        const float* qr1 = qr0 + 8 * (size_t)Dc;
#pragma unroll
        for (int ks = 0; ks < 4; ks++) {
            const int k = ks * 16;
            float2 a  = *reinterpret_cast<const float2*>(qr0 + k + 2 * cc);
            float2 bv = *reinterpret_cast<const float2*>(qr1 + k + 2 * cc);
            float2 c2 = *reinterpret_cast<const float2*>(qr0 + k + 8 + 2 * cc);
            float2 d2 = *reinterpret_cast<const float2*>(qr1 + k + 8 + 2 * cc);
            qf[ks][0] = pack_h2(a.x * scale, a.y * scale);
            qf[ks][1] = pack_h2(bv.x * scale, bv.y * scale);
            qf[ks][2] = pack_h2(c2.x * scale, c2.y * scale);
            qf[ks][3] = pack_h2(d2.x * scale, d2.y * scale);
        }
    }

    float outc[8][4];
#pragma unroll
    for (int nt = 0; nt < 8; nt++)
#pragma unroll
        for (int r = 0; r < 4; r++) outc[nt][r] = 0.f;

    const int lrow = tid >> 3;   // 0..31
    const int seg  = tid & 7;

    for (int segi = 0; segi < 2; segi++) {
        const int s_begin = segi ? na : 0;
        const int s_end   = segi ? TKc : na;
        const int s_cnt   = s_end - s_begin;
        if (s_cnt <= 0) continue;
        const float coef = (segi ? -1.f : 1.f) / sqrtf((float)s_cnt);

        float m0v = -INFINITY, m1v = -INFINITY;
        float l0 = 0.f, l1 = 0.f;
        float o[8][4];
#pragma unroll
        for (int nt = 0; nt < 8; nt++)
#pragma unroll
            for (int r = 0; r < 4; r++) o[nt][r] = 0.f;

        const int ntiles = (s_cnt + TSa - 1) / TSa;
        for (int tile = 0; tile < ntiles; tile++) {
            const int kbase = s_begin + tile * TSa;
            const int valid = min(TSa, s_end - kbase);
            const bool partial = (valid < TSa);

            __syncthreads();
            // K tile: 128 rows x 64 dims, 4 passes (256 threads)
#pragma unroll
            for (int p = 0; p < 4; p++) {
                const int r = lrow + p * 32;
                const int g = seg ^ (r & 7);
                uint4 v = make_uint4(0, 0, 0, 0);
                if (r < valid)
                    v = *reinterpret_cast<const uint4*>(
                        Kh + ((size_t)(b * TKc + kbase + r)) * Dc + h * HDc + seg * 8);
                *reinterpret_cast<uint4*>(&Ks[r * 64 + g * 8]) = v;
            }
            // Vt tile: 64 rows x 128 keys, 2 passes x 2 halves
#pragma unroll
            for (int p = 0; p < 2; p++) {
                const int r = lrow + p * 32;
                const __half* src = Vt + ((size_t)((b * NHc + h) * HDc + r)) * TKc + kbase;
                uint4 v0 = *reinterpret_cast<const uint4*>(src + seg * 8);
                uint4 v1 = *reinterpret_cast<const uint4*>(src + (seg + 8) * 8);
                const int g0 = seg ^ (r & 7);
                *reinterpret_cast<uint4*>(&VtS[r * 128 + g0 * 8]) = v0;
                *reinterpret_cast<uint4*>(&VtS[r * 128 + (g0 + 8) * 8]) = v1;
            }
            __syncthreads();

            // S = Q K^T : 16 n-tiles x 4 k-steps
            float sacc[16][4];
#pragma unroll
            for (int nt = 0; nt < 16; nt++)
#pragma unroll
                for (int r = 0; r < 4; r++) sacc[nt][r] = 0.f;
#pragma unroll
            for (int ks = 0; ks < 4; ks++) {
#pragma unroll
                for (int nt = 0; nt < 16; nt++) {
                    const int n = nt * 8 + gr;
                    uint32_t b0 = Ks32[sw_idx64(n, 2 * ks,     cc)];
                    uint32_t b1 = Ks32[sw_idx64(n, 2 * ks + 1, cc)];
                    mma_f16(sacc[nt][0], sacc[nt][1], sacc[nt][2], sacc[nt][3],
                            qf[ks][0], qf[ks][1], qf[ks][2], qf[ks][3], b0, b1);
                }
            }

            if (partial) {
#pragma unroll
                for (int nt = 0; nt < 16; nt++) {
                    const int col = nt * 8 + 2 * cc;
                    if (col     >= valid) { sacc[nt][0] = -INFINITY; sacc[nt][2] = -INFINITY; }
                    if (col + 1 >= valid) { sacc[nt][1] = -INFINITY; sacc[nt][3] = -INFINITY; }
                }
            }

            // online softmax
            float rm0 = -INFINITY, rm1 = -INFINITY;
#pragma unroll
            for (int nt = 0; nt < 16; nt++) {
                rm0 = fmaxf(rm0, fmaxf(sacc[nt][0], sacc[nt][1]));
                rm1 = fmaxf(rm1, fmaxf(sacc[nt][2], sacc[nt][3]));
            }
            rm0 = fmaxf(rm0, __shfl_xor_sync(0xffffffffu, rm0, 1));
            rm0 = fmaxf(rm0, __shfl_xor_sync(0xffffffffu, rm0, 2));
            rm1 = fmaxf(rm1, __shfl_xor_sync(0xffffffffu, rm1, 1));
            rm1 = fmaxf(rm1, __shfl_xor_sync(0xffffffffu, rm1, 2));
            const float nm0 = fmaxf(m0v, rm0);
            const float nm1 = fmaxf(m1v, rm1);
            const float corr0 = __expf(m0v - nm0);
            const float corr1 = __expf(m1v - nm1);
            m0v = nm0; m1v = nm1;
            l0 *= corr0; l1 *= corr1;
#pragma unroll
            for (int nt = 0; nt < 8; nt++) {
                o[nt][0] *= corr0; o[nt][1] *= corr0;
                o[nt][2] *= corr1; o[nt][3] *= corr1;
            }

            // exp -> P packed directly into A fragments (registers, no smem)
            uint32_t ap[8][4];
#pragma unroll
            for (int nt = 0; nt < 16; nt++) {
                float p0 = __expf(sacc[nt][0] - nm0);
                float p1 = __expf(sacc[nt][1] - nm0);
                float p2 = __expf(sacc[nt][2] - nm1);
                float p3 = __expf(sacc[nt][3] - nm1);
                l0 += p0 + p1;
                l1 += p2 + p3;
                const int kt   = nt >> 1;
                const int half = nt & 1;           // 0 -> a0/a1, 1 -> a2/a3
                ap[kt][half * 2]     = pack_h2(p0, p1);
                ap[kt][half * 2 + 1] = pack_h2(p2, p3);
            }

            // O += P V : 8 k-tiles x 8 n-tiles, A from registers
#pragma unroll
            for (int kt = 0; kt < 8; kt++) {
#pragma unroll
                for (int nt = 0; nt < 8; nt++) {
                    const int n = nt * 8 + gr;
                    uint32_t b0 = VtS32[sw_idx128(n, 2 * kt,     cc)];
                    uint32_t b1 = VtS32[sw_idx128(n, 2 * kt + 1, cc)];
                    mma_f16(o[nt][0], o[nt][1], o[nt][2], o[nt][3],
                            ap[kt][0], ap[kt][1], ap[kt][2], ap[kt][3], b0, b1);
                }
            }
        }

        l0 += __shfl_xor_sync(0xffffffffu, l0, 1);
        l0 += __shfl_xor_sync(0xffffffffu, l0, 2);
        l1 += __shfl_xor_sync(0xffffffffu, l1, 1);
        l1 += __shfl_xor_sync(0xffffffffu, l1, 2);
        const float inv0 = coef / l0;
        const float inv1 = coef / l1;
#pragma unroll
        for (int nt = 0; nt < 8; nt++) {
            outc[nt][0] += o[nt][0] * inv0;
            outc[nt][1] += o[nt][1] * inv0;
            outc[nt][2] += o[nt][2] * inv1;
            outc[nt][3] += o[nt][3] * inv1;
        }
    }

    float* ob = At + ((size_t)(b * TQc + row0)) * Dc + h * HDc;
#pragma unroll
    for (int nt = 0; nt < 8; nt++) {
        const int col = nt * 8 + 2 * cc;
        *reinterpret_cast<float2*>(ob + col) = make_float2(outc[nt][0], outc[nt][1]);
        *reinterpret_cast<float2*>(ob + 8 * (size_t)Dc + col) = make_float2(outc[nt][2], outc[nt][3]);
    }
}

// ---------------------------------------------------------------------------
// kernel_launch: plain kernel launches only, no statics, no attribute calls.
// ---------------------------------------------------------------------------
extern "C" void kernel_launch(void* const* d_in, const int* in_sizes, int n_in,
                              void* d_out, int out_size)
{
    const float* q    = (const float*)d_in[0];
    const float* kv   = (const float*)d_in[1];
    const float* Wq   = (const float*)d_in[2];
    const float* bq   = (const float*)d_in[3];
    const float* Wk   = (const float*)d_in[4];
    const float* bk   = (const float*)d_in[5];
    const float* Wv   = (const float*)d_in[6];
    const float* bv   = (const float*)d_in[7];
    const float* Wo   = (const float*)d_in[8];
    const float* bo   = (const float*)d_in[9];
    const float* abA  = (const float*)d_in[10];
    const float* abI  = (const float*)d_in[11];
    const float* logt = (const float*)d_in[12];
    const int*   pNA  = (const int*)d_in[13];
    float* out = (float*)d_out;

    void *pQp, *pA16, *pWk16, *pWv16, *pKh, *pVh, *pVt, *pAt;
    cudaGetSymbolAddress(&pQp,   g_Qp);
    cudaGetSymbolAddress(&pA16,  g_A16);
    cudaGetSymbolAddress(&pWk16, g_Wk16);
    cudaGetSymbolAddress(&pWv16, g_Wv16);
    cudaGetSymbolAddress(&pKh,   g_Kh);
    cudaGetSymbolAddress(&pVh,   g_Vh);
    cudaGetSymbolAddress(&pVt,   g_Vt);
    cudaGetSymbolAddress(&pAt,   g_At);

    const dim3 gblk(256);

    // prep: kv + group bias -> fp16; Wk, Wv -> fp16
    prep_kv<<<(Bc * TKc * Dc) / (256 * 8), gblk>>>(kv, abA, abI, pNA, (__half*)pA16);
    prep_w<<<(Dc * Dc) / (256 * 8), gblk>>>(Wk, (__half*)pWk16);
    prep_w<<<(Dc * Dc) / (256 * 8), gblk>>>(Wv, (__half*)pWv16);

    // Q projection -> fp32 (BM=64 for occupancy)
    gemm16b<<<dim3(Dc / 128, (Bc * TQc) / 64), gblk>>>(
        q, Wq, bq, (float*)pQp, Bc * TQc, Dc, Dc);

    // Fused K+V projection (fp16 in / fp16 out)
    kvgemm<<<dim3(Dc / 128, (Bc * TKc) / 128), dim3(512)>>>(
        (const __half*)pA16, (const __half*)pWk16, (const __half*)pWv16,
        bk, bv, (__half*)pKh, (__half*)pVh);

    // V transpose per (b,h)
    vtrans<<<dim3(TKc / 64, Bc * NHc), gblk>>>((const __half*)pVh, (__half*)pVt);

    // Two-segment attention (128 q-rows/block, P in registers, 32KB smem)
    attn_f16<<<dim3(TQc / 128, NHc, Bc), gblk>>>(
        (const float*)pQp, (const __half*)pKh, (const __half*)pVt, (float*)pAt,
        logt, pNA);

    // Output projection -> fp32 d_out (BM=64)
    gemm16b<<<dim3(Dc / 128, (Bc * TQc) / 64), gblk>>>(
        (const float*)pAt, Wo, bo, out, Bc * TQc, Dc, Dc);
}

// round 9
// speedup vs baseline: 13.1308x; 1.1291x over previous
#include <cuda_runtime.h>
#include <cuda_fp16.h>
#include <cstdint>
#include <math.h>

// Problem dimensions (fixed)
constexpr int Bc  = 2;
constexpr int TQc = 512;
constexpr int TKc = 8192;
constexpr int Dc  = 1024;
constexpr int NHc = 16;
constexpr int HDc = 64;

// Scratch (allocation-free)
__device__ float  g_Qp[(size_t)Bc * TQc * Dc];            // Q projected, fp32
__device__ __half g_A16[(size_t)Bc * TKc * Dc];           // kv + group bias, fp16
__device__ __half g_Wk16[(size_t)Dc * Dc];
__device__ __half g_Wv16[(size_t)Dc * Dc];
__device__ __half g_Kh[(size_t)Bc * TKc * Dc];            // K projected, fp16
__device__ __half g_Vh[(size_t)Bc * TKc * Dc];            // V projected, fp16
__device__ __half g_Vt[(size_t)Bc * NHc * HDc * TKc];     // V transposed [b,h,dim][key]
__device__ float  g_At[(size_t)Bc * TQc * Dc];            // attention out, fp32

// ---------------------------------------------------------------------------
// helpers
// ---------------------------------------------------------------------------
__device__ __forceinline__ uint32_t pack_h2(float lo, float hi) {
    __half2 h = __floats2half2_rn(lo, hi);
    return *reinterpret_cast<uint32_t*>(&h);
}

__device__ __forceinline__ void mma_f16(float& c0, float& c1, float& c2, float& c3,
                                        uint32_t a0, uint32_t a1, uint32_t a2, uint32_t a3,
                                        uint32_t b0, uint32_t b1)
{
    asm volatile(
        "mma.sync.aligned.m16n8k16.row.col.f32.f16.f16.f32 "
        "{%0,%1,%2,%3}, {%4,%5,%6,%7}, {%8,%9}, {%0,%1,%2,%3};"
        : "+f"(c0), "+f"(c1), "+f"(c2), "+f"(c3)
        : "r"(a0), "r"(a1), "r"(a2), "r"(a3), "r"(b0), "r"(b1));
}

// ldmatrix x4: 4 8x8 b16 matrices; lanes 0-7/8-15/16-23/24-31 give row addrs.
__device__ __forceinline__ void ldsm_x4(uint32_t& r0, uint32_t& r1,
                                        uint32_t& r2, uint32_t& r3, uint32_t addr)
{
    asm volatile("ldmatrix.sync.aligned.m8n8.x4.shared.b16 {%0,%1,%2,%3}, [%4];"
                 : "=r"(r0), "=r"(r1), "=r"(r2), "=r"(r3) : "r"(addr));
}

// swizzled u32 index, fp16 tile, row stride 64 halves (32 u32)
__device__ __forceinline__ int sw_idx64(int row, int gbase, int cc) {
    return row * 32 + ((gbase ^ (row & 7)) << 2) + cc;
}

// ---------------------------------------------------------------------------
// prep: kv(fp32) + group bias -> fp16 ; generic fp32 -> fp16 for weights
// ---------------------------------------------------------------------------
__global__ __launch_bounds__(256)
void prep_kv(const float* __restrict__ kv, const float* __restrict__ abA,
             const float* __restrict__ abI, const int* __restrict__ pNA,
             __half* __restrict__ dst)
{
    const int na = *pNA;
    const size_t i8 = (size_t)(blockIdx.x * 256 + threadIdx.x) * 8;  // 8 floats
    const int row = (int)(i8 >> 10);            // /Dc
    const int col = (int)(i8 & 1023);
    const float* ab = ((row % TKc) < na) ? abA : abI;
    float4 v0 = *reinterpret_cast<const float4*>(kv + i8);
    float4 v1 = *reinterpret_cast<const float4*>(kv + i8 + 4);
    float4 b0 = *reinterpret_cast<const float4*>(ab + col);
    float4 b1 = *reinterpret_cast<const float4*>(ab + col + 4);
    uint4 o;
    o.x = pack_h2(v0.x + b0.x, v0.y + b0.y);
    o.y = pack_h2(v0.z + b0.z, v0.w + b0.w);
    o.z = pack_h2(v1.x + b1.x, v1.y + b1.y);
    o.w = pack_h2(v1.z + b1.z, v1.w + b1.w);
    *reinterpret_cast<uint4*>(dst + i8) = o;
}

__global__ __launch_bounds__(256)
void prep_w(const float* __restrict__ src, __half* __restrict__ dst)
{
    const size_t i8 = (size_t)(blockIdx.x * 256 + threadIdx.x) * 8;
    float4 v0 = *reinterpret_cast<const float4*>(src + i8);
    float4 v1 = *reinterpret_cast<const float4*>(src + i8 + 4);
    uint4 o;
    o.x = pack_h2(v0.x, v0.y); o.y = pack_h2(v0.z, v0.w);
    o.z = pack_h2(v1.x, v1.y); o.w = pack_h2(v1.z, v1.w);
    *reinterpret_cast<uint4*>(dst + i8) = o;
}

// ---------------------------------------------------------------------------
// Fused K+V projection GEMM, fragment loads via ldmatrix.
// BM=BN=128, BK=64, 512 threads (16 warps), warp tile 32x32 (x2 outputs).
// Static smem 48KB, register-prefetch pipelined.
// ---------------------------------------------------------------------------
__global__ __launch_bounds__(512)
void kvgemm(const __half* __restrict__ A, const __half* __restrict__ Wk,
            const __half* __restrict__ Wv, const float* __restrict__ bk,
            const float* __restrict__ bv, __half* __restrict__ CK,
            __half* __restrict__ CV)
{
    __shared__ __half As[128 * 64];
    __shared__ __half Bks[128 * 64];
    __shared__ __half Bvs[128 * 64];

    const int tid  = threadIdx.x;
    const int warp = tid >> 5;
    const int lane = tid & 31;
    const int gr   = lane >> 2;
    const int cc   = lane & 3;
    const int lr   = lane & 7;      // row within ldmatrix 8x8
    const int lmh  = lane >> 4;     // (lm>>1): which k-half set of matrices
    const int lml  = (lane >> 3) & 1;
    const int wm   = (warp >> 2) * 32;
    const int wn   = (warp & 3) * 32;
    const int m0   = blockIdx.y * 128;
    const int n0   = blockIdx.x * 128;

    const uint32_t aBase = (uint32_t)__cvta_generic_to_shared(As);
    const uint32_t kBase = (uint32_t)__cvta_generic_to_shared(Bks);
    const uint32_t vBase = (uint32_t)__cvta_generic_to_shared(Bvs);

    float accK[2][4][4], accV[2][4][4];
#pragma unroll
    for (int mt = 0; mt < 2; mt++)
#pragma unroll
        for (int nt = 0; nt < 4; nt++)
#pragma unroll
            for (int r = 0; r < 4; r++) { accK[mt][nt][r] = 0.f; accV[mt][nt][r] = 0.f; }

    uint4 rA[2], rK[2], rV[2];
    auto load_tiles = [&](int k0) {
#pragma unroll
        for (int p = 0; p < 2; p++) {
            const int idx = tid + p * 512;
            const int r   = idx >> 3;
            const int g0  = idx & 7;
            const size_t goff = (size_t)g0 * 8 + k0;
            rA[p] = *reinterpret_cast<const uint4*>(A  + (size_t)(m0 + r) * Dc + goff);
            rK[p] = *reinterpret_cast<const uint4*>(Wk + (size_t)(n0 + r) * Dc + goff);
            rV[p] = *reinterpret_cast<const uint4*>(Wv + (size_t)(n0 + r) * Dc + goff);
        }
    };
    auto store_tiles = [&]() {
#pragma unroll
        for (int p = 0; p < 2; p++) {
            const int idx = tid + p * 512;
            const int r   = idx >> 3;
            const int g   = (idx & 7) ^ (r & 7);
            *reinterpret_cast<uint4*>(&As[r * 64 + g * 8])  = rA[p];
            *reinterpret_cast<uint4*>(&Bks[r * 64 + g * 8]) = rK[p];
            *reinterpret_cast<uint4*>(&Bvs[r * 64 + g * 8]) = rV[p];
        }
    };

    load_tiles(0);
    for (int k0 = 0; k0 < Dc; k0 += 64) {
        store_tiles();
        __syncthreads();
        if (k0 + 64 < Dc) load_tiles(k0 + 64);

#pragma unroll
        for (int ks = 0; ks < 4; ks++) {
            // A fragments: 2 LDSM.x4 (matrices: rows lo/hi x k lo/hi)
            uint32_t af[2][4];
#pragma unroll
            for (int mt = 0; mt < 2; mt++) {
                const int r  = wm + mt * 16 + lml * 8 + lr;
                const int lg = 2 * ks + lmh;
                ldsm_x4(af[mt][0], af[mt][1], af[mt][2], af[mt][3],
                        aBase + (uint32_t)(r * 128 + ((lg ^ (r & 7)) << 4)));
            }
            // B fragments (K and V): 2 LDSM.x4 each (nt pairs)
            uint32_t bkf[8], bvf[8];
#pragma unroll
            for (int j = 0; j < 2; j++) {
                const int n  = wn + (2 * j + lmh) * 8 + lr;
                const int lg = 2 * ks + lml;
                const uint32_t off = (uint32_t)(n * 128 + ((lg ^ (n & 7)) << 4));
                ldsm_x4(bkf[4 * j], bkf[4 * j + 1], bkf[4 * j + 2], bkf[4 * j + 3], kBase + off);
                ldsm_x4(bvf[4 * j], bvf[4 * j + 1], bvf[4 * j + 2], bvf[4 * j + 3], vBase + off);
            }
#pragma unroll
            for (int nt = 0; nt < 4; nt++) {
                const int bi = 4 * (nt >> 1) + 2 * (nt & 1);
#pragma unroll
                for (int mt = 0; mt < 2; mt++) {
                    mma_f16(accK[mt][nt][0], accK[mt][nt][1], accK[mt][nt][2], accK[mt][nt][3],
                            af[mt][0], af[mt][1], af[mt][2], af[mt][3], bkf[bi], bkf[bi + 1]);
                    mma_f16(accV[mt][nt][0], accV[mt][nt][1], accV[mt][nt][2], accV[mt][nt][3],
                            af[mt][0], af[mt][1], af[mt][2], af[mt][3], bvf[bi], bvf[bi + 1]);
                }
            }
        }
        __syncthreads();
    }

#pragma unroll
    for (int mt = 0; mt < 2; mt++) {
#pragma unroll
        for (int nt = 0; nt < 4; nt++) {
            const int row = m0 + wm + mt * 16 + gr;
            const int col = n0 + wn + nt * 8 + 2 * cc;
            const float bk0 = bk[col], bk1 = bk[col + 1];
            const float bv0 = bv[col], bv1 = bv[col + 1];
            __half2* CKp = (__half2*)CK;
            __half2* CVp = (__half2*)CV;
            CKp[((size_t)row * Dc + col) >> 1] =
                __floats2half2_rn(accK[mt][nt][0] + bk0, accK[mt][nt][1] + bk1);
            CKp[((size_t)(row + 8) * Dc + col) >> 1] =
                __floats2half2_rn(accK[mt][nt][2] + bk0, accK[mt][nt][3] + bk1);
            CVp[((size_t)row * Dc + col) >> 1] =
                __floats2half2_rn(accV[mt][nt][0] + bv0, accV[mt][nt][1] + bv1);
            CVp[((size_t)(row + 8) * Dc + col) >> 1] =
                __floats2half2_rn(accV[mt][nt][2] + bv0, accV[mt][nt][3] + bv1);
        }
    }
}

// ---------------------------------------------------------------------------
// fp16 GEMM for Q / O projections, BM=64 x BN=128 (unchanged from R8).
// ---------------------------------------------------------------------------
__global__ __launch_bounds__(256)
void gemm16b(const float* __restrict__ A, const float* __restrict__ W,
             const float* __restrict__ bias, float* __restrict__ C,
             int M, int N, int K)
{
    __shared__ __half As[64 * 64];     // 8 KB
    __shared__ __half Bs[128 * 64];    // 16 KB
    uint32_t* As32 = reinterpret_cast<uint32_t*>(As);
    uint32_t* Bs32 = reinterpret_cast<uint32_t*>(Bs);

    const int tid  = threadIdx.x;
    const int warp = tid >> 5;
    const int lane = tid & 31;
    const int gr   = lane >> 2;
    const int cc   = lane & 3;
    const int wm   = (warp >> 2) * 32;
    const int wn   = (warp & 3) * 32;
    const int m0   = blockIdx.y * 64;
    const int n0   = blockIdx.x * 128;

    float acc[2][4][4];
#pragma unroll
    for (int mt = 0; mt < 2; mt++)
#pragma unroll
        for (int nt = 0; nt < 4; nt++)
#pragma unroll
            for (int r = 0; r < 4; r++) acc[mt][nt][r] = 0.f;

    float4 rA[4], rB[8];
    auto load_tiles = [&](int k0) {
#pragma unroll
        for (int p = 0; p < 2; p++) {
            const int idx = tid + p * 256;
            const int r   = idx >> 3;
            const int gk  = k0 + (idx & 7) * 8;
            const float* ap = A + (size_t)(m0 + r) * K + gk;
            rA[p * 2]     = *reinterpret_cast<const float4*>(ap);
            rA[p * 2 + 1] = *reinterpret_cast<const float4*>(ap + 4);
        }
#pragma unroll
        for (int p = 0; p < 4; p++) {
            const int idx = tid + p * 256;
            const int r   = idx >> 3;
            const int gk  = k0 + (idx & 7) * 8;
            const float* wp = W + (size_t)(n0 + r) * K + gk;
            rB[p * 2]     = *reinterpret_cast<const float4*>(wp);
            rB[p * 2 + 1] = *reinterpret_cast<const float4*>(wp + 4);
        }
    };
    auto store_tiles = [&]() {
#pragma unroll
        for (int p = 0; p < 2; p++) {
            const int idx = tid + p * 256;
            const int r   = idx >> 3;
            const int g   = (idx & 7) ^ (r & 7);
            float4 a0 = rA[p * 2], a1 = rA[p * 2 + 1];
            uint4 ua;
            ua.x = pack_h2(a0.x, a0.y); ua.y = pack_h2(a0.z, a0.w);
            ua.z = pack_h2(a1.x, a1.y); ua.w = pack_h2(a1.z, a1.w);
            *reinterpret_cast<uint4*>(&As[r * 64 + g * 8]) = ua;
        }
#pragma unroll
        for (int p = 0; p < 4; p++) {
            const int idx = tid + p * 256;
            const int r   = idx >> 3;
            const int g   = (idx & 7) ^ (r & 7);
            float4 b0 = rB[p * 2], b1 = rB[p * 2 + 1];
            uint4 ub;
            ub.x = pack_h2(b0.x, b0.y); ub.y = pack_h2(b0.z, b0.w);
            ub.z = pack_h2(b1.x, b1.y); ub.w = pack_h2(b1.z, b1.w);
            *reinterpret_cast<uint4*>(&Bs[r * 64 + g * 8]) = ub;
        }
    };

    load_tiles(0);
    for (int k0 = 0; k0 < K; k0 += 64) {
        store_tiles();
        __syncthreads();
        if (k0 + 64 < K) load_tiles(k0 + 64);
#pragma unroll
        for (int ks = 0; ks < 4; ks++) {
            uint32_t af[2][4];
#pragma unroll
            for (int mt = 0; mt < 2; mt++) {
                const int r = wm + mt * 16 + gr;
                af[mt][0] = As32[sw_idx64(r,     2 * ks,     cc)];
                af[mt][1] = As32[sw_idx64(r + 8, 2 * ks,     cc)];
                af[mt][2] = As32[sw_idx64(r,     2 * ks + 1, cc)];
                af[mt][3] = As32[sw_idx64(r + 8, 2 * ks + 1, cc)];
            }
#pragma unroll
            for (int nt = 0; nt < 4; nt++) {
                const int n = wn + nt * 8 + gr;
                uint32_t b0 = Bs32[sw_idx64(n, 2 * ks,     cc)];
                uint32_t b1 = Bs32[sw_idx64(n, 2 * ks + 1, cc)];
#pragma unroll
                for (int mt = 0; mt < 2; mt++)
                    mma_f16(acc[mt][nt][0], acc[mt][nt][1], acc[mt][nt][2], acc[mt][nt][3],
                            af[mt][0], af[mt][1], af[mt][2], af[mt][3], b0, b1);
            }
        }
        __syncthreads();
    }

#pragma unroll
    for (int mt = 0; mt < 2; mt++) {
#pragma unroll
        for (int nt = 0; nt < 4; nt++) {
            const int row = m0 + wm + mt * 16 + gr;
            const int col = n0 + wn + nt * 8 + 2 * cc;
            const float b0v = bias[col], b1v = bias[col + 1];
            *reinterpret_cast<float2*>(C + (size_t)row * N + col) =
                make_float2(acc[mt][nt][0] + b0v, acc[mt][nt][1] + b1v);
            *reinterpret_cast<float2*>(C + (size_t)(row + 8) * N + col) =
                make_float2(acc[mt][nt][2] + b0v, acc[mt][nt][3] + b1v);
        }
    }
}

// ---------------------------------------------------------------------------
// V transpose: Vh[b*TK+key][h*64+d] -> Vt[((b*16+h)*64+d)*TK + key]
// ---------------------------------------------------------------------------
__global__ __launch_bounds__(256)
void vtrans(const __half* __restrict__ Vh, __half* __restrict__ Vt)
{
    __shared__ __half s[64][66];
    const int tid = threadIdx.x;
    const int bh  = blockIdx.y;
    const int b   = bh >> 4;
    const int h   = bh & 15;
    const int k0  = blockIdx.x * 64;

    const int d2 = tid & 31;
    const int kr = tid >> 5;
#pragma unroll
    for (int p = 0; p < 8; p++) {
        const int key = kr + p * 8;
        __half2 v = *reinterpret_cast<const __half2*>(
            Vh + ((size_t)(b * TKc + k0 + key)) * Dc + h * HDc + 2 * d2);
        *reinterpret_cast<__half2*>(&s[key][2 * d2]) = v;
    }
    __syncthreads();

    const int k2 = tid & 31;
    const int dr = tid >> 5;
#pragma unroll
    for (int p = 0; p < 8; p++) {
        const int d = dr + p * 8;
        __half2 v = __halves2half2(s[2 * k2][d], s[2 * k2 + 1][d]);
        *reinterpret_cast<__half2*>(
            Vt + ((size_t)(bh * HDc + d)) * TKc + k0 + 2 * k2) = v;
    }
}

// ---------------------------------------------------------------------------
// fp16 MMA flash attention, two segments. P in registers; B-frags via ldmatrix.
// 256 threads (8 warps), 128 q-rows/block, TS=128 keys per tile. 32KB smem.
// ---------------------------------------------------------------------------
constexpr int TSa = 128;

__global__ __launch_bounds__(256)
void attn_f16(const float* __restrict__ Qp, const __half* __restrict__ Kh,
              const __half* __restrict__ Vt, float* __restrict__ At,
              const float* __restrict__ p_log_temp, const int* __restrict__ pNA)
{
    __shared__ __half Ks[128 * 64];
    __shared__ __half VtS[64 * 128];

    const int b    = blockIdx.z;
    const int h    = blockIdx.y;
    const int q0   = blockIdx.x * 128;
    const int tid  = threadIdx.x;
    const int warp = tid >> 5;
    const int lane = tid & 31;
    const int gr   = lane >> 2;
    const int cc   = lane & 3;
    const int lr   = lane & 7;
    const int lmh  = lane >> 4;
    const int lml  = (lane >> 3) & 1;
    const int rl   = warp * 16 + gr;
    const int row0 = q0 + rl;

    const uint32_t ksBase  = (uint32_t)__cvta_generic_to_shared(Ks);
    const uint32_t vtsBase = (uint32_t)__cvta_generic_to_shared(VtS);

    const int na = *pNA;
    float temp = __expf(*p_log_temp);
    temp = fminf(fmaxf(temp, 0.1f), 10.0f);
    const float scale = 1.0f / ((float)HDc * temp);

    // Q fragments (fp16, whole kernel): 4 k-steps x 4 regs
    uint32_t qf[4][4];
    {
        const float* qr0 = Qp + ((size_t)(b * TQc + row0)) * Dc + h * HDc;
        const float* qr1 = qr0 + 8 * (size_t)Dc;
#pragma unroll
        for (int ks = 0; ks < 4; ks++) {
            const int k = ks * 16;
            float2 a  = *reinterpret_cast<const float2*>(qr0 + k + 2 * cc);
            float2 bv = *reinterpret_cast<const float2*>(qr1 + k + 2 * cc);
            float2 c2 = *reinterpret_cast<const float2*>(qr0 + k + 8 + 2 * cc);
            float2 d2 = *reinterpret_cast<const float2*>(qr1 + k + 8 + 2 * cc);
            qf[ks][0] = pack_h2(a.x * scale, a.y * scale);
            qf[ks][1] = pack_h2(bv.x * scale, bv.y * scale);
            qf[ks][2] = pack_h2(c2.x * scale, c2.y * scale);
            qf[ks][3] = pack_h2(d2.x * scale, d2.y * scale);
        }
    }

    float outc[8][4];
#pragma unroll
    for (int nt = 0; nt < 8; nt++)
#pragma unroll
        for (int r = 0; r < 4; r++) outc[nt][r] = 0.f;

    const int lrow = tid >> 3;   // 0..31
    const int seg  = tid & 7;

    for (int segi = 0; segi < 2; segi++) {
        const int s_begin = segi ? na : 0;
        const int s_end   = segi ? TKc : na;
        const int s_cnt   = s_end - s_begin;
        if (s_cnt <= 0) continue;
        const float coef = (segi ? -1.f : 1.f) / sqrtf((float)s_cnt);

        float m0v = -INFINITY, m1v = -INFINITY;
        float l0 = 0.f, l1 = 0.f;
        float o[8][4];
#pragma unroll
        for (int nt = 0; nt < 8; nt++)
#pragma unroll
            for (int r = 0; r < 4; r++) o[nt][r] = 0.f;

        const int ntiles = (s_cnt + TSa - 1) / TSa;
        for (int tile = 0; tile < ntiles; tile++) {
            const int kbase = s_begin + tile * TSa;
            const int valid = min(TSa, s_end - kbase);
            const bool partial = (valid < TSa);

            __syncthreads();
            // K tile: 128 rows x 64 dims, 4 passes (256 threads)
#pragma unroll
            for (int p = 0; p < 4; p++) {
                const int r = lrow + p * 32;
                const int g = seg ^ (r & 7);
                uint4 v = make_uint4(0, 0, 0, 0);
                if (r < valid)
                    v = *reinterpret_cast<const uint4*>(
                        Kh + ((size_t)(b * TKc + kbase + r)) * Dc + h * HDc + seg * 8);
                *reinterpret_cast<uint4*>(&Ks[r * 64 + g * 8]) = v;
            }
            // Vt tile: 64 rows x 128 keys, 2 passes x 2 halves
#pragma unroll
            for (int p = 0; p < 2; p++) {
                const int r = lrow + p * 32;
                const __half* src = Vt + ((size_t)((b * NHc + h) * HDc + r)) * TKc + kbase;
                uint4 v0 = *reinterpret_cast<const uint4*>(src + seg * 8);
                uint4 v1 = *reinterpret_cast<const uint4*>(src + (seg + 8) * 8);
                const int g0 = seg ^ (r & 7);
                *reinterpret_cast<uint4*>(&VtS[r * 128 + g0 * 8]) = v0;
                *reinterpret_cast<uint4*>(&VtS[r * 128 + (g0 + 8) * 8]) = v1;
            }
            __syncthreads();

            // S = Q K^T : 16 n-tiles x 4 k-steps, B frags via LDSM (nt pairs)
            float sacc[16][4];
#pragma unroll
            for (int nt = 0; nt < 16; nt++)
#pragma unroll
                for (int r = 0; r < 4; r++) sacc[nt][r] = 0.f;
#pragma unroll
            for (int ks = 0; ks < 4; ks++) {
#pragma unroll
                for (int j = 0; j < 8; j++) {
                    const int n  = (2 * j + lmh) * 8 + lr;
                    const int lg = 2 * ks + lml;
                    uint32_t f0, f1, f2, f3;
                    ldsm_x4(f0, f1, f2, f3,
                            ksBase + (uint32_t)(n * 128 + ((lg ^ (n & 7)) << 4)));
                    mma_f16(sacc[2*j][0], sacc[2*j][1], sacc[2*j][2], sacc[2*j][3],
                            qf[ks][0], qf[ks][1], qf[ks][2], qf[ks][3], f0, f1);
                    mma_f16(sacc[2*j+1][0], sacc[2*j+1][1], sacc[2*j+1][2], sacc[2*j+1][3],
                            qf[ks][0], qf[ks][1], qf[ks][2], qf[ks][3], f2, f3);
                }
            }

            if (partial) {
#pragma unroll
                for (int nt = 0; nt < 16; nt++) {
                    const int col = nt * 8 + 2 * cc;
                    if (col     >= valid) { sacc[nt][0] = -INFINITY; sacc[nt][2] = -INFINITY; }
                    if (col + 1 >= valid) { sacc[nt][1] = -INFINITY; sacc[nt][3] = -INFINITY; }
                }
            }

            // online softmax
            float rm0 = -INFINITY, rm1 = -INFINITY;
#pragma unroll
            for (int nt = 0; nt < 16; nt++) {
                rm0 = fmaxf(rm0, fmaxf(sacc[nt][0], sacc[nt][1]));
                rm1 = fmaxf(rm1, fmaxf(sacc[nt][2], sacc[nt][3]));
            }
            rm0 = fmaxf(rm0, __shfl_xor_sync(0xffffffffu, rm0, 1));
            rm0 = fmaxf(rm0, __shfl_xor_sync(0xffffffffu, rm0, 2));
            rm1 = fmaxf(rm1, __shfl_xor_sync(0xffffffffu, rm1, 1));
            rm1 = fmaxf(rm1, __shfl_xor_sync(0xffffffffu, rm1, 2));
            const float nm0 = fmaxf(m0v, rm0);
            const float nm1 = fmaxf(m1v, rm1);
            const float corr0 = __expf(m0v - nm0);
            const float corr1 = __expf(m1v - nm1);
            m0v = nm0; m1v = nm1;
            l0 *= corr0; l1 *= corr1;
#pragma unroll
            for (int nt = 0; nt < 8; nt++) {
                o[nt][0] *= corr0; o[nt][1] *= corr0;
                o[nt][2] *= corr1; o[nt][3] *= corr1;
            }

            // exp -> P packed directly into A fragments (registers, no smem)
            uint32_t ap[8][4];
#pragma unroll
            for (int nt = 0; nt < 16; nt++) {
                float p0 = __expf(sacc[nt][0] - nm0);
                float p1 = __expf(sacc[nt][1] - nm0);
                float p2 = __expf(sacc[nt][2] - nm1);
                float p3 = __expf(sacc[nt][3] - nm1);
                l0 += p0 + p1;
                l1 += p2 + p3;
                const int kt   = nt >> 1;
                const int half = nt & 1;
                ap[kt][half * 2]     = pack_h2(p0, p1);
                ap[kt][half * 2 + 1] = pack_h2(p2, p3);
            }

            // O += P V : 8 k-tiles x 8 n-tiles, B frags via LDSM (nt pairs)
#pragma unroll
            for (int kt = 0; kt < 8; kt++) {
#pragma unroll
                for (int j = 0; j < 4; j++) {
                    const int n  = (2 * j + lmh) * 8 + lr;
                    const int lg = 2 * kt + lml;
                    uint32_t f0, f1, f2, f3;
                    ldsm_x4(f0, f1, f2, f3,
                            vtsBase + (uint32_t)(n * 256 + ((lg ^ (n & 7)) << 4)));
                    mma_f16(o[2*j][0], o[2*j][1], o[2*j][2], o[2*j][3],
                            ap[kt][0], ap[kt][1], ap[kt][2], ap[kt][3], f0, f1);
                    mma_f16(o[2*j+1][0], o[2*j+1][1], o[2*j+1][2], o[2*j+1][3],
                            ap[kt][0], ap[kt][1], ap[kt][2], ap[kt][3], f2, f3);
                }
            }
        }

        l0 += __shfl_xor_sync(0xffffffffu, l0, 1);
        l0 += __shfl_xor_sync(0xffffffffu, l0, 2);
        l1 += __shfl_xor_sync(0xffffffffu, l1, 1);
        l1 += __shfl_xor_sync(0xffffffffu, l1, 2);
        const float inv0 = coef / l0;
        const float inv1 = coef / l1;
#pragma unroll
        for (int nt = 0; nt < 8; nt++) {
            outc[nt][0] += o[nt][0] * inv0;
            outc[nt][1] += o[nt][1] * inv0;
            outc[nt][2] += o[nt][2] * inv1;
            outc[nt][3] += o[nt][3] * inv1;
        }
    }

    float* ob = At + ((size_t)(b * TQc + row0)) * Dc + h * HDc;
#pragma unroll
    for (int nt = 0; nt < 8; nt++) {
        const int col = nt * 8 + 2 * cc;
        *reinterpret_cast<float2*>(ob + col) = make_float2(outc[nt][0], outc[nt][1]);
        *reinterpret_cast<float2*>(ob + 8 * (size_t)Dc + col) = make_float2(outc[nt][2], outc[nt][3]);
    }
}

// ---------------------------------------------------------------------------
// kernel_launch: plain kernel launches only, no statics, no attribute calls.
// ---------------------------------------------------------------------------
extern "C" void kernel_launch(void* const* d_in, const int* in_sizes, int n_in,
                              void* d_out, int out_size)
{
    const float* q    = (const float*)d_in[0];
    const float* kv   = (const float*)d_in[1];
    const float* Wq   = (const float*)d_in[2];
    const float* bq   = (const float*)d_in[3];
    const float* Wk   = (const float*)d_in[4];
    const float* bk   = (const float*)d_in[5];
    const float* Wv   = (const float*)d_in[6];
    const float* bv   = (const float*)d_in[7];
    const float* Wo   = (const float*)d_in[8];
    const float* bo   = (const float*)d_in[9];
    const float* abA  = (const float*)d_in[10];
    const float* abI  = (const float*)d_in[11];
    const float* logt = (const float*)d_in[12];
    const int*   pNA  = (const int*)d_in[13];
    float* out = (float*)d_out;

    void *pQp, *pA16, *pWk16, *pWv16, *pKh, *pVh, *pVt, *pAt;
    cudaGetSymbolAddress(&pQp,   g_Qp);
    cudaGetSymbolAddress(&pA16,  g_A16);
    cudaGetSymbolAddress(&pWk16, g_Wk16);
    cudaGetSymbolAddress(&pWv16, g_Wv16);
    cudaGetSymbolAddress(&pKh,   g_Kh);
    cudaGetSymbolAddress(&pVh,   g_Vh);
    cudaGetSymbolAddress(&pVt,   g_Vt);
    cudaGetSymbolAddress(&pAt,   g_At);

    const dim3 gblk(256);

    // prep: kv + group bias -> fp16; Wk, Wv -> fp16
    prep_kv<<<(Bc * TKc * Dc) / (256 * 8), gblk>>>(kv, abA, abI, pNA, (__half*)pA16);
    prep_w<<<(Dc * Dc) / (256 * 8), gblk>>>(Wk, (__half*)pWk16);
    prep_w<<<(Dc * Dc) / (256 * 8), gblk>>>(Wv, (__half*)pWv16);

    // Q projection -> fp32 (BM=64 for occupancy)
    gemm16b<<<dim3(Dc / 128, (Bc * TQc) / 64), gblk>>>(
        q, Wq, bq, (float*)pQp, Bc * TQc, Dc, Dc);

    // Fused K+V projection (fp16 in / fp16 out), ldmatrix fragment loads
    kvgemm<<<dim3(Dc / 128, (Bc * TKc) / 128), dim3(512)>>>(
        (const __half*)pA16, (const __half*)pWk16, (const __half*)pWv16,
        bk, bv, (__half*)pKh, (__half*)pVh);

    // V transpose per (b,h)
    vtrans<<<dim3(TKc / 64, Bc * NHc), gblk>>>((const __half*)pVh, (__half*)pVt);

    // Two-segment attention (128 q-rows/block, P in regs, ldmatrix B-frags)
    attn_f16<<<dim3(TQc / 128, NHc, Bc), gblk>>>(
        (const float*)pQp, (const __half*)pKh, (const __half*)pVt, (float*)pAt,
        logt, pNA);

    // Output projection -> fp32 d_out (BM=64)
    gemm16b<<<dim3(Dc / 128, (Bc * TQc) / 64), gblk>>>(
        (const float*)pAt, Wo, bo, out, Bc * TQc, Dc, Dc);
}

// round 11
// speedup vs baseline: 13.9542x; 1.0627x over previous
#include <cuda_runtime.h>
#include <cuda_fp16.h>
#include <cstdint>
#include <math.h>

// Problem dimensions (fixed)
constexpr int Bc  = 2;
constexpr int TQc = 512;
constexpr int TKc = 8192;
constexpr int Dc  = 1024;
constexpr int NHc = 16;
constexpr int HDc = 64;

// Scratch (allocation-free)
__device__ float  g_Qp[(size_t)Bc * TQc * Dc];            // Q projected, fp32
__device__ __half g_A16[(size_t)Bc * TKc * Dc];           // kv + group bias, fp16
__device__ __half g_Wk16[(size_t)Dc * Dc];
__device__ __half g_Wv16[(size_t)Dc * Dc];
__device__ __half g_Kh[(size_t)Bc * TKc * Dc];            // K projected, fp16
__device__ __half g_Vt[(size_t)Bc * NHc * HDc * TKc];     // V transposed [b,h,dim][key]
__device__ float  g_At[(size_t)Bc * TQc * Dc];            // attention out, fp32

// ---------------------------------------------------------------------------
// helpers
// ---------------------------------------------------------------------------
__device__ __forceinline__ uint32_t pack_h2(float lo, float hi) {
    __half2 h = __floats2half2_rn(lo, hi);
    return *reinterpret_cast<uint32_t*>(&h);
}

__device__ __forceinline__ void mma_f16(float& c0, float& c1, float& c2, float& c3,
                                        uint32_t a0, uint32_t a1, uint32_t a2, uint32_t a3,
                                        uint32_t b0, uint32_t b1)
{
    asm volatile(
        "mma.sync.aligned.m16n8k16.row.col.f32.f16.f16.f32 "
        "{%0,%1,%2,%3}, {%4,%5,%6,%7}, {%8,%9}, {%0,%1,%2,%3};"
        : "+f"(c0), "+f"(c1), "+f"(c2), "+f"(c3)
        : "r"(a0), "r"(a1), "r"(a2), "r"(a3), "r"(b0), "r"(b1));
}

__device__ __forceinline__ void ldsm_x4(uint32_t& r0, uint32_t& r1,
                                        uint32_t& r2, uint32_t& r3, uint32_t addr)
{
    asm volatile("ldmatrix.sync.aligned.m8n8.x4.shared.b16 {%0,%1,%2,%3}, [%4];"
                 : "=r"(r0), "=r"(r1), "=r"(r2), "=r"(r3) : "r"(addr));
}

// swizzled u32 index, fp16 tile, row stride 64 halves (32 u32)
__device__ __forceinline__ int sw_idx64(int row, int gbase, int cc) {
    return row * 32 + ((gbase ^ (row & 7)) << 2) + cc;
}

// ---------------------------------------------------------------------------
// prep: kv(fp32) + group bias -> fp16 ; generic fp32 -> fp16 for weights
// ---------------------------------------------------------------------------
__global__ __launch_bounds__(256)
void prep_kv(const float* __restrict__ kv, const float* __restrict__ abA,
             const float* __restrict__ abI, const int* __restrict__ pNA,
             __half* __restrict__ dst)
{
    const int na = *pNA;
    const size_t i8 = (size_t)(blockIdx.x * 256 + threadIdx.x) * 8;  // 8 floats
    const int row = (int)(i8 >> 10);            // /Dc
    const int col = (int)(i8 & 1023);
    const float* ab = ((row % TKc) < na) ? abA : abI;
    float4 v0 = *reinterpret_cast<const float4*>(kv + i8);
    float4 v1 = *reinterpret_cast<const float4*>(kv + i8 + 4);
    float4 b0 = *reinterpret_cast<const float4*>(ab + col);
    float4 b1 = *reinterpret_cast<const float4*>(ab + col + 4);
    uint4 o;
    o.x = pack_h2(v0.x + b0.x, v0.y + b0.y);
    o.y = pack_h2(v0.z + b0.z, v0.w + b0.w);
    o.z = pack_h2(v1.x + b1.x, v1.y + b1.y);
    o.w = pack_h2(v1.z + b1.z, v1.w + b1.w);
    *reinterpret_cast<uint4*>(dst + i8) = o;
}

__global__ __launch_bounds__(256)
void prep_w(const float* __restrict__ src, __half* __restrict__ dst)
{
    const size_t i8 = (size_t)(blockIdx.x * 256 + threadIdx.x) * 8;
    float4 v0 = *reinterpret_cast<const float4*>(src + i8);
    float4 v1 = *reinterpret_cast<const float4*>(src + i8 + 4);
    uint4 o;
    o.x = pack_h2(v0.x, v0.y); o.y = pack_h2(v0.z, v0.w);
    o.z = pack_h2(v1.x, v1.y); o.w = pack_h2(v1.z, v1.w);
    *reinterpret_cast<uint4*>(dst + i8) = o;
}

// ---------------------------------------------------------------------------
// Fused K+V projection GEMM; V written TRANSPOSED into g_Vt (vtrans fused).
// BM=BN=128, BK=64, 512 threads (16 warps), warp tile 32x32 (x2 outputs).
// Static smem 48KB (3 tiles in mainloop; V-transpose staging in epilogue).
// ---------------------------------------------------------------------------
__global__ __launch_bounds__(512)
void kvgemm(const __half* __restrict__ A, const __half* __restrict__ Wk,
            const __half* __restrict__ Wv, const float* __restrict__ bk,
            const float* __restrict__ bv, __half* __restrict__ CK,
            __half* __restrict__ Vt)
{
    __shared__ __half sm[3 * 128 * 64];   // 48 KB
    __half* As  = sm;
    __half* Bks = sm + 128 * 64;
    __half* Bvs = sm + 2 * 128 * 64;

    const int tid  = threadIdx.x;
    const int warp = tid >> 5;
    const int lane = tid & 31;
    const int gr   = lane >> 2;
    const int cc   = lane & 3;
    const int lr   = lane & 7;
    const int lmh  = lane >> 4;
    const int lml  = (lane >> 3) & 1;
    const int wm   = (warp >> 2) * 32;
    const int wn   = (warp & 3) * 32;
    const int m0   = blockIdx.y * 128;
    const int n0   = blockIdx.x * 128;

    const uint32_t aBase = (uint32_t)__cvta_generic_to_shared(As);
    const uint32_t kBase = (uint32_t)__cvta_generic_to_shared(Bks);
    const uint32_t vBase = (uint32_t)__cvta_generic_to_shared(Bvs);

    float accK[2][4][4], accV[2][4][4];
#pragma unroll
    for (int mt = 0; mt < 2; mt++)
#pragma unroll
        for (int nt = 0; nt < 4; nt++)
#pragma unroll
            for (int r = 0; r < 4; r++) { accK[mt][nt][r] = 0.f; accV[mt][nt][r] = 0.f; }

    uint4 rA[2], rK[2], rV[2];
    auto load_tiles = [&](int k0) {
#pragma unroll
        for (int p = 0; p < 2; p++) {
            const int idx = tid + p * 512;
            const int r   = idx >> 3;
            const int g0  = idx & 7;
            const size_t goff = (size_t)g0 * 8 + k0;
            rA[p] = *reinterpret_cast<const uint4*>(A  + (size_t)(m0 + r) * Dc + goff);
            rK[p] = *reinterpret_cast<const uint4*>(Wk + (size_t)(n0 + r) * Dc + goff);
            rV[p] = *reinterpret_cast<const uint4*>(Wv + (size_t)(n0 + r) * Dc + goff);
        }
    };
    auto store_tiles = [&]() {
#pragma unroll
        for (int p = 0; p < 2; p++) {
            const int idx = tid + p * 512;
            const int r   = idx >> 3;
            const int g   = (idx & 7) ^ (r & 7);
            *reinterpret_cast<uint4*>(&As[r * 64 + g * 8])  = rA[p];
            *reinterpret_cast<uint4*>(&Bks[r * 64 + g * 8]) = rK[p];
            *reinterpret_cast<uint4*>(&Bvs[r * 64 + g * 8]) = rV[p];
        }
    };

    load_tiles(0);
    for (int k0 = 0; k0 < Dc; k0 += 64) {
        store_tiles();
        __syncthreads();
        if (k0 + 64 < Dc) load_tiles(k0 + 64);

#pragma unroll
        for (int ks = 0; ks < 4; ks++) {
            uint32_t af[2][4];
#pragma unroll
            for (int mt = 0; mt < 2; mt++) {
                const int r  = wm + mt * 16 + lml * 8 + lr;
                const int lg = 2 * ks + lmh;
                ldsm_x4(af[mt][0], af[mt][1], af[mt][2], af[mt][3],
                        aBase + (uint32_t)(r * 128 + ((lg ^ (r & 7)) << 4)));
            }
            uint32_t bkf[8], bvf[8];
#pragma unroll
            for (int j = 0; j < 2; j++) {
                const int n  = wn + (2 * j + lmh) * 8 + lr;
                const int lg = 2 * ks + lml;
                const uint32_t off = (uint32_t)(n * 128 + ((lg ^ (n & 7)) << 4));
                ldsm_x4(bkf[4 * j], bkf[4 * j + 1], bkf[4 * j + 2], bkf[4 * j + 3], kBase + off);
                ldsm_x4(bvf[4 * j], bvf[4 * j + 1], bvf[4 * j + 2], bvf[4 * j + 3], vBase + off);
            }
#pragma unroll
            for (int nt = 0; nt < 4; nt++) {
                const int bi = 4 * (nt >> 1) + 2 * (nt & 1);
#pragma unroll
                for (int mt = 0; mt < 2; mt++) {
                    mma_f16(accK[mt][nt][0], accK[mt][nt][1], accK[mt][nt][2], accK[mt][nt][3],
                            af[mt][0], af[mt][1], af[mt][2], af[mt][3], bkf[bi], bkf[bi + 1]);
                    mma_f16(accV[mt][nt][0], accV[mt][nt][1], accV[mt][nt][2], accV[mt][nt][3],
                            af[mt][0], af[mt][1], af[mt][2], af[mt][3], bvf[bi], bvf[bi + 1]);
                }
            }
        }
        __syncthreads();
    }

    // epilogue 1: K direct (row-major fp16), accV staged transposed into smem
    constexpr int LDV = 136;   // halves; 272B row stride (17x16B) -> aligned 16B chunks
    __half* VsT = sm;          // [128 dims][LDV] = 34816 B <= 48 KB
#pragma unroll
    for (int mt = 0; mt < 2; mt++) {
#pragma unroll
        for (int nt = 0; nt < 4; nt++) {
            const int rl  = wm + mt * 16 + gr;        // local key row
            const int cl  = wn + nt * 8 + 2 * cc;     // local dim col
            const int row = m0 + rl;
            const int col = n0 + cl;
            const float bk0 = bk[col], bk1 = bk[col + 1];
            const float bv0 = bv[col], bv1 = bv[col + 1];
            __half2* CKp = (__half2*)CK;
            CKp[((size_t)row * Dc + col) >> 1] =
                __floats2half2_rn(accK[mt][nt][0] + bk0, accK[mt][nt][1] + bk1);
            CKp[((size_t)(row + 8) * Dc + col) >> 1] =
                __floats2half2_rn(accK[mt][nt][2] + bk0, accK[mt][nt][3] + bk1);
            VsT[(cl)     * LDV + rl]     = __float2half_rn(accV[mt][nt][0] + bv0);
            VsT[(cl + 1) * LDV + rl]     = __float2half_rn(accV[mt][nt][1] + bv1);
            VsT[(cl)     * LDV + rl + 8] = __float2half_rn(accV[mt][nt][2] + bv0);
            VsT[(cl + 1) * LDV + rl + 8] = __float2half_rn(accV[mt][nt][3] + bv1);
        }
    }
    __syncthreads();

    // epilogue 2: coalesced transposed V write: Vt[(b*16+h)*64+d][key]
    const int bb   = m0 >> 13;           // m0 / TKc
    const int key0 = m0 & (TKc - 1);
#pragma unroll
    for (int p = 0; p < 4; p++) {
        const int idx = tid + p * 512;    // 0..2047
        const int dl  = idx >> 4;         // local dim 0..127
        const int kc  = idx & 15;         // 16B chunk within 128 keys
        const int gd  = n0 + dl;          // global dim
        const int h   = gd >> 6;
        const int d   = gd & 63;
        uint4 v = *reinterpret_cast<const uint4*>(&VsT[dl * LDV + kc * 8]);
        *reinterpret_cast<uint4*>(
            Vt + ((size_t)((bb * NHc + h) * HDc + d)) * TKc + key0 + kc * 8) = v;
    }
}

// ---------------------------------------------------------------------------
// fp16 GEMM for Q / O projections, BM=64 x BN=128 (unchanged).
// ---------------------------------------------------------------------------
__global__ __launch_bounds__(256)
void gemm16b(const float* __restrict__ A, const float* __restrict__ W,
             const float* __restrict__ bias, float* __restrict__ C,
             int M, int N, int K)
{
    __shared__ __half As[64 * 64];
    __shared__ __half Bs[128 * 64];
    uint32_t* As32 = reinterpret_cast<uint32_t*>(As);
    uint32_t* Bs32 = reinterpret_cast<uint32_t*>(Bs);

    const int tid  = threadIdx.x;
    const int warp = tid >> 5;
    const int lane = tid & 31;
    const int gr   = lane >> 2;
    const int cc   = lane & 3;
    const int wm   = (warp >> 2) * 32;
    const int wn   = (warp & 3) * 32;
    const int m0   = blockIdx.y * 64;
    const int n0   = blockIdx.x * 128;

    float acc[2][4][4];
#pragma unroll
    for (int mt = 0; mt < 2; mt++)
#pragma unroll
        for (int nt = 0; nt < 4; nt++)
#pragma unroll
            for (int r = 0; r < 4; r++) acc[mt][nt][r] = 0.f;

    float4 rA[4], rB[8];
    auto load_tiles = [&](int k0) {
#pragma unroll
        for (int p = 0; p < 2; p++) {
            const int idx = tid + p * 256;
            const int r   = idx >> 3;
            const int gk  = k0 + (idx & 7) * 8;
            const float* ap = A + (size_t)(m0 + r) * K + gk;
            rA[p * 2]     = *reinterpret_cast<const float4*>(ap);
            rA[p * 2 + 1] = *reinterpret_cast<const float4*>(ap + 4);
        }
#pragma unroll
        for (int p = 0; p < 4; p++) {
            const int idx = tid + p * 256;
            const int r   = idx >> 3;
            const int gk  = k0 + (idx & 7) * 8;
            const float* wp = W + (size_t)(n0 + r) * K + gk;
            rB[p * 2]     = *reinterpret_cast<const float4*>(wp);
            rB[p * 2 + 1] = *reinterpret_cast<const float4*>(wp + 4);
        }
    };
    auto store_tiles = [&]() {
#pragma unroll
        for (int p = 0; p < 2; p++) {
            const int idx = tid + p * 256;
            const int r   = idx >> 3;
            const int g   = (idx & 7) ^ (r & 7);
            float4 a0 = rA[p * 2], a1 = rA[p * 2 + 1];
            uint4 ua;
            ua.x = pack_h2(a0.x, a0.y); ua.y = pack_h2(a0.z, a0.w);
            ua.z = pack_h2(a1.x, a1.y); ua.w = pack_h2(a1.z, a1.w);
            *reinterpret_cast<uint4*>(&As[r * 64 + g * 8]) = ua;
        }
#pragma unroll
        for (int p = 0; p < 4; p++) {
            const int idx = tid + p * 256;
            const int r   = idx >> 3;
            const int g   = (idx & 7) ^ (r & 7);
            float4 b0 = rB[p * 2], b1 = rB[p * 2 + 1];
            uint4 ub;
            ub.x = pack_h2(b0.x, b0.y); ub.y = pack_h2(b0.z, b0.w);
            ub.z = pack_h2(b1.x, b1.y); ub.w = pack_h2(b1.z, b1.w);
            *reinterpret_cast<uint4*>(&Bs[r * 64 + g * 8]) = ub;
        }
    };

    load_tiles(0);
    for (int k0 = 0; k0 < K; k0 += 64) {
        store_tiles();
        __syncthreads();
        if (k0 + 64 < K) load_tiles(k0 + 64);
#pragma unroll
        for (int ks = 0; ks < 4; ks++) {
            uint32_t af[2][4];
#pragma unroll
            for (int mt = 0; mt < 2; mt++) {
                const int r = wm + mt * 16 + gr;
                af[mt][0] = As32[sw_idx64(r,     2 * ks,     cc)];
                af[mt][1] = As32[sw_idx64(r + 8, 2 * ks,     cc)];
                af[mt][2] = As32[sw_idx64(r,     2 * ks + 1, cc)];
                af[mt][3] = As32[sw_idx64(r + 8, 2 * ks + 1, cc)];
            }
#pragma unroll
            for (int nt = 0; nt < 4; nt++) {
                const int n = wn + nt * 8 + gr;
                uint32_t b0 = Bs32[sw_idx64(n, 2 * ks,     cc)];
                uint32_t b1 = Bs32[sw_idx64(n, 2 * ks + 1, cc)];
#pragma unroll
                for (int mt = 0; mt < 2; mt++)
                    mma_f16(acc[mt][nt][0], acc[mt][nt][1], acc[mt][nt][2], acc[mt][nt][3],
                            af[mt][0], af[mt][1], af[mt][2], af[mt][3], b0, b1);
            }
        }
        __syncthreads();
    }

#pragma unroll
    for (int mt = 0; mt < 2; mt++) {
#pragma unroll
        for (int nt = 0; nt < 4; nt++) {
            const int row = m0 + wm + mt * 16 + gr;
            const int col = n0 + wn + nt * 8 + 2 * cc;
            const float b0v = bias[col], b1v = bias[col + 1];
            *reinterpret_cast<float2*>(C + (size_t)row * N + col) =
                make_float2(acc[mt][nt][0] + b0v, acc[mt][nt][1] + b1v);
            *reinterpret_cast<float2*>(C + (size_t)(row + 8) * N + col) =
                make_float2(acc[mt][nt][2] + b0v, acc[mt][nt][3] + b1v);
        }
    }
}

// ---------------------------------------------------------------------------
// fp16 MMA flash attention, two segments. Fixed m=0 softmax (scores are
// analytically tiny; softmax is shift-invariant). P in registers; B-frags
// via ldmatrix. 256 threads, 128 q-rows/block, TS=128 keys/tile, 32KB smem.
// ---------------------------------------------------------------------------
constexpr int TSa = 128;

__global__ __launch_bounds__(256)
void attn_f16(const float* __restrict__ Qp, const __half* __restrict__ Kh,
              const __half* __restrict__ Vt, float* __restrict__ At,
              const float* __restrict__ p_log_temp, const int* __restrict__ pNA)
{
    __shared__ __half Ks[128 * 64];
    __shared__ __half VtS[64 * 128];

    const int b    = blockIdx.z;
    const int h    = blockIdx.y;
    const int q0   = blockIdx.x * 128;
    const int tid  = threadIdx.x;
    const int warp = tid >> 5;
    const int lane = tid & 31;
    const int gr   = lane >> 2;
    const int cc   = lane & 3;
    const int lr   = lane & 7;
    const int lmh  = lane >> 4;
    const int lml  = (lane >> 3) & 1;
    const int rl   = warp * 16 + gr;
    const int row0 = q0 + rl;

    const uint32_t ksBase  = (uint32_t)__cvta_generic_to_shared(Ks);
    const uint32_t vtsBase = (uint32_t)__cvta_generic_to_shared(VtS);

    const int na = *pNA;
    float temp = __expf(*p_log_temp);
    temp = fminf(fmaxf(temp, 0.1f), 10.0f);
    const float scale = 1.0f / ((float)HDc * temp);

    uint32_t qf[4][4];
    {
        const float* qr0 = Qp + ((size_t)(b * TQc + row0)) * Dc + h * HDc;
        const float* qr1 = qr0 + 8 * (size_t)Dc;
#pragma unroll
        for (int ks = 0; ks < 4; ks++) {
            const int k = ks * 16;
            float2 a  = *reinterpret_cast<const float2*>(qr0 + k + 2 * cc);
            float2 bv = *reinterpret_cast<const float2*>(qr1 + k + 2 * cc);
            float2 c2 = *reinterpret_cast<const float2*>(qr0 + k + 8 + 2 * cc);
            float2 d2 = *reinterpret_cast<const float2*>(qr1 + k + 8 + 2 * cc);
            qf[ks][0] = pack_h2(a.x * scale, a.y * scale);
            qf[ks][1] = pack_h2(bv.x * scale, bv.y * scale);
            qf[ks][2] = pack_h2(c2.x * scale, c2.y * scale);
            qf[ks][3] = pack_h2(d2.x * scale, d2.y * scale);
        }
    }

    float outc[8][4];
#pragma unroll
    for (int nt = 0; nt < 8; nt++)
#pragma unroll
        for (int r = 0; r < 4; r++) outc[nt][r] = 0.f;

    const int lrow = tid >> 3;   // 0..31
    const int seg  = tid & 7;

    for (int segi = 0; segi < 2; segi++) {
        const int s_begin = segi ? na : 0;
        const int s_end   = segi ? TKc : na;
        const int s_cnt   = s_end - s_begin;
        if (s_cnt <= 0) continue;
        const float coef = (segi ? -1.f : 1.f) / sqrtf((float)s_cnt);

        float l0 = 0.f, l1 = 0.f;
        float o[8][4];
#pragma unroll
        for (int nt = 0; nt < 8; nt++)
#pragma unroll
            for (int r = 0; r < 4; r++) o[nt][r] = 0.f;

        const int ntiles = (s_cnt + TSa - 1) / TSa;
        for (int tile = 0; tile < ntiles; tile++) {
            const int kbase = s_begin + tile * TSa;
            const int valid = min(TSa, s_end - kbase);
            const bool partial = (valid < TSa);

            __syncthreads();
#pragma unroll
            for (int p = 0; p < 4; p++) {
                const int r = lrow + p * 32;
                const int g = seg ^ (r & 7);
                uint4 v = make_uint4(0, 0, 0, 0);
                if (r < valid)
                    v = *reinterpret_cast<const uint4*>(
                        Kh + ((size_t)(b * TKc + kbase + r)) * Dc + h * HDc + seg * 8);
                *reinterpret_cast<uint4*>(&Ks[r * 64 + g * 8]) = v;
            }
#pragma unroll
            for (int p = 0; p < 2; p++) {
                const int r = lrow + p * 32;
                const __half* src = Vt + ((size_t)((b * NHc + h) * HDc + r)) * TKc + kbase;
                uint4 v0 = *reinterpret_cast<const uint4*>(src + seg * 8);
                uint4 v1 = *reinterpret_cast<const uint4*>(src + (seg + 8) * 8);
                const int g0 = seg ^ (r & 7);
                *reinterpret_cast<uint4*>(&VtS[r * 128 + g0 * 8]) = v0;
                *reinterpret_cast<uint4*>(&VtS[r * 128 + (g0 + 8) * 8]) = v1;
            }
            __syncthreads();

            // S = Q K^T
            float sacc[16][4];
#pragma unroll
            for (int nt = 0; nt < 16; nt++)
#pragma unroll
                for (int r = 0; r < 4; r++) sacc[nt][r] = 0.f;
#pragma unroll
            for (int ks = 0; ks < 4; ks++) {
#pragma unroll
                for (int j = 0; j < 8; j++) {
                    const int n  = (2 * j + lmh) * 8 + lr;
                    const int lg = 2 * ks + lml;
                    uint32_t f0, f1, f2, f3;
                    ldsm_x4(f0, f1, f2, f3,
                            ksBase + (uint32_t)(n * 128 + ((lg ^ (n & 7)) << 4)));
                    mma_f16(sacc[2*j][0], sacc[2*j][1], sacc[2*j][2], sacc[2*j][3],
                            qf[ks][0], qf[ks][1], qf[ks][2], qf[ks][3], f0, f1);
                    mma_f16(sacc[2*j+1][0], sacc[2*j+1][1], sacc[2*j+1][2], sacc[2*j+1][3],
                            qf[ks][0], qf[ks][1], qf[ks][2], qf[ks][3], f2, f3);
                }
            }

            if (partial) {
#pragma unroll
                for (int nt = 0; nt < 16; nt++) {
                    const int col = nt * 8 + 2 * cc;
                    if (col     >= valid) { sacc[nt][0] = -INFINITY; sacc[nt][2] = -INFINITY; }
                    if (col + 1 >= valid) { sacc[nt][1] = -INFINITY; sacc[nt][3] = -INFINITY; }
                }
            }

            // exp (fixed m=0) -> P packed directly into A fragments
            uint32_t ap[8][4];
#pragma unroll
            for (int nt = 0; nt < 16; nt++) {
                float p0 = __expf(sacc[nt][0]);
                float p1 = __expf(sacc[nt][1]);
                float p2 = __expf(sacc[nt][2]);
                float p3 = __expf(sacc[nt][3]);
                l0 += p0 + p1;
                l1 += p2 + p3;
                const int kt   = nt >> 1;
                const int half = nt & 1;
                ap[kt][half * 2]     = pack_h2(p0, p1);
                ap[kt][half * 2 + 1] = pack_h2(p2, p3);
            }

            // O += P V
#pragma unroll
            for (int kt = 0; kt < 8; kt++) {
#pragma unroll
                for (int j = 0; j < 4; j++) {
                    const int n  = (2 * j + lmh) * 8 + lr;
                    const int lg = 2 * kt + lml;
                    uint32_t f0, f1, f2, f3;
                    ldsm_x4(f0, f1, f2, f3,
                            vtsBase + (uint32_t)(n * 256 + ((lg ^ (n & 7)) << 4)));
                    mma_f16(o[2*j][0], o[2*j][1], o[2*j][2], o[2*j][3],
                            ap[kt][0], ap[kt][1], ap[kt][2], ap[kt][3], f0, f1);
                    mma_f16(o[2*j+1][0], o[2*j+1][1], o[2*j+1][2], o[2*j+1][3],
                            ap[kt][0], ap[kt][1], ap[kt][2], ap[kt][3], f2, f3);
                }
            }
        }

        l0 += __shfl_xor_sync(0xffffffffu, l0, 1);
        l0 += __shfl_xor_sync(0xffffffffu, l0, 2);
        l1 += __shfl_xor_sync(0xffffffffu, l1, 1);
        l1 += __shfl_xor_sync(0xffffffffu, l1, 2);
        const float inv0 = coef / l0;
        const float inv1 = coef / l1;
#pragma unroll
        for (int nt = 0; nt < 8; nt++) {
            outc[nt][0] += o[nt][0] * inv0;
            outc[nt][1] += o[nt][1] * inv0;
            outc[nt][2] += o[nt][2] * inv1;
            outc[nt][3] += o[nt][3] * inv1;
        }
    }

    float* ob = At + ((size_t)(b * TQc + row0)) * Dc + h * HDc;
#pragma unroll
    for (int nt = 0; nt < 8; nt++) {
        const int col = nt * 8 + 2 * cc;
        *reinterpret_cast<float2*>(ob + col) = make_float2(outc[nt][0], outc[nt][1]);
        *reinterpret_cast<float2*>(ob + 8 * (size_t)Dc + col) = make_float2(outc[nt][2], outc[nt][3]);
    }
}

// ---------------------------------------------------------------------------
// kernel_launch: plain kernel launches only, no statics, no attribute calls.
// ---------------------------------------------------------------------------
extern "C" void kernel_launch(void* const* d_in, const int* in_sizes, int n_in,
                              void* d_out, int out_size)
{
    const float* q    = (const float*)d_in[0];
    const float* kv   = (const float*)d_in[1];
    const float* Wq   = (const float*)d_in[2];
    const float* bq   = (const float*)d_in[3];
    const float* Wk   = (const float*)d_in[4];
    const float* bk   = (const float*)d_in[5];
    const float* Wv   = (const float*)d_in[6];
    const float* bv   = (const float*)d_in[7];
    const float* Wo   = (const float*)d_in[8];
    const float* bo   = (const float*)d_in[9];
    const float* abA  = (const float*)d_in[10];
    const float* abI  = (const float*)d_in[11];
    const float* logt = (const float*)d_in[12];
    const int*   pNA  = (const int*)d_in[13];
    float* out = (float*)d_out;

    void *pQp, *pA16, *pWk16, *pWv16, *pKh, *pVt, *pAt;
    cudaGetSymbolAddress(&pQp,   g_Qp);
    cudaGetSymbolAddress(&pA16,  g_A16);
    cudaGetSymbolAddress(&pWk16, g_Wk16);
    cudaGetSymbolAddress(&pWv16, g_Wv16);
    cudaGetSymbolAddress(&pKh,   g_Kh);
    cudaGetSymbolAddress(&pVt,   g_Vt);
    cudaGetSymbolAddress(&pAt,   g_At);

    const dim3 gblk(256);

    // prep: kv + group bias -> fp16; Wk, Wv -> fp16
    prep_kv<<<(Bc * TKc * Dc) / (256 * 8), gblk>>>(kv, abA, abI, pNA, (__half*)pA16);
    prep_w<<<(Dc * Dc) / (256 * 8), gblk>>>(Wk, (__half*)pWk16);
    prep_w<<<(Dc * Dc) / (256 * 8), gblk>>>(Wv, (__half*)pWv16);

    // Q projection -> fp32 (BM=64 for occupancy)
    gemm16b<<<dim3(Dc / 128, (Bc * TQc) / 64), gblk>>>(
        q, Wq, bq, (float*)pQp, Bc * TQc, Dc, Dc);

    // Fused K+V projection; V written transposed (vtrans fused away)
    kvgemm<<<dim3(Dc / 128, (Bc * TKc) / 128), dim3(512)>>>(
        (const __half*)pA16, (const __half*)pWk16, (const __half*)pWv16,
        bk, bv, (__half*)pKh, (__half*)pVt);

    // Two-segment attention (fixed m=0 softmax, P in regs, ldmatrix B-frags)
    attn_f16<<<dim3(TQc / 128, NHc, Bc), gblk>>>(
        (const float*)pQp, (const __half*)pKh, (const __half*)pVt, (float*)pAt,
        logt, pNA);

    // Output projection -> fp32 d_out (BM=64)
    gemm16b<<<dim3(Dc / 128, (Bc * TQc) / 64), gblk>>>(
        (const float*)pAt, Wo, bo, out, Bc * TQc, Dc, Dc);
}

// round 12
// speedup vs baseline: 14.8077x; 1.0612x over previous
#include <cuda_runtime.h>
#include <cuda_fp16.h>
#include <cstdint>
#include <math.h>

// Problem dimensions (fixed)
constexpr int Bc  = 2;
constexpr int TQc = 512;
constexpr int TKc = 8192;
constexpr int Dc  = 1024;
constexpr int NHc = 16;
constexpr int HDc = 64;

// Scratch (allocation-free)
__device__ float  g_Qp[(size_t)Bc * TQc * Dc];            // Q projected, fp32
__device__ __half g_A16[(size_t)Bc * TKc * Dc];           // kv + group bias, fp16
__device__ __half g_Wk16[(size_t)Dc * Dc];
__device__ __half g_Wv16[(size_t)Dc * Dc];
__device__ __half g_Kh[(size_t)Bc * TKc * Dc];            // K projected, fp16
__device__ __half g_Vt[(size_t)Bc * NHc * HDc * TKc];     // V transposed [b,h,dim][key]
__device__ float  g_At[(size_t)Bc * TQc * Dc];            // attention out, fp32

// ---------------------------------------------------------------------------
// helpers
// ---------------------------------------------------------------------------
__device__ __forceinline__ uint32_t pack_h2(float lo, float hi) {
    __half2 h = __floats2half2_rn(lo, hi);
    return *reinterpret_cast<uint32_t*>(&h);
}

__device__ __forceinline__ void mma_f16(float& c0, float& c1, float& c2, float& c3,
                                        uint32_t a0, uint32_t a1, uint32_t a2, uint32_t a3,
                                        uint32_t b0, uint32_t b1)
{
    asm volatile(
        "mma.sync.aligned.m16n8k16.row.col.f32.f16.f16.f32 "
        "{%0,%1,%2,%3}, {%4,%5,%6,%7}, {%8,%9}, {%0,%1,%2,%3};"
        : "+f"(c0), "+f"(c1), "+f"(c2), "+f"(c3)
        : "r"(a0), "r"(a1), "r"(a2), "r"(a3), "r"(b0), "r"(b1));
}

__device__ __forceinline__ void ldsm_x4(uint32_t& r0, uint32_t& r1,
                                        uint32_t& r2, uint32_t& r3, uint32_t addr)
{
    asm volatile("ldmatrix.sync.aligned.m8n8.x4.shared.b16 {%0,%1,%2,%3}, [%4];"
                 : "=r"(r0), "=r"(r1), "=r"(r2), "=r"(r3) : "r"(addr));
}

// cp.async with src-size (zero-fills dst bytes beyond srcsz)
__device__ __forceinline__ void cp16z(uint32_t dst, const void* src, int srcsz) {
    asm volatile("cp.async.cg.shared.global [%0], [%1], 16, %2;"
                 :: "r"(dst), "l"(src), "r"(srcsz));
}
__device__ __forceinline__ void cp_commit() { asm volatile("cp.async.commit_group;"); }
template <int N>
__device__ __forceinline__ void cp_wait() { asm volatile("cp.async.wait_group %0;" :: "n"(N)); }

// swizzled u32 index, fp16 tile, row stride 64 halves (32 u32)
__device__ __forceinline__ int sw_idx64(int row, int gbase, int cc) {
    return row * 32 + ((gbase ^ (row & 7)) << 2) + cc;
}

// ---------------------------------------------------------------------------
// prep: kv(fp32) + group bias -> fp16 ; generic fp32 -> fp16 for weights
// ---------------------------------------------------------------------------
__global__ __launch_bounds__(256)
void prep_kv(const float* __restrict__ kv, const float* __restrict__ abA,
             const float* __restrict__ abI, const int* __restrict__ pNA,
             __half* __restrict__ dst)
{
    const int na = *pNA;
    const size_t i8 = (size_t)(blockIdx.x * 256 + threadIdx.x) * 8;  // 8 floats
    const int row = (int)(i8 >> 10);            // /Dc
    const int col = (int)(i8 & 1023);
    const float* ab = ((row % TKc) < na) ? abA : abI;
    float4 v0 = *reinterpret_cast<const float4*>(kv + i8);
    float4 v1 = *reinterpret_cast<const float4*>(kv + i8 + 4);
    float4 b0 = *reinterpret_cast<const float4*>(ab + col);
    float4 b1 = *reinterpret_cast<const float4*>(ab + col + 4);
    uint4 o;
    o.x = pack_h2(v0.x + b0.x, v0.y + b0.y);
    o.y = pack_h2(v0.z + b0.z, v0.w + b0.w);
    o.z = pack_h2(v1.x + b1.x, v1.y + b1.y);
    o.w = pack_h2(v1.z + b1.z, v1.w + b1.w);
    *reinterpret_cast<uint4*>(dst + i8) = o;
}

__global__ __launch_bounds__(256)
void prep_w(const float* __restrict__ src, __half* __restrict__ dst)
{
    const size_t i8 = (size_t)(blockIdx.x * 256 + threadIdx.x) * 8;
    float4 v0 = *reinterpret_cast<const float4*>(src + i8);
    float4 v1 = *reinterpret_cast<const float4*>(src + i8 + 4);
    uint4 o;
    o.x = pack_h2(v0.x, v0.y); o.y = pack_h2(v0.z, v0.w);
    o.z = pack_h2(v1.x, v1.y); o.w = pack_h2(v1.z, v1.w);
    *reinterpret_cast<uint4*>(dst + i8) = o;
}

// ---------------------------------------------------------------------------
// Fused K+V projection GEMM; V written TRANSPOSED into g_Vt (unchanged R11).
// ---------------------------------------------------------------------------
__global__ __launch_bounds__(512)
void kvgemm(const __half* __restrict__ A, const __half* __restrict__ Wk,
            const __half* __restrict__ Wv, const float* __restrict__ bk,
            const float* __restrict__ bv, __half* __restrict__ CK,
            __half* __restrict__ Vt)
{
    __shared__ __half sm[3 * 128 * 64];   // 48 KB
    __half* As  = sm;
    __half* Bks = sm + 128 * 64;
    __half* Bvs = sm + 2 * 128 * 64;

    const int tid  = threadIdx.x;
    const int warp = tid >> 5;
    const int lane = tid & 31;
    const int gr   = lane >> 2;
    const int cc   = lane & 3;
    const int lr   = lane & 7;
    const int lmh  = lane >> 4;
    const int lml  = (lane >> 3) & 1;
    const int wm   = (warp >> 2) * 32;
    const int wn   = (warp & 3) * 32;
    const int m0   = blockIdx.y * 128;
    const int n0   = blockIdx.x * 128;

    const uint32_t aBase = (uint32_t)__cvta_generic_to_shared(As);
    const uint32_t kBase = (uint32_t)__cvta_generic_to_shared(Bks);
    const uint32_t vBase = (uint32_t)__cvta_generic_to_shared(Bvs);

    float accK[2][4][4], accV[2][4][4];
#pragma unroll
    for (int mt = 0; mt < 2; mt++)
#pragma unroll
        for (int nt = 0; nt < 4; nt++)
#pragma unroll
            for (int r = 0; r < 4; r++) { accK[mt][nt][r] = 0.f; accV[mt][nt][r] = 0.f; }

    uint4 rA[2], rK[2], rV[2];
    auto load_tiles = [&](int k0) {
#pragma unroll
        for (int p = 0; p < 2; p++) {
            const int idx = tid + p * 512;
            const int r   = idx >> 3;
            const int g0  = idx & 7;
            const size_t goff = (size_t)g0 * 8 + k0;
            rA[p] = *reinterpret_cast<const uint4*>(A  + (size_t)(m0 + r) * Dc + goff);
            rK[p] = *reinterpret_cast<const uint4*>(Wk + (size_t)(n0 + r) * Dc + goff);
            rV[p] = *reinterpret_cast<const uint4*>(Wv + (size_t)(n0 + r) * Dc + goff);
        }
    };
    auto store_tiles = [&]() {
#pragma unroll
        for (int p = 0; p < 2; p++) {
            const int idx = tid + p * 512;
            const int r   = idx >> 3;
            const int g   = (idx & 7) ^ (r & 7);
            *reinterpret_cast<uint4*>(&As[r * 64 + g * 8])  = rA[p];
            *reinterpret_cast<uint4*>(&Bks[r * 64 + g * 8]) = rK[p];
            *reinterpret_cast<uint4*>(&Bvs[r * 64 + g * 8]) = rV[p];
        }
    };

    load_tiles(0);
    for (int k0 = 0; k0 < Dc; k0 += 64) {
        store_tiles();
        __syncthreads();
        if (k0 + 64 < Dc) load_tiles(k0 + 64);

#pragma unroll
        for (int ks = 0; ks < 4; ks++) {
            uint32_t af[2][4];
#pragma unroll
            for (int mt = 0; mt < 2; mt++) {
                const int r  = wm + mt * 16 + lml * 8 + lr;
                const int lg = 2 * ks + lmh;
                ldsm_x4(af[mt][0], af[mt][1], af[mt][2], af[mt][3],
                        aBase + (uint32_t)(r * 128 + ((lg ^ (r & 7)) << 4)));
            }
            uint32_t bkf[8], bvf[8];
#pragma unroll
            for (int j = 0; j < 2; j++) {
                const int n  = wn + (2 * j + lmh) * 8 + lr;
                const int lg = 2 * ks + lml;
                const uint32_t off = (uint32_t)(n * 128 + ((lg ^ (n & 7)) << 4));
                ldsm_x4(bkf[4 * j], bkf[4 * j + 1], bkf[4 * j + 2], bkf[4 * j + 3], kBase + off);
                ldsm_x4(bvf[4 * j], bvf[4 * j + 1], bvf[4 * j + 2], bvf[4 * j + 3], vBase + off);
            }
#pragma unroll
            for (int nt = 0; nt < 4; nt++) {
                const int bi = 4 * (nt >> 1) + 2 * (nt & 1);
#pragma unroll
                for (int mt = 0; mt < 2; mt++) {
                    mma_f16(accK[mt][nt][0], accK[mt][nt][1], accK[mt][nt][2], accK[mt][nt][3],
                            af[mt][0], af[mt][1], af[mt][2], af[mt][3], bkf[bi], bkf[bi + 1]);
                    mma_f16(accV[mt][nt][0], accV[mt][nt][1], accV[mt][nt][2], accV[mt][nt][3],
                            af[mt][0], af[mt][1], af[mt][2], af[mt][3], bvf[bi], bvf[bi + 1]);
                }
            }
        }
        __syncthreads();
    }

    // epilogue 1: K direct (row-major fp16), accV staged transposed into smem
    constexpr int LDV = 136;
    __half* VsT = sm;          // [128 dims][LDV] = 34816 B <= 48 KB
#pragma unroll
    for (int mt = 0; mt < 2; mt++) {
#pragma unroll
        for (int nt = 0; nt < 4; nt++) {
            const int rl  = wm + mt * 16 + gr;
            const int cl  = wn + nt * 8 + 2 * cc;
            const int row = m0 + rl;
            const int col = n0 + cl;
            const float bk0 = bk[col], bk1 = bk[col + 1];
            const float bv0 = bv[col], bv1 = bv[col + 1];
            __half2* CKp = (__half2*)CK;
            CKp[((size_t)row * Dc + col) >> 1] =
                __floats2half2_rn(accK[mt][nt][0] + bk0, accK[mt][nt][1] + bk1);
            CKp[((size_t)(row + 8) * Dc + col) >> 1] =
                __floats2half2_rn(accK[mt][nt][2] + bk0, accK[mt][nt][3] + bk1);
            VsT[(cl)     * LDV + rl]     = __float2half_rn(accV[mt][nt][0] + bv0);
            VsT[(cl + 1) * LDV + rl]     = __float2half_rn(accV[mt][nt][1] + bv1);
            VsT[(cl)     * LDV + rl + 8] = __float2half_rn(accV[mt][nt][2] + bv0);
            VsT[(cl + 1) * LDV + rl + 8] = __float2half_rn(accV[mt][nt][3] + bv1);
        }
    }
    __syncthreads();

    // epilogue 2: coalesced transposed V write: Vt[(b*16+h)*64+d][key]
    const int bb   = m0 >> 13;
    const int key0 = m0 & (TKc - 1);
#pragma unroll
    for (int p = 0; p < 4; p++) {
        const int idx = tid + p * 512;
        const int dl  = idx >> 4;
        const int kc  = idx & 15;
        const int gd  = n0 + dl;
        const int h   = gd >> 6;
        const int d   = gd & 63;
        uint4 v = *reinterpret_cast<const uint4*>(&VsT[dl * LDV + kc * 8]);
        *reinterpret_cast<uint4*>(
            Vt + ((size_t)((bb * NHc + h) * HDc + d)) * TKc + key0 + kc * 8) = v;
    }
}

// ---------------------------------------------------------------------------
// fp16 GEMM for Q / O projections, BM=64 x BN=128 (unchanged).
// ---------------------------------------------------------------------------
__global__ __launch_bounds__(256)
void gemm16b(const float* __restrict__ A, const float* __restrict__ W,
             const float* __restrict__ bias, float* __restrict__ C,
             int M, int N, int K)
{
    __shared__ __half As[64 * 64];
    __shared__ __half Bs[128 * 64];
    uint32_t* As32 = reinterpret_cast<uint32_t*>(As);
    uint32_t* Bs32 = reinterpret_cast<uint32_t*>(Bs);

    const int tid  = threadIdx.x;
    const int warp = tid >> 5;
    const int lane = tid & 31;
    const int gr   = lane >> 2;
    const int cc   = lane & 3;
    const int wm   = (warp >> 2) * 32;
    const int wn   = (warp & 3) * 32;
    const int m0   = blockIdx.y * 64;
    const int n0   = blockIdx.x * 128;

    float acc[2][4][4];
#pragma unroll
    for (int mt = 0; mt < 2; mt++)
#pragma unroll
        for (int nt = 0; nt < 4; nt++)
#pragma unroll
            for (int r = 0; r < 4; r++) acc[mt][nt][r] = 0.f;

    float4 rA[4], rB[8];
    auto load_tiles = [&](int k0) {
#pragma unroll
        for (int p = 0; p < 2; p++) {
            const int idx = tid + p * 256;
            const int r   = idx >> 3;
            const int gk  = k0 + (idx & 7) * 8;
            const float* ap = A + (size_t)(m0 + r) * K + gk;
            rA[p * 2]     = *reinterpret_cast<const float4*>(ap);
            rA[p * 2 + 1] = *reinterpret_cast<const float4*>(ap + 4);
        }
#pragma unroll
        for (int p = 0; p < 4; p++) {
            const int idx = tid + p * 256;
            const int r   = idx >> 3;
            const int gk  = k0 + (idx & 7) * 8;
            const float* wp = W + (size_t)(n0 + r) * K + gk;
            rB[p * 2]     = *reinterpret_cast<const float4*>(wp);
            rB[p * 2 + 1] = *reinterpret_cast<const float4*>(wp + 4);
        }
    };
    auto store_tiles = [&]() {
#pragma unroll
        for (int p = 0; p < 2; p++) {
            const int idx = tid + p * 256;
            const int r   = idx >> 3;
            const int g   = (idx & 7) ^ (r & 7);
            float4 a0 = rA[p * 2], a1 = rA[p * 2 + 1];
            uint4 ua;
            ua.x = pack_h2(a0.x, a0.y); ua.y = pack_h2(a0.z, a0.w);
            ua.z = pack_h2(a1.x, a1.y); ua.w = pack_h2(a1.z, a1.w);
            *reinterpret_cast<uint4*>(&As[r * 64 + g * 8]) = ua;
        }
#pragma unroll
        for (int p = 0; p < 4; p++) {
            const int idx = tid + p * 256;
            const int r   = idx >> 3;
            const int g   = (idx & 7) ^ (r & 7);
            float4 b0 = rB[p * 2], b1 = rB[p * 2 + 1];
            uint4 ub;
            ub.x = pack_h2(b0.x, b0.y); ub.y = pack_h2(b0.z, b0.w);
            ub.z = pack_h2(b1.x, b1.y); ub.w = pack_h2(b1.z, b1.w);
            *reinterpret_cast<uint4*>(&Bs[r * 64 + g * 8]) = ub;
        }
    };

    load_tiles(0);
    for (int k0 = 0; k0 < K; k0 += 64) {
        store_tiles();
        __syncthreads();
        if (k0 + 64 < K) load_tiles(k0 + 64);
#pragma unroll
        for (int ks = 0; ks < 4; ks++) {
            uint32_t af[2][4];
#pragma unroll
            for (int mt = 0; mt < 2; mt++) {
                const int r = wm + mt * 16 + gr;
                af[mt][0] = As32[sw_idx64(r,     2 * ks,     cc)];
                af[mt][1] = As32[sw_idx64(r + 8, 2 * ks,     cc)];
                af[mt][2] = As32[sw_idx64(r,     2 * ks + 1, cc)];
                af[mt][3] = As32[sw_idx64(r + 8, 2 * ks + 1, cc)];
            }
#pragma unroll
            for (int nt = 0; nt < 4; nt++) {
                const int n = wn + nt * 8 + gr;
                uint32_t b0 = Bs32[sw_idx64(n, 2 * ks,     cc)];
                uint32_t b1 = Bs32[sw_idx64(n, 2 * ks + 1, cc)];
#pragma unroll
                for (int mt = 0; mt < 2; mt++)
                    mma_f16(acc[mt][nt][0], acc[mt][nt][1], acc[mt][nt][2], acc[mt][nt][3],
                            af[mt][0], af[mt][1], af[mt][2], af[mt][3], b0, b1);
            }
        }
        __syncthreads();
    }

#pragma unroll
    for (int mt = 0; mt < 2; mt++) {
#pragma unroll
        for (int nt = 0; nt < 4; nt++) {
            const int row = m0 + wm + mt * 16 + gr;
            const int col = n0 + wn + nt * 8 + 2 * cc;
            const float b0v = bias[col], b1v = bias[col + 1];
            *reinterpret_cast<float2*>(C + (size_t)row * N + col) =
                make_float2(acc[mt][nt][0] + b0v, acc[mt][nt][1] + b1v);
            *reinterpret_cast<float2*>(C + (size_t)(row + 8) * N + col) =
                make_float2(acc[mt][nt][2] + b0v, acc[mt][nt][3] + b1v);
        }
    }
}

// ---------------------------------------------------------------------------
// fp16 MMA flash attention, two segments. cp.async double-buffered TS=64
// tiles (load latency hidden behind compute). Fixed m=0 softmax, P in regs,
// ldmatrix B-frags. 256 threads, 128 q-rows/block. Smem 2x16KB = 32 KB.
// ---------------------------------------------------------------------------
constexpr int TSa = 64;

__global__ __launch_bounds__(256)
void attn_f16(const float* __restrict__ Qp, const __half* __restrict__ Kh,
              const __half* __restrict__ Vt, float* __restrict__ At,
              const float* __restrict__ p_log_temp, const int* __restrict__ pNA)
{
    __shared__ __half Ks[2][64 * 64];    // [stage][key row][dim]
    __shared__ __half VtS[2][64 * 64];   // [stage][dim row][key]

    const int b    = blockIdx.z;
    const int h    = blockIdx.y;
    const int q0   = blockIdx.x * 128;
    const int tid  = threadIdx.x;
    const int warp = tid >> 5;
    const int lane = tid & 31;
    const int gr   = lane >> 2;
    const int cc   = lane & 3;
    const int lr   = lane & 7;
    const int lmh  = lane >> 4;
    const int lml  = (lane >> 3) & 1;
    const int rl   = warp * 16 + gr;
    const int row0 = q0 + rl;

    const uint32_t ksBase  = (uint32_t)__cvta_generic_to_shared(&Ks[0][0]);
    const uint32_t vtsBase = (uint32_t)__cvta_generic_to_shared(&VtS[0][0]);

    const int na = *pNA;
    float temp = __expf(*p_log_temp);
    temp = fminf(fmaxf(temp, 0.1f), 10.0f);
    const float scale = 1.0f / ((float)HDc * temp);

    // Q fragments (fp16, whole kernel)
    uint32_t qf[4][4];
    {
        const float* qr0 = Qp + ((size_t)(b * TQc + row0)) * Dc + h * HDc;
        const float* qr1 = qr0 + 8 * (size_t)Dc;
#pragma unroll
        for (int ks = 0; ks < 4; ks++) {
            const int k = ks * 16;
            float2 a  = *reinterpret_cast<const float2*>(qr0 + k + 2 * cc);
            float2 bv = *reinterpret_cast<const float2*>(qr1 + k + 2 * cc);
            float2 c2 = *reinterpret_cast<const float2*>(qr0 + k + 8 + 2 * cc);
            float2 d2 = *reinterpret_cast<const float2*>(qr1 + k + 8 + 2 * cc);
            qf[ks][0] = pack_h2(a.x * scale, a.y * scale);
            qf[ks][1] = pack_h2(bv.x * scale, bv.y * scale);
            qf[ks][2] = pack_h2(c2.x * scale, c2.y * scale);
            qf[ks][3] = pack_h2(d2.x * scale, d2.y * scale);
        }
    }

    float outc[8][4];
#pragma unroll
    for (int nt = 0; nt < 8; nt++)
#pragma unroll
        for (int r = 0; r < 4; r++) outc[nt][r] = 0.f;

    const int lrow = tid >> 3;   // 0..31
    const int seg  = tid & 7;

    // issue one TS=64 tile into stage st (K rows + Vt rows, zero-filled tails)
    auto issue_tile = [&](int kbase, int valid, int st) {
        const uint32_t ksSt = ksBase  + (uint32_t)st * 8192;
        const uint32_t vtSt = vtsBase + (uint32_t)st * 8192;
#pragma unroll
        for (int p = 0; p < 2; p++) {
            const int r = lrow + p * 32;                 // key row 0..63
            const int g = seg ^ (r & 7);
            const int srcsz = (r < valid) ? 16 : 0;
            const int gkey  = kbase + ((r < valid) ? r : 0);
            cp16z(ksSt + (uint32_t)(r * 128 + g * 16),
                  Kh + ((size_t)(b * TKc + gkey)) * Dc + h * HDc + seg * 8, srcsz);
        }
#pragma unroll
        for (int p = 0; p < 2; p++) {
            const int r = lrow + p * 32;                 // dim row 0..63
            const int g = seg ^ (r & 7);
            int srcsz = (valid - seg * 8) * 2;
            srcsz = srcsz < 0 ? 0 : (srcsz > 16 ? 16 : srcsz);
            cp16z(vtSt + (uint32_t)(r * 128 + g * 16),
                  Vt + ((size_t)((b * NHc + h) * HDc + r)) * TKc + kbase + seg * 8, srcsz);
        }
        cp_commit();
    };

    for (int segi = 0; segi < 2; segi++) {
        const int s_begin = segi ? na : 0;
        const int s_end   = segi ? TKc : na;
        const int s_cnt   = s_end - s_begin;
        if (s_cnt <= 0) continue;
        const float coef = (segi ? -1.f : 1.f) / sqrtf((float)s_cnt);

        float l0 = 0.f, l1 = 0.f;
        float o[8][4];
#pragma unroll
        for (int nt = 0; nt < 8; nt++)
#pragma unroll
            for (int r = 0; r < 4; r++) o[nt][r] = 0.f;

        const int ntiles = (s_cnt + TSa - 1) / TSa;
        issue_tile(s_begin, min(TSa, s_cnt), 0);

        for (int tile = 0; tile < ntiles; tile++) {
            const int kbase = s_begin + tile * TSa;
            const int valid = min(TSa, s_end - kbase);
            const bool partial = (valid < TSa);
            const int st = tile & 1;

            if (tile + 1 < ntiles) {
                const int kb2 = kbase + TSa;
                issue_tile(kb2, min(TSa, s_end - kb2), (tile + 1) & 1);
                cp_wait<1>();
            } else {
                cp_wait<0>();
            }
            __syncthreads();

            const uint32_t ksSt = ksBase  + (uint32_t)st * 8192;
            const uint32_t vtSt = vtsBase + (uint32_t)st * 8192;

            // S = Q K^T : 8 n-tiles x 4 k-steps
            float sacc[8][4];
#pragma unroll
            for (int nt = 0; nt < 8; nt++)
#pragma unroll
                for (int r = 0; r < 4; r++) sacc[nt][r] = 0.f;
#pragma unroll
            for (int ks = 0; ks < 4; ks++) {
#pragma unroll
                for (int j = 0; j < 4; j++) {
                    const int n  = (2 * j + lmh) * 8 + lr;
                    const int lg = 2 * ks + lml;
                    uint32_t f0, f1, f2, f3;
                    ldsm_x4(f0, f1, f2, f3,
                            ksSt + (uint32_t)(n * 128 + ((lg ^ (n & 7)) << 4)));
                    mma_f16(sacc[2*j][0], sacc[2*j][1], sacc[2*j][2], sacc[2*j][3],
                            qf[ks][0], qf[ks][1], qf[ks][2], qf[ks][3], f0, f1);
                    mma_f16(sacc[2*j+1][0], sacc[2*j+1][1], sacc[2*j+1][2], sacc[2*j+1][3],
                            qf[ks][0], qf[ks][1], qf[ks][2], qf[ks][3], f2, f3);
                }
            }

            if (partial) {
#pragma unroll
                for (int nt = 0; nt < 8; nt++) {
                    const int col = nt * 8 + 2 * cc;
                    if (col     >= valid) { sacc[nt][0] = -INFINITY; sacc[nt][2] = -INFINITY; }
                    if (col + 1 >= valid) { sacc[nt][1] = -INFINITY; sacc[nt][3] = -INFINITY; }
                }
            }

            // exp (fixed m=0) -> P packed directly into A fragments
            uint32_t ap[4][4];
#pragma unroll
            for (int nt = 0; nt < 8; nt++) {
                float p0 = __expf(sacc[nt][0]);
                float p1 = __expf(sacc[nt][1]);
                float p2 = __expf(sacc[nt][2]);
                float p3 = __expf(sacc[nt][3]);
                l0 += p0 + p1;
                l1 += p2 + p3;
                const int kt   = nt >> 1;
                const int half = nt & 1;
                ap[kt][half * 2]     = pack_h2(p0, p1);
                ap[kt][half * 2 + 1] = pack_h2(p2, p3);
            }

            // O += P V : 4 k-tiles x 8 dim-tiles
#pragma unroll
            for (int kt = 0; kt < 4; kt++) {
#pragma unroll
                for (int j = 0; j < 4; j++) {
                    const int n  = (2 * j + lmh) * 8 + lr;
                    const int lg = 2 * kt + lml;
                    uint32_t f0, f1, f2, f3;
                    ldsm_x4(f0, f1, f2, f3,
                            vtSt + (uint32_t)(n * 128 + ((lg ^ (n & 7)) << 4)));
                    mma_f16(o[2*j][0], o[2*j][1], o[2*j][2], o[2*j][3],
                            ap[kt][0], ap[kt][1], ap[kt][2], ap[kt][3], f0, f1);
                    mma_f16(o[2*j+1][0], o[2*j+1][1], o[2*j+1][2], o[2*j+1][3],
                            ap[kt][0], ap[kt][1], ap[kt][2], ap[kt][3], f2, f3);
                }
            }
            __syncthreads();
        }

        l0 += __shfl_xor_sync(0xffffffffu, l0, 1);
        l0 += __shfl_xor_sync(0xffffffffu, l0, 2);
        l1 += __shfl_xor_sync(0xffffffffu, l1, 1);
        l1 += __shfl_xor_sync(0xffffffffu, l1, 2);
        const float inv0 = coef / l0;
        const float inv1 = coef / l1;
#pragma unroll
        for (int nt = 0; nt < 8; nt++) {
            outc[nt][0] += o[nt][0] * inv0;
            outc[nt][1] += o[nt][1] * inv0;
            outc[nt][2] += o[nt][2] * inv1;
            outc[nt][3] += o[nt][3] * inv1;
        }
    }

    float* ob = At + ((size_t)(b * TQc + row0)) * Dc + h * HDc;
#pragma unroll
    for (int nt = 0; nt < 8; nt++) {
        const int col = nt * 8 + 2 * cc;
        *reinterpret_cast<float2*>(ob + col) = make_float2(outc[nt][0], outc[nt][1]);
        *reinterpret_cast<float2*>(ob + 8 * (size_t)Dc + col) = make_float2(outc[nt][2], outc[nt][3]);
    }
}

// ---------------------------------------------------------------------------
// kernel_launch: plain kernel launches only, no statics, no attribute calls.
// ---------------------------------------------------------------------------
extern "C" void kernel_launch(void* const* d_in, const int* in_sizes, int n_in,
                              void* d_out, int out_size)
{
    const float* q    = (const float*)d_in[0];
    const float* kv   = (const float*)d_in[1];
    const float* Wq   = (const float*)d_in[2];
    const float* bq   = (const float*)d_in[3];
    const float* Wk   = (const float*)d_in[4];
    const float* bk   = (const float*)d_in[5];
    const float* Wv   = (const float*)d_in[6];
    const float* bv   = (const float*)d_in[7];
    const float* Wo   = (const float*)d_in[8];
    const float* bo   = (const float*)d_in[9];
    const float* abA  = (const float*)d_in[10];
    const float* abI  = (const float*)d_in[11];
    const float* logt = (const float*)d_in[12];
    const int*   pNA  = (const int*)d_in[13];
    float* out = (float*)d_out;

    void *pQp, *pA16, *pWk16, *pWv16, *pKh, *pVt, *pAt;
    cudaGetSymbolAddress(&pQp,   g_Qp);
    cudaGetSymbolAddress(&pA16,  g_A16);
    cudaGetSymbolAddress(&pWk16, g_Wk16);
    cudaGetSymbolAddress(&pWv16, g_Wv16);
    cudaGetSymbolAddress(&pKh,   g_Kh);
    cudaGetSymbolAddress(&pVt,   g_Vt);
    cudaGetSymbolAddress(&pAt,   g_At);

    const dim3 gblk(256);

    // prep: kv + group bias -> fp16; Wk, Wv -> fp16
    prep_kv<<<(Bc * TKc * Dc) / (256 * 8), gblk>>>(kv, abA, abI, pNA, (__half*)pA16);
    prep_w<<<(Dc * Dc) / (256 * 8), gblk>>>(Wk, (__half*)pWk16);
    prep_w<<<(Dc * Dc) / (256 * 8), gblk>>>(Wv, (__half*)pWv16);

    // Q projection -> fp32 (BM=64 for occupancy)
    gemm16b<<<dim3(Dc / 128, (Bc * TQc) / 64), gblk>>>(
        q, Wq, bq, (float*)pQp, Bc * TQc, Dc, Dc);

    // Fused K+V projection; V written transposed
    kvgemm<<<dim3(Dc / 128, (Bc * TKc) / 128), dim3(512)>>>(
        (const __half*)pA16, (const __half*)pWk16, (const __half*)pWv16,
        bk, bv, (__half*)pKh, (__half*)pVt);

    // Two-segment attention (cp.async double-buffered TS=64 tiles)
    attn_f16<<<dim3(TQc / 128, NHc, Bc), gblk>>>(
        (const float*)pQp, (const __half*)pKh, (const __half*)pVt, (float*)pAt,
        logt, pNA);

    // Output projection -> fp32 d_out (BM=64)
    gemm16b<<<dim3(Dc / 128, (Bc * TQc) / 64), gblk>>>(
        (const float*)pAt, Wo, bo, out, Bc * TQc, Dc, Dc);
}

// round 15
// speedup vs baseline: 16.0266x; 1.0823x over previous
#include <cuda_runtime.h>
#include <cuda_fp16.h>
#include <cstdint>
#include <math.h>

// Problem dimensions (fixed)
constexpr int Bc  = 2;
constexpr int TQc = 512;
constexpr int TKc = 8192;
constexpr int Dc  = 1024;
constexpr int NHc = 16;
constexpr int HDc = 64;

// Scratch (allocation-free)
__device__ float  g_Qp[(size_t)Bc * TQc * Dc];            // Q projected, fp32
__device__ __half g_A16[(size_t)Bc * TKc * Dc];           // kv + group bias, fp16
__device__ __half g_Wk16[(size_t)Dc * Dc];
__device__ __half g_Wv16[(size_t)Dc * Dc];
__device__ __half g_Kh[(size_t)Bc * TKc * Dc];            // K projected, fp16
__device__ __half g_Vt[(size_t)Bc * NHc * HDc * TKc];     // V transposed [b,h,dim][key]
__device__ float  g_At[(size_t)Bc * TQc * Dc];            // attention out, fp32

// ---------------------------------------------------------------------------
// helpers
// ---------------------------------------------------------------------------
__device__ __forceinline__ uint32_t pack_h2(float lo, float hi) {
    __half2 h = __floats2half2_rn(lo, hi);
    return *reinterpret_cast<uint32_t*>(&h);
}

__device__ __forceinline__ void mma_f16(float& c0, float& c1, float& c2, float& c3,
                                        uint32_t a0, uint32_t a1, uint32_t a2, uint32_t a3,
                                        uint32_t b0, uint32_t b1)
{
    asm volatile(
        "mma.sync.aligned.m16n8k16.row.col.f32.f16.f16.f32 "
        "{%0,%1,%2,%3}, {%4,%5,%6,%7}, {%8,%9}, {%0,%1,%2,%3};"
        : "+f"(c0), "+f"(c1), "+f"(c2), "+f"(c3)
        : "r"(a0), "r"(a1), "r"(a2), "r"(a3), "r"(b0), "r"(b1));
}

__device__ __forceinline__ void ldsm_x4(uint32_t& r0, uint32_t& r1,
                                        uint32_t& r2, uint32_t& r3, uint32_t addr)
{
    asm volatile("ldmatrix.sync.aligned.m8n8.x4.shared.b16 {%0,%1,%2,%3}, [%4];"
                 : "=r"(r0), "=r"(r1), "=r"(r2), "=r"(r3) : "r"(addr));
}

__device__ __forceinline__ void cp16(uint32_t dst, const void* src) {
    asm volatile("cp.async.cg.shared.global [%0], [%1], 16;" :: "r"(dst), "l"(src));
}
__device__ __forceinline__ void cp16z(uint32_t dst, const void* src, int srcsz) {
    asm volatile("cp.async.cg.shared.global [%0], [%1], 16, %2;"
                 :: "r"(dst), "l"(src), "r"(srcsz));
}
__device__ __forceinline__ void cp_commit() { asm volatile("cp.async.commit_group;"); }
template <int N>
__device__ __forceinline__ void cp_wait() { asm volatile("cp.async.wait_group %0;" :: "n"(N)); }

// swizzled u32 index, fp16 tile, row stride 64 halves (32 u32)
__device__ __forceinline__ int sw_idx64(int row, int gbase, int cc) {
    return row * 32 + ((gbase ^ (row & 7)) << 2) + cc;
}

// ---------------------------------------------------------------------------
// prep: kv(fp32) + group bias -> fp16 ; generic fp32 -> fp16 for weights
// ---------------------------------------------------------------------------
__global__ __launch_bounds__(256)
void prep_kv(const float* __restrict__ kv, const float* __restrict__ abA,
             const float* __restrict__ abI, const int* __restrict__ pNA,
             __half* __restrict__ dst)
{
    const int na = *pNA;
    const size_t i8 = (size_t)(blockIdx.x * 256 + threadIdx.x) * 8;
    const int row = (int)(i8 >> 10);
    const int col = (int)(i8 & 1023);
    const float* ab = ((row % TKc) < na) ? abA : abI;
    float4 v0 = *reinterpret_cast<const float4*>(kv + i8);
    float4 v1 = *reinterpret_cast<const float4*>(kv + i8 + 4);
    float4 b0 = *reinterpret_cast<const float4*>(ab + col);
    float4 b1 = *reinterpret_cast<const float4*>(ab + col + 4);
    uint4 o;
    o.x = pack_h2(v0.x + b0.x, v0.y + b0.y);
    o.y = pack_h2(v0.z + b0.z, v0.w + b0.w);
    o.z = pack_h2(v1.x + b1.x, v1.y + b1.y);
    o.w = pack_h2(v1.z + b1.z, v1.w + b1.w);
    *reinterpret_cast<uint4*>(dst + i8) = o;
}

__global__ __launch_bounds__(256)
void prep_w(const float* __restrict__ src, __half* __restrict__ dst)
{
    const size_t i8 = (size_t)(blockIdx.x * 256 + threadIdx.x) * 8;
    float4 v0 = *reinterpret_cast<const float4*>(src + i8);
    float4 v1 = *reinterpret_cast<const float4*>(src + i8 + 4);
    uint4 o;
    o.x = pack_h2(v0.x, v0.y); o.y = pack_h2(v0.z, v0.w);
    o.z = pack_h2(v1.x, v1.y); o.w = pack_h2(v1.z, v1.w);
    *reinterpret_cast<uint4*>(dst + i8) = o;
}

// ---------------------------------------------------------------------------
// Fused K+V projection GEMM, cp.async 2-stage pipelined; V written TRANSPOSED.
// BM=BN=128, BK=64, 512 threads (16 warps), warp tile 32x32 (x2 outputs).
// Dynamic smem: 2 stages x (A 16KB + Bk 16KB + Bv 16KB) = 96 KB.
// ---------------------------------------------------------------------------
constexpr int KV_STAGE_H = 3 * 128 * 64;                // halves per stage
constexpr int KV_SMEM_BYTES = 2 * KV_STAGE_H * 2;       // 96 KB

__global__ __launch_bounds__(512)
void kvgemm(const __half* __restrict__ A, const __half* __restrict__ Wk,
            const __half* __restrict__ Wv, const float* __restrict__ bk,
            const float* __restrict__ bv, __half* __restrict__ CK,
            __half* __restrict__ Vt)
{
    extern __shared__ __half sm[];

    const int tid  = threadIdx.x;
    const int warp = tid >> 5;
    const int lane = tid & 31;
    const int gr   = lane >> 2;
    const int cc   = lane & 3;
    const int lr   = lane & 7;
    const int lmh  = lane >> 4;
    const int lml  = (lane >> 3) & 1;
    const int wm   = (warp >> 2) * 32;
    const int wn   = (warp & 3) * 32;
    const int m0   = blockIdx.y * 128;
    const int n0   = blockIdx.x * 128;

    const uint32_t smBase = (uint32_t)__cvta_generic_to_shared(sm);

    float accK[2][4][4], accV[2][4][4];
#pragma unroll
    for (int mt = 0; mt < 2; mt++)
#pragma unroll
        for (int nt = 0; nt < 4; nt++)
#pragma unroll
            for (int r = 0; r < 4; r++) { accK[mt][nt][r] = 0.f; accV[mt][nt][r] = 0.f; }

    // issue one BK=64 stage via cp.async (A + Wk + Wv tiles, swizzled)
    auto issue_stage = [&](int k0, int st) {
        const uint32_t sa = smBase + (uint32_t)(st * KV_STAGE_H) * 2;
        const uint32_t sk = sa + 128 * 64 * 2;
        const uint32_t sv = sk + 128 * 64 * 2;
#pragma unroll
        for (int p = 0; p < 2; p++) {
            const int idx = tid + p * 512;
            const int r   = idx >> 3;
            const int g0  = idx & 7;
            const uint32_t off = (uint32_t)(r * 128 + ((g0 ^ (r & 7)) << 4));
            const size_t goff = (size_t)g0 * 8 + k0;
            cp16(sa + off, A  + (size_t)(m0 + r) * Dc + goff);
            cp16(sk + off, Wk + (size_t)(n0 + r) * Dc + goff);
            cp16(sv + off, Wv + (size_t)(n0 + r) * Dc + goff);
        }
        cp_commit();
    };

    issue_stage(0, 0);

    constexpr int NSTAGES = Dc / 64;   // 16
    for (int it = 0; it < NSTAGES; it++) {
        if (it + 1 < NSTAGES) {
            issue_stage((it + 1) * 64, (it + 1) & 1);
            cp_wait<1>();
        } else {
            cp_wait<0>();
        }
        __syncthreads();

        const uint32_t aBase = smBase + (uint32_t)((it & 1) * KV_STAGE_H) * 2;
        const uint32_t kBase = aBase + 128 * 64 * 2;
        const uint32_t vBase = kBase + 128 * 64 * 2;

#pragma unroll
        for (int ks = 0; ks < 4; ks++) {
            uint32_t af[2][4];
#pragma unroll
            for (int mt = 0; mt < 2; mt++) {
                const int r  = wm + mt * 16 + lml * 8 + lr;
                const int lg = 2 * ks + lmh;
                ldsm_x4(af[mt][0], af[mt][1], af[mt][2], af[mt][3],
                        aBase + (uint32_t)(r * 128 + ((lg ^ (r & 7)) << 4)));
            }
            uint32_t bkf[8], bvf[8];
#pragma unroll
            for (int j = 0; j < 2; j++) {
                const int n  = wn + (2 * j + lmh) * 8 + lr;
                const int lg = 2 * ks + lml;
                const uint32_t off = (uint32_t)(n * 128 + ((lg ^ (n & 7)) << 4));
                ldsm_x4(bkf[4 * j], bkf[4 * j + 1], bkf[4 * j + 2], bkf[4 * j + 3], kBase + off);
                ldsm_x4(bvf[4 * j], bvf[4 * j + 1], bvf[4 * j + 2], bvf[4 * j + 3], vBase + off);
            }
#pragma unroll
            for (int nt = 0; nt < 4; nt++) {
                const int bi = 4 * (nt >> 1) + 2 * (nt & 1);
#pragma unroll
                for (int mt = 0; mt < 2; mt++) {
                    mma_f16(accK[mt][nt][0], accK[mt][nt][1], accK[mt][nt][2], accK[mt][nt][3],
                            af[mt][0], af[mt][1], af[mt][2], af[mt][3], bkf[bi], bkf[bi + 1]);
                    mma_f16(accV[mt][nt][0], accV[mt][nt][1], accV[mt][nt][2], accV[mt][nt][3],
                            af[mt][0], af[mt][1], af[mt][2], af[mt][3], bvf[bi], bvf[bi + 1]);
                }
            }
        }
        __syncthreads();
    }

    // epilogue 1: K direct (row-major fp16), accV staged transposed into smem
    constexpr int LDV = 136;
    __half* VsT = sm;          // stage-0 smem: [128 dims][LDV] = 34816 B
#pragma unroll
    for (int mt = 0; mt < 2; mt++) {
#pragma unroll
        for (int nt = 0; nt < 4; nt++) {
            const int rl  = wm + mt * 16 + gr;
            const int cl  = wn + nt * 8 + 2 * cc;
            const int row = m0 + rl;
            const int col = n0 + cl;
            const float bk0 = bk[col], bk1 = bk[col + 1];
            const float bv0 = bv[col], bv1 = bv[col + 1];
            __half2* CKp = (__half2*)CK;
            CKp[((size_t)row * Dc + col) >> 1] =
                __floats2half2_rn(accK[mt][nt][0] + bk0, accK[mt][nt][1] + bk1);
            CKp[((size_t)(row + 8) * Dc + col) >> 1] =
                __floats2half2_rn(accK[mt][nt][2] + bk0, accK[mt][nt][3] + bk1);
            VsT[(cl)     * LDV + rl]     = __float2half_rn(accV[mt][nt][0] + bv0);
            VsT[(cl + 1) * LDV + rl]     = __float2half_rn(accV[mt][nt][1] + bv1);
            VsT[(cl)     * LDV + rl + 8] = __float2half_rn(accV[mt][nt][2] + bv0);
            VsT[(cl + 1) * LDV + rl + 8] = __float2half_rn(accV[mt][nt][3] + bv1);
        }
    }
    __syncthreads();

    // epilogue 2: coalesced transposed V write: Vt[(b*16+h)*64+d][key]
    const int bb   = m0 >> 13;
    const int key0 = m0 & (TKc - 1);
#pragma unroll
    for (int p = 0; p < 4; p++) {
        const int idx = tid + p * 512;
        const int dl  = idx >> 4;
        const int kc  = idx & 15;
        const int gd  = n0 + dl;
        const int h   = gd >> 6;
        const int d   = gd & 63;
        uint4 v = *reinterpret_cast<const uint4*>(&VsT[dl * LDV + kc * 8]);
        *reinterpret_cast<uint4*>(
            Vt + ((size_t)((bb * NHc + h) * HDc + d)) * TKc + key0 + kc * 8) = v;
    }
}

// ---------------------------------------------------------------------------
// fp16 GEMM for Q / O projections, BM=64 x BN=128 (unchanged).
// ---------------------------------------------------------------------------
__global__ __launch_bounds__(256)
void gemm16b(const float* __restrict__ A, const float* __restrict__ W,
             const float* __restrict__ bias, float* __restrict__ C,
             int M, int N, int K)
{
    __shared__ __half As[64 * 64];
    __shared__ __half Bs[128 * 64];
    uint32_t* As32 = reinterpret_cast<uint32_t*>(As);
    uint32_t* Bs32 = reinterpret_cast<uint32_t*>(Bs);

    const int tid  = threadIdx.x;
    const int warp = tid >> 5;
    const int lane = tid & 31;
    const int gr   = lane >> 2;
    const int cc   = lane & 3;
    const int wm   = (warp >> 2) * 32;
    const int wn   = (warp & 3) * 32;
    const int m0   = blockIdx.y * 64;
    const int n0   = blockIdx.x * 128;

    float acc[2][4][4];
#pragma unroll
    for (int mt = 0; mt < 2; mt++)
#pragma unroll
        for (int nt = 0; nt < 4; nt++)
#pragma unroll
            for (int r = 0; r < 4; r++) acc[mt][nt][r] = 0.f;

    float4 rA[4], rB[8];
    auto load_tiles = [&](int k0) {
#pragma unroll
        for (int p = 0; p < 2; p++) {
            const int idx = tid + p * 256;
            const int r   = idx >> 3;
            const int gk  = k0 + (idx & 7) * 8;
            const float* ap = A + (size_t)(m0 + r) * K + gk;
            rA[p * 2]     = *reinterpret_cast<const float4*>(ap);
            rA[p * 2 + 1] = *reinterpret_cast<const float4*>(ap + 4);
        }
#pragma unroll
        for (int p = 0; p < 4; p++) {
            const int idx = tid + p * 256;
            const int r   = idx >> 3;
            const int gk  = k0 + (idx & 7) * 8;
            const float* wp = W + (size_t)(n0 + r) * K + gk;
            rB[p * 2]     = *reinterpret_cast<const float4*>(wp);
            rB[p * 2 + 1] = *reinterpret_cast<const float4*>(wp + 4);
        }
    };
    auto store_tiles = [&]() {
#pragma unroll
        for (int p = 0; p < 2; p++) {
            const int idx = tid + p * 256;
            const int r   = idx >> 3;
            const int g   = (idx & 7) ^ (r & 7);
            float4 a0 = rA[p * 2], a1 = rA[p * 2 + 1];
            uint4 ua;
            ua.x = pack_h2(a0.x, a0.y); ua.y = pack_h2(a0.z, a0.w);
            ua.z = pack_h2(a1.x, a1.y); ua.w = pack_h2(a1.z, a1.w);
            *reinterpret_cast<uint4*>(&As[r * 64 + g * 8]) = ua;
        }
#pragma unroll
        for (int p = 0; p < 4; p++) {
            const int idx = tid + p * 256;
            const int r   = idx >> 3;
            const int g   = (idx & 7) ^ (r & 7);
            float4 b0 = rB[p * 2], b1 = rB[p * 2 + 1];
            uint4 ub;
            ub.x = pack_h2(b0.x, b0.y); ub.y = pack_h2(b0.z, b0.w);
            ub.z = pack_h2(b1.x, b1.y); ub.w = pack_h2(b1.z, b1.w);
            *reinterpret_cast<uint4*>(&Bs[r * 64 + g * 8]) = ub;
        }
    };

    load_tiles(0);
    for (int k0 = 0; k0 < K; k0 += 64) {
        store_tiles();
        __syncthreads();
        if (k0 + 64 < K) load_tiles(k0 + 64);
#pragma unroll
        for (int ks = 0; ks < 4; ks++) {
            uint32_t af[2][4];
#pragma unroll
            for (int mt = 0; mt < 2; mt++) {
                const int r = wm + mt * 16 + gr;
                af[mt][0] = As32[sw_idx64(r,     2 * ks,     cc)];
                af[mt][1] = As32[sw_idx64(r + 8, 2 * ks,     cc)];
                af[mt][2] = As32[sw_idx64(r,     2 * ks + 1, cc)];
                af[mt][3] = As32[sw_idx64(r + 8, 2 * ks + 1, cc)];
            }
#pragma unroll
            for (int nt = 0; nt < 4; nt++) {
                const int n = wn + nt * 8 + gr;
                uint32_t b0 = Bs32[sw_idx64(n, 2 * ks,     cc)];
                uint32_t b1 = Bs32[sw_idx64(n, 2 * ks + 1, cc)];
#pragma unroll
                for (int mt = 0; mt < 2; mt++)
                    mma_f16(acc[mt][nt][0], acc[mt][nt][1], acc[mt][nt][2], acc[mt][nt][3],
                            af[mt][0], af[mt][1], af[mt][2], af[mt][3], b0, b1);
            }
        }
        __syncthreads();
    }

#pragma unroll
    for (int mt = 0; mt < 2; mt++) {
#pragma unroll
        for (int nt = 0; nt < 4; nt++) {
            const int row = m0 + wm + mt * 16 + gr;
            const int col = n0 + wn + nt * 8 + 2 * cc;
            const float b0v = bias[col], b1v = bias[col + 1];
            *reinterpret_cast<float2*>(C + (size_t)row * N + col) =
                make_float2(acc[mt][nt][0] + b0v, acc[mt][nt][1] + b1v);
            *reinterpret_cast<float2*>(C + (size_t)(row + 8) * N + col) =
                make_float2(acc[mt][nt][2] + b0v, acc[mt][nt][3] + b1v);
        }
    }
}

// ---------------------------------------------------------------------------
// fp16 MMA flash attention (unchanged R12): cp.async double-buffered TS=64.
// ---------------------------------------------------------------------------
constexpr int TSa = 64;

__global__ __launch_bounds__(256)
void attn_f16(const float* __restrict__ Qp, const __half* __restrict__ Kh,
              const __half* __restrict__ Vt, float* __restrict__ At,
              const float* __restrict__ p_log_temp, const int* __restrict__ pNA)
{
    __shared__ __half Ks[2][64 * 64];
    __shared__ __half VtS[2][64 * 64];

    const int b    = blockIdx.z;
    const int h    = blockIdx.y;
    const int q0   = blockIdx.x * 128;
    const int tid  = threadIdx.x;
    const int warp = tid >> 5;
    const int lane = tid & 31;
    const int gr   = lane >> 2;
    const int cc   = lane & 3;
    const int lr   = lane & 7;
    const int lmh  = lane >> 4;
    const int lml  = (lane >> 3) & 1;
    const int rl   = warp * 16 + gr;
    const int row0 = q0 + rl;

    const uint32_t ksBase  = (uint32_t)__cvta_generic_to_shared(&Ks[0][0]);
    const uint32_t vtsBase = (uint32_t)__cvta_generic_to_shared(&VtS[0][0]);

    const int na = *pNA;
    float temp = __expf(*p_log_temp);
    temp = fminf(fmaxf(temp, 0.1f), 10.0f);
    const float scale = 1.0f / ((float)HDc * temp);

    uint32_t qf[4][4];
    {
        const float* qr0 = Qp + ((size_t)(b * TQc + row0)) * Dc + h * HDc;
        const float* qr1 = qr0 + 8 * (size_t)Dc;
#pragma unroll
        for (int ks = 0; ks < 4; ks++) {
            const int k = ks * 16;
            float2 a  = *reinterpret_cast<const float2*>(qr0 + k + 2 * cc);
            float2 bv = *reinterpret_cast<const float2*>(qr1 + k + 2 * cc);
            float2 c2 = *reinterpret_cast<const float2*>(qr0 + k + 8 + 2 * cc);
            float2 d2 = *reinterpret_cast<const float2*>(qr1 + k + 8 + 2 * cc);
            qf[ks][0] = pack_h2(a.x * scale, a.y * scale);
            qf[ks][1] = pack_h2(bv.x * scale, bv.y * scale);
            qf[ks][2] = pack_h2(c2.x * scale, c2.y * scale);
            qf[ks][3] = pack_h2(d2.x * scale, d2.y * scale);
        }
    }

    float outc[8][4];
#pragma unroll
    for (int nt = 0; nt < 8; nt++)
#pragma unroll
        for (int r = 0; r < 4; r++) outc[nt][r] = 0.f;

    const int lrow = tid >> 3;
    const int seg  = tid & 7;

    auto issue_tile = [&](int kbase, int valid, int st) {
        const uint32_t ksSt = ksBase  + (uint32_t)st * 8192;
        const uint32_t vtSt = vtsBase + (uint32_t)st * 8192;
#pragma unroll
        for (int p = 0; p < 2; p++) {
            const int r = lrow + p * 32;
            const int g = seg ^ (r & 7);
            const int srcsz = (r < valid) ? 16 : 0;
            const int gkey  = kbase + ((r < valid) ? r : 0);
            cp16z(ksSt + (uint32_t)(r * 128 + g * 16),
                  Kh + ((size_t)(b * TKc + gkey)) * Dc + h * HDc + seg * 8, srcsz);
        }
#pragma unroll
        for (int p = 0; p < 2; p++) {
            const int r = lrow + p * 32;
            const int g = seg ^ (r & 7);
            int srcsz = (valid - seg * 8) * 2;
            srcsz = srcsz < 0 ? 0 : (srcsz > 16 ? 16 : srcsz);
            cp16z(vtSt + (uint32_t)(r * 128 + g * 16),
                  Vt + ((size_t)((b * NHc + h) * HDc + r)) * TKc + kbase + seg * 8, srcsz);
        }
        cp_commit();
    };

    for (int segi = 0; segi < 2; segi++) {
        const int s_begin = segi ? na : 0;
        const int s_end   = segi ? TKc : na;
        const int s_cnt   = s_end - s_begin;
        if (s_cnt <= 0) continue;
        const float coef = (segi ? -1.f : 1.f) / sqrtf((float)s_cnt);

        float l0 = 0.f, l1 = 0.f;
        float o[8][4];
#pragma unroll
        for (int nt = 0; nt < 8; nt++)
#pragma unroll
            for (int r = 0; r < 4; r++) o[nt][r] = 0.f;

        const int ntiles = (s_cnt + TSa - 1) / TSa;
        issue_tile(s_begin, min(TSa, s_cnt), 0);

        for (int tile = 0; tile < ntiles; tile++) {
            const int kbase = s_begin + tile * TSa;
            const int valid = min(TSa, s_end - kbase);
            const bool partial = (valid < TSa);
            const int st = tile & 1;

            if (tile + 1 < ntiles) {
                const int kb2 = kbase + TSa;
                issue_tile(kb2, min(TSa, s_end - kb2), (tile + 1) & 1);
                cp_wait<1>();
            } else {
                cp_wait<0>();
            }
            __syncthreads();

            const uint32_t ksSt = ksBase  + (uint32_t)st * 8192;
            const uint32_t vtSt = vtsBase + (uint32_t)st * 8192;

            float sacc[8][4];
#pragma unroll
            for (int nt = 0; nt < 8; nt++)
#pragma unroll
                for (int r = 0; r < 4; r++) sacc[nt][r] = 0.f;
#pragma unroll
            for (int ks = 0; ks < 4; ks++) {
#pragma unroll
                for (int j = 0; j < 4; j++) {
                    const int n  = (2 * j + lmh) * 8 + lr;
                    const int lg = 2 * ks + lml;
                    uint32_t f0, f1, f2, f3;
                    ldsm_x4(f0, f1, f2, f3,
                            ksSt + (uint32_t)(n * 128 + ((lg ^ (n & 7)) << 4)));
                    mma_f16(sacc[2*j][0], sacc[2*j][1], sacc[2*j][2], sacc[2*j][3],
                            qf[ks][0], qf[ks][1], qf[ks][2], qf[ks][3], f0, f1);
                    mma_f16(sacc[2*j+1][0], sacc[2*j+1][1], sacc[2*j+1][2], sacc[2*j+1][3],
                            qf[ks][0], qf[ks][1], qf[ks][2], qf[ks][3], f2, f3);
                }
            }

            if (partial) {
#pragma unroll
                for (int nt = 0; nt < 8; nt++) {
                    const int col = nt * 8 + 2 * cc;
                    if (col     >= valid) { sacc[nt][0] = -INFINITY; sacc[nt][2] = -INFINITY; }
                    if (col + 1 >= valid) { sacc[nt][1] = -INFINITY; sacc[nt][3] = -INFINITY; }
                }
            }

            uint32_t ap[4][4];
#pragma unroll
            for (int nt = 0; nt < 8; nt++) {
                float p0 = __expf(sacc[nt][0]);
                float p1 = __expf(sacc[nt][1]);
                float p2 = __expf(sacc[nt][2]);
                float p3 = __expf(sacc[nt][3]);
                l0 += p0 + p1;
                l1 += p2 + p3;
                const int kt   = nt >> 1;
                const int half = nt & 1;
                ap[kt][half * 2]     = pack_h2(p0, p1);
                ap[kt][half * 2 + 1] = pack_h2(p2, p3);
            }

#pragma unroll
            for (int kt = 0; kt < 4; kt++) {
#pragma unroll
                for (int j = 0; j < 4; j++) {
                    const int n  = (2 * j + lmh) * 8 + lr;
                    const int lg = 2 * kt + lml;
                    uint32_t f0, f1, f2, f3;
                    ldsm_x4(f0, f1, f2, f3,
                            vtSt + (uint32_t)(n * 128 + ((lg ^ (n & 7)) << 4)));
                    mma_f16(o[2*j][0], o[2*j][1], o[2*j][2], o[2*j][3],
                            ap[kt][0], ap[kt][1], ap[kt][2], ap[kt][3], f0, f1);
                    mma_f16(o[2*j+1][0], o[2*j+1][1], o[2*j+1][2], o[2*j+1][3],
                            ap[kt][0], ap[kt][1], ap[kt][2], ap[kt][3], f2, f3);
                }
            }
            __syncthreads();
        }

        l0 += __shfl_xor_sync(0xffffffffu, l0, 1);
        l0 += __shfl_xor_sync(0xffffffffu, l0, 2);
        l1 += __shfl_xor_sync(0xffffffffu, l1, 1);
        l1 += __shfl_xor_sync(0xffffffffu, l1, 2);
        const float inv0 = coef / l0;
        const float inv1 = coef / l1;
#pragma unroll
        for (int nt = 0; nt < 8; nt++) {
            outc[nt][0] += o[nt][0] * inv0;
            outc[nt][1] += o[nt][1] * inv0;
            outc[nt][2] += o[nt][2] * inv1;
            outc[nt][3] += o[nt][3] * inv1;
        }
    }

    float* ob = At + ((size_t)(b * TQc + row0)) * Dc + h * HDc;
#pragma unroll
    for (int nt = 0; nt < 8; nt++) {
        const int col = nt * 8 + 2 * cc;
        *reinterpret_cast<float2*>(ob + col) = make_float2(outc[nt][0], outc[nt][1]);
        *reinterpret_cast<float2*>(ob + 8 * (size_t)Dc + col) = make_float2(outc[nt][2], outc[nt][3]);
    }
}

// ---------------------------------------------------------------------------
// kernel_launch
// ---------------------------------------------------------------------------
extern "C" void kernel_launch(void* const* d_in, const int* in_sizes, int n_in,
                              void* d_out, int out_size)
{
    const float* q    = (const float*)d_in[0];
    const float* kv   = (const float*)d_in[1];
    const float* Wq   = (const float*)d_in[2];
    const float* bq   = (const float*)d_in[3];
    const float* Wk   = (const float*)d_in[4];
    const float* bk   = (const float*)d_in[5];
    const float* Wv   = (const float*)d_in[6];
    const float* bv   = (const float*)d_in[7];
    const float* Wo   = (const float*)d_in[8];
    const float* bo   = (const float*)d_in[9];
    const float* abA  = (const float*)d_in[10];
    const float* abI  = (const float*)d_in[11];
    const float* logt = (const float*)d_in[12];
    const int*   pNA  = (const int*)d_in[13];
    float* out = (float*)d_out;

    void *pQp, *pA16, *pWk16, *pWv16, *pKh, *pVt, *pAt;
    cudaGetSymbolAddress(&pQp,   g_Qp);
    cudaGetSymbolAddress(&pA16,  g_A16);
    cudaGetSymbolAddress(&pWk16, g_Wk16);
    cudaGetSymbolAddress(&pWv16, g_Wv16);
    cudaGetSymbolAddress(&pKh,   g_Kh);
    cudaGetSymbolAddress(&pVt,   g_Vt);
    cudaGetSymbolAddress(&pAt,   g_At);

    // opt-in to >48KB dynamic smem for the pipelined kvgemm
    cudaFuncSetAttribute(kvgemm, cudaFuncAttributeMaxDynamicSharedMemorySize,
                         KV_SMEM_BYTES);

    const dim3 gblk(256);

    prep_kv<<<(Bc * TKc * Dc) / (256 * 8), gblk>>>(kv, abA, abI, pNA, (__half*)pA16);
    prep_w<<<(Dc * Dc) / (256 * 8), gblk>>>(Wk, (__half*)pWk16);
    prep_w<<<(Dc * Dc) / (256 * 8), gblk>>>(Wv, (__half*)pWv16);

    gemm16b<<<dim3(Dc / 128, (Bc * TQc) / 64), gblk>>>(
        q, Wq, bq, (float*)pQp, Bc * TQc, Dc, Dc);

    // cp.async 2-stage fused K+V projection (K row-major, V transposed)
    kvgemm<<<dim3(Dc / 128, (Bc * TKc) / 128), dim3(512), KV_SMEM_BYTES>>>(
        (const __half*)pA16, (const __half*)pWk16, (const __half*)pWv16,
        bk, bv, (__half*)pKh, (__half*)pVt);

    attn_f16<<<dim3(TQc / 128, NHc, Bc), gblk>>>(
        (const float*)pQp, (const __half*)pKh, (const __half*)pVt, (float*)pAt,
        logt, pNA);

    gemm16b<<<dim3(Dc / 128, (Bc * TQc) / 64), gblk>>>(
        (const float*)pAt, Wo, bo, out, Bc * TQc, Dc, Dc);
}

// round 16
// speedup vs baseline: 16.0663x; 1.0025x over previous
#include <cuda_runtime.h>
#include <cuda_fp16.h>
#include <cstdint>
#include <math.h>

// Problem dimensions (fixed)
constexpr int Bc  = 2;
constexpr int TQc = 512;
constexpr int TKc = 8192;
constexpr int Dc  = 1024;
constexpr int NHc = 16;
constexpr int HDc = 64;

// Scratch (allocation-free)
__device__ float  g_Qp[(size_t)Bc * TQc * Dc];            // Q projected, fp32
__device__ __half g_A16[(size_t)Bc * TKc * Dc];           // kv + group bias, fp16
__device__ __half g_Wk16[(size_t)Dc * Dc];
__device__ __half g_Wv16[(size_t)Dc * Dc];
__device__ __half g_Kh[(size_t)Bc * TKc * Dc];            // K projected, fp16
__device__ __half g_Vt[(size_t)Bc * NHc * HDc * TKc];     // V transposed [b,h,dim][key]
__device__ float  g_At[(size_t)Bc * TQc * Dc];            // attention out, fp32

// ---------------------------------------------------------------------------
// helpers
// ---------------------------------------------------------------------------
__device__ __forceinline__ uint32_t pack_h2(float lo, float hi) {
    __half2 h = __floats2half2_rn(lo, hi);
    return *reinterpret_cast<uint32_t*>(&h);
}

__device__ __forceinline__ void mma_f16(float& c0, float& c1, float& c2, float& c3,
                                        uint32_t a0, uint32_t a1, uint32_t a2, uint32_t a3,
                                        uint32_t b0, uint32_t b1)
{
    asm volatile(
        "mma.sync.aligned.m16n8k16.row.col.f32.f16.f16.f32 "
        "{%0,%1,%2,%3}, {%4,%5,%6,%7}, {%8,%9}, {%0,%1,%2,%3};"
        : "+f"(c0), "+f"(c1), "+f"(c2), "+f"(c3)
        : "r"(a0), "r"(a1), "r"(a2), "r"(a3), "r"(b0), "r"(b1));
}

__device__ __forceinline__ void ldsm_x4(uint32_t& r0, uint32_t& r1,
                                        uint32_t& r2, uint32_t& r3, uint32_t addr)
{
    asm volatile("ldmatrix.sync.aligned.m8n8.x4.shared.b16 {%0,%1,%2,%3}, [%4];"
                 : "=r"(r0), "=r"(r1), "=r"(r2), "=r"(r3) : "r"(addr));
}

__device__ __forceinline__ void cp16(uint32_t dst, const void* src) {
    asm volatile("cp.async.cg.shared.global [%0], [%1], 16;" :: "r"(dst), "l"(src));
}
__device__ __forceinline__ void cp16z(uint32_t dst, const void* src, int srcsz) {
    asm volatile("cp.async.cg.shared.global [%0], [%1], 16, %2;"
                 :: "r"(dst), "l"(src), "r"(srcsz));
}
__device__ __forceinline__ void cp_commit() { asm volatile("cp.async.commit_group;"); }
template <int N>
__device__ __forceinline__ void cp_wait() { asm volatile("cp.async.wait_group %0;" :: "n"(N)); }

// swizzled u32 index, fp16 tile, row stride 64 halves (32 u32)
__device__ __forceinline__ int sw_idx64(int row, int gbase, int cc) {
    return row * 32 + ((gbase ^ (row & 7)) << 2) + cc;
}

// ---------------------------------------------------------------------------
// prep: kv(fp32) + group bias -> fp16 ; fp32 -> fp16 for both weights (y=0/1)
// ---------------------------------------------------------------------------
__global__ __launch_bounds__(256)
void prep_kv(const float* __restrict__ kv, const float* __restrict__ abA,
             const float* __restrict__ abI, const int* __restrict__ pNA,
             __half* __restrict__ dst)
{
    const int na = *pNA;
    const size_t i8 = (size_t)(blockIdx.x * 256 + threadIdx.x) * 8;
    const int row = (int)(i8 >> 10);
    const int col = (int)(i8 & 1023);
    const float* ab = ((row % TKc) < na) ? abA : abI;
    float4 v0 = *reinterpret_cast<const float4*>(kv + i8);
    float4 v1 = *reinterpret_cast<const float4*>(kv + i8 + 4);
    float4 b0 = *reinterpret_cast<const float4*>(ab + col);
    float4 b1 = *reinterpret_cast<const float4*>(ab + col + 4);
    uint4 o;
    o.x = pack_h2(v0.x + b0.x, v0.y + b0.y);
    o.y = pack_h2(v0.z + b0.z, v0.w + b0.w);
    o.z = pack_h2(v1.x + b1.x, v1.y + b1.y);
    o.w = pack_h2(v1.z + b1.z, v1.w + b1.w);
    *reinterpret_cast<uint4*>(dst + i8) = o;
}

__global__ __launch_bounds__(256)
void prep_w2(const float* __restrict__ srcK, const float* __restrict__ srcV,
             __half* __restrict__ dstK, __half* __restrict__ dstV)
{
    const float* src = blockIdx.y ? srcV : srcK;
    __half*      dst = blockIdx.y ? dstV : dstK;
    const size_t i8 = (size_t)(blockIdx.x * 256 + threadIdx.x) * 8;
    float4 v0 = *reinterpret_cast<const float4*>(src + i8);
    float4 v1 = *reinterpret_cast<const float4*>(src + i8 + 4);
    uint4 o;
    o.x = pack_h2(v0.x, v0.y); o.y = pack_h2(v0.z, v0.w);
    o.z = pack_h2(v1.x, v1.y); o.w = pack_h2(v1.z, v1.w);
    *reinterpret_cast<uint4*>(dst + i8) = o;
}

// ---------------------------------------------------------------------------
// Fused K+V projection GEMM, cp.async 3-stage pipelined, ONE barrier/stage;
// V written TRANSPOSED. BM=BN=128, BK=64, 512 threads, warp tile 32x32 x2.
// Dynamic smem: 3 stages x (A 16KB + Bk 16KB + Bv 16KB) = 144 KB.
// Iteration order: wait(1) -> bar -> issue(it+2) -> compute(it).
// ---------------------------------------------------------------------------
constexpr int KV_STAGE_H = 3 * 128 * 64;                // halves per stage
constexpr int KV_SMEM_BYTES = 3 * KV_STAGE_H * 2;       // 144 KB

__global__ __launch_bounds__(512)
void kvgemm(const __half* __restrict__ A, const __half* __restrict__ Wk,
            const __half* __restrict__ Wv, const float* __restrict__ bk,
            const float* __restrict__ bv, __half* __restrict__ CK,
            __half* __restrict__ Vt)
{
    extern __shared__ __half sm[];

    const int tid  = threadIdx.x;
    const int warp = tid >> 5;
    const int lane = tid & 31;
    const int gr   = lane >> 2;
    const int cc   = lane & 3;
    const int lr   = lane & 7;
    const int lmh  = lane >> 4;
    const int lml  = (lane >> 3) & 1;
    const int wm   = (warp >> 2) * 32;
    const int wn   = (warp & 3) * 32;
    const int m0   = blockIdx.y * 128;
    const int n0   = blockIdx.x * 128;

    const uint32_t smBase = (uint32_t)__cvta_generic_to_shared(sm);

    float accK[2][4][4], accV[2][4][4];
#pragma unroll
    for (int mt = 0; mt < 2; mt++)
#pragma unroll
        for (int nt = 0; nt < 4; nt++)
#pragma unroll
            for (int r = 0; r < 4; r++) { accK[mt][nt][r] = 0.f; accV[mt][nt][r] = 0.f; }

    // issue one BK=64 stage via cp.async (A + Wk + Wv tiles, swizzled)
    auto issue_stage = [&](int k0, int st) {
        const uint32_t sa = smBase + (uint32_t)(st * KV_STAGE_H) * 2;
        const uint32_t sk = sa + 128 * 64 * 2;
        const uint32_t sv = sk + 128 * 64 * 2;
#pragma unroll
        for (int p = 0; p < 2; p++) {
            const int idx = tid + p * 512;
            const int r   = idx >> 3;
            const int g0  = idx & 7;
            const uint32_t off = (uint32_t)(r * 128 + ((g0 ^ (r & 7)) << 4));
            const size_t goff = (size_t)g0 * 8 + k0;
            cp16(sa + off, A  + (size_t)(m0 + r) * Dc + goff);
            cp16(sk + off, Wk + (size_t)(n0 + r) * Dc + goff);
            cp16(sv + off, Wv + (size_t)(n0 + r) * Dc + goff);
        }
        cp_commit();
    };

    issue_stage(0, 0);
    issue_stage(64, 1);

    constexpr int NSTAGES = Dc / 64;   // 16
    for (int it = 0; it < NSTAGES; it++) {
        if (it < NSTAGES - 1) cp_wait<1>();   // stage it complete (it+1 may fly)
        else                  cp_wait<0>();   // last stage: drain all
        __syncthreads();                      // visibility + WAR guard
        if (it + 2 < NSTAGES) issue_stage((it + 2) * 64, (it + 2) % 3);

        const int st = it % 3;
        const uint32_t aBase = smBase + (uint32_t)(st * KV_STAGE_H) * 2;
        const uint32_t kBase = aBase + 128 * 64 * 2;
        const uint32_t vBase = kBase + 128 * 64 * 2;

#pragma unroll
        for (int ks = 0; ks < 4; ks++) {
            uint32_t af[2][4];
#pragma unroll
            for (int mt = 0; mt < 2; mt++) {
                const int r  = wm + mt * 16 + lml * 8 + lr;
                const int lg = 2 * ks + lmh;
                ldsm_x4(af[mt][0], af[mt][1], af[mt][2], af[mt][3],
                        aBase + (uint32_t)(r * 128 + ((lg ^ (r & 7)) << 4)));
            }
            uint32_t bkf[8], bvf[8];
#pragma unroll
            for (int j = 0; j < 2; j++) {
                const int n  = wn + (2 * j + lmh) * 8 + lr;
                const int lg = 2 * ks + lml;
                const uint32_t off = (uint32_t)(n * 128 + ((lg ^ (n & 7)) << 4));
                ldsm_x4(bkf[4 * j], bkf[4 * j + 1], bkf[4 * j + 2], bkf[4 * j + 3], kBase + off);
                ldsm_x4(bvf[4 * j], bvf[4 * j + 1], bvf[4 * j + 2], bvf[4 * j + 3], vBase + off);
            }
#pragma unroll
            for (int nt = 0; nt < 4; nt++) {
                const int bi = 4 * (nt >> 1) + 2 * (nt & 1);
#pragma unroll
                for (int mt = 0; mt < 2; mt++) {
                    mma_f16(accK[mt][nt][0], accK[mt][nt][1], accK[mt][nt][2], accK[mt][nt][3],
                            af[mt][0], af[mt][1], af[mt][2], af[mt][3], bkf[bi], bkf[bi + 1]);
                    mma_f16(accV[mt][nt][0], accV[mt][nt][1], accV[mt][nt][2], accV[mt][nt][3],
                            af[mt][0], af[mt][1], af[mt][2], af[mt][3], bvf[bi], bvf[bi + 1]);
                }
            }
        }
    }
    __syncthreads();   // all warps done with final stage before smem reuse

    // epilogue 1: K direct (row-major fp16), accV staged transposed into smem
    constexpr int LDV = 136;
    __half* VsT = sm;          // stage-0 smem: [128 dims][LDV] = 34816 B
#pragma unroll
    for (int mt = 0; mt < 2; mt++) {
#pragma unroll
        for (int nt = 0; nt < 4; nt++) {
            const int rl  = wm + mt * 16 + gr;
            const int cl  = wn + nt * 8 + 2 * cc;
            const int row = m0 + rl;
            const int col = n0 + cl;
            const float bk0 = bk[col], bk1 = bk[col + 1];
            const float bv0 = bv[col], bv1 = bv[col + 1];
            __half2* CKp = (__half2*)CK;
            CKp[((size_t)row * Dc + col) >> 1] =
                __floats2half2_rn(accK[mt][nt][0] + bk0, accK[mt][nt][1] + bk1);
            CKp[((size_t)(row + 8) * Dc + col) >> 1] =
                __floats2half2_rn(accK[mt][nt][2] + bk0, accK[mt][nt][3] + bk1);
            VsT[(cl)     * LDV + rl]     = __float2half_rn(accV[mt][nt][0] + bv0);
            VsT[(cl + 1) * LDV + rl]     = __float2half_rn(accV[mt][nt][1] + bv1);
            VsT[(cl)     * LDV + rl + 8] = __float2half_rn(accV[mt][nt][2] + bv0);
            VsT[(cl + 1) * LDV + rl + 8] = __float2half_rn(accV[mt][nt][3] + bv1);
        }
    }
    __syncthreads();

    // epilogue 2: coalesced transposed V write: Vt[(b*16+h)*64+d][key]
    const int bb   = m0 >> 13;
    const int key0 = m0 & (TKc - 1);
#pragma unroll
    for (int p = 0; p < 4; p++) {
        const int idx = tid + p * 512;
        const int dl  = idx >> 4;
        const int kc  = idx & 15;
        const int gd  = n0 + dl;
        const int h   = gd >> 6;
        const int d   = gd & 63;
        uint4 v = *reinterpret_cast<const uint4*>(&VsT[dl * LDV + kc * 8]);
        *reinterpret_cast<uint4*>(
            Vt + ((size_t)((bb * NHc + h) * HDc + d)) * TKc + key0 + kc * 8) = v;
    }
}

// ---------------------------------------------------------------------------
// fp16 GEMM for Q / O projections, BM=64 x BN=128 (unchanged).
// ---------------------------------------------------------------------------
__global__ __launch_bounds__(256)
void gemm16b(const float* __restrict__ A, const float* __restrict__ W,
             const float* __restrict__ bias, float* __restrict__ C,
             int M, int N, int K)
{
    __shared__ __half As[64 * 64];
    __shared__ __half Bs[128 * 64];
    uint32_t* As32 = reinterpret_cast<uint32_t*>(As);
    uint32_t* Bs32 = reinterpret_cast<uint32_t*>(Bs);

    const int tid  = threadIdx.x;
    const int warp = tid >> 5;
    const int lane = tid & 31;
    const int gr   = lane >> 2;
    const int cc   = lane & 3;
    const int wm   = (warp >> 2) * 32;
    const int wn   = (warp & 3) * 32;
    const int m0   = blockIdx.y * 64;
    const int n0   = blockIdx.x * 128;

    float acc[2][4][4];
#pragma unroll
    for (int mt = 0; mt < 2; mt++)
#pragma unroll
        for (int nt = 0; nt < 4; nt++)
#pragma unroll
            for (int r = 0; r < 4; r++) acc[mt][nt][r] = 0.f;

    float4 rA[4], rB[8];
    auto load_tiles = [&](int k0) {
#pragma unroll
        for (int p = 0; p < 2; p++) {
            const int idx = tid + p * 256;
            const int r   = idx >> 3;
            const int gk  = k0 + (idx & 7) * 8;
            const float* ap = A + (size_t)(m0 + r) * K + gk;
            rA[p * 2]     = *reinterpret_cast<const float4*>(ap);
            rA[p * 2 + 1] = *reinterpret_cast<const float4*>(ap + 4);
        }
#pragma unroll
        for (int p = 0; p < 4; p++) {
            const int idx = tid + p * 256;
            const int r   = idx >> 3;
            const int gk  = k0 + (idx & 7) * 8;
            const float* wp = W + (size_t)(n0 + r) * K + gk;
            rB[p * 2]     = *reinterpret_cast<const float4*>(wp);
            rB[p * 2 + 1] = *reinterpret_cast<const float4*>(wp + 4);
        }
    };
    auto store_tiles = [&]() {
#pragma unroll
        for (int p = 0; p < 2; p++) {
            const int idx = tid + p * 256;
            const int r   = idx >> 3;
            const int g   = (idx & 7) ^ (r & 7);
            float4 a0 = rA[p * 2], a1 = rA[p * 2 + 1];
            uint4 ua;
            ua.x = pack_h2(a0.x, a0.y); ua.y = pack_h2(a0.z, a0.w);
            ua.z = pack_h2(a1.x, a1.y); ua.w = pack_h2(a1.z, a1.w);
            *reinterpret_cast<uint4*>(&As[r * 64 + g * 8]) = ua;
        }
#pragma unroll
        for (int p = 0; p < 4; p++) {
            const int idx = tid + p * 256;
            const int r   = idx >> 3;
            const int g   = (idx & 7) ^ (r & 7);
            float4 b0 = rB[p * 2], b1 = rB[p * 2 + 1];
            uint4 ub;
            ub.x = pack_h2(b0.x, b0.y); ub.y = pack_h2(b0.z, b0.w);
            ub.z = pack_h2(b1.x, b1.y); ub.w = pack_h2(b1.z, b1.w);
            *reinterpret_cast<uint4*>(&Bs[r * 64 + g * 8]) = ub;
        }
    };

    load_tiles(0);
    for (int k0 = 0; k0 < K; k0 += 64) {
        store_tiles();
        __syncthreads();
        if (k0 + 64 < K) load_tiles(k0 + 64);
#pragma unroll
        for (int ks = 0; ks < 4; ks++) {
            uint32_t af[2][4];
#pragma unroll
            for (int mt = 0; mt < 2; mt++) {
                const int r = wm + mt * 16 + gr;
                af[mt][0] = As32[sw_idx64(r,     2 * ks,     cc)];
                af[mt][1] = As32[sw_idx64(r + 8, 2 * ks,     cc)];
                af[mt][2] = As32[sw_idx64(r,     2 * ks + 1, cc)];
                af[mt][3] = As32[sw_idx64(r + 8, 2 * ks + 1, cc)];
            }
#pragma unroll
            for (int nt = 0; nt < 4; nt++) {
                const int n = wn + nt * 8 + gr;
                uint32_t b0 = Bs32[sw_idx64(n, 2 * ks,     cc)];
                uint32_t b1 = Bs32[sw_idx64(n, 2 * ks + 1, cc)];
#pragma unroll
                for (int mt = 0; mt < 2; mt++)
                    mma_f16(acc[mt][nt][0], acc[mt][nt][1], acc[mt][nt][2], acc[mt][nt][3],
                            af[mt][0], af[mt][1], af[mt][2], af[mt][3], b0, b1);
            }
        }
        __syncthreads();
    }

#pragma unroll
    for (int mt = 0; mt < 2; mt++) {
#pragma unroll
        for (int nt = 0; nt < 4; nt++) {
            const int row = m0 + wm + mt * 16 + gr;
            const int col = n0 + wn + nt * 8 + 2 * cc;
            const float b0v = bias[col], b1v = bias[col + 1];
            *reinterpret_cast<float2*>(C + (size_t)row * N + col) =
                make_float2(acc[mt][nt][0] + b0v, acc[mt][nt][1] + b1v);
            *reinterpret_cast<float2*>(C + (size_t)(row + 8) * N + col) =
                make_float2(acc[mt][nt][2] + b0v, acc[mt][nt][3] + b1v);
        }
    }
}

// ---------------------------------------------------------------------------
// fp16 MMA flash attention (unchanged): cp.async double-buffered TS=64.
// ---------------------------------------------------------------------------
constexpr int TSa = 64;

__global__ __launch_bounds__(256)
void attn_f16(const float* __restrict__ Qp, const __half* __restrict__ Kh,
              const __half* __restrict__ Vt, float* __restrict__ At,
              const float* __restrict__ p_log_temp, const int* __restrict__ pNA)
{
    __shared__ __half Ks[2][64 * 64];
    __shared__ __half VtS[2][64 * 64];

    const int b    = blockIdx.z;
    const int h    = blockIdx.y;
    const int q0   = blockIdx.x * 128;
    const int tid  = threadIdx.x;
    const int warp = tid >> 5;
    const int lane = tid & 31;
    const int gr   = lane >> 2;
    const int cc   = lane & 3;
    const int lr   = lane & 7;
    const int lmh  = lane >> 4;
    const int lml  = (lane >> 3) & 1;
    const int rl   = warp * 16 + gr;
    const int row0 = q0 + rl;

    const uint32_t ksBase  = (uint32_t)__cvta_generic_to_shared(&Ks[0][0]);
    const uint32_t vtsBase = (uint32_t)__cvta_generic_to_shared(&VtS[0][0]);

    const int na = *pNA;
    float temp = __expf(*p_log_temp);
    temp = fminf(fmaxf(temp, 0.1f), 10.0f);
    const float scale = 1.0f / ((float)HDc * temp);

    uint32_t qf[4][4];
    {
        const float* qr0 = Qp + ((size_t)(b * TQc + row0)) * Dc + h * HDc;
        const float* qr1 = qr0 + 8 * (size_t)Dc;
#pragma unroll
        for (int ks = 0; ks < 4; ks++) {
            const int k = ks * 16;
            float2 a  = *reinterpret_cast<const float2*>(qr0 + k + 2 * cc);
            float2 bv = *reinterpret_cast<const float2*>(qr1 + k + 2 * cc);
            float2 c2 = *reinterpret_cast<const float2*>(qr0 + k + 8 + 2 * cc);
            float2 d2 = *reinterpret_cast<const float2*>(qr1 + k + 8 + 2 * cc);
            qf[ks][0] = pack_h2(a.x * scale, a.y * scale);
            qf[ks][1] = pack_h2(bv.x * scale, bv.y * scale);
            qf[ks][2] = pack_h2(c2.x * scale, c2.y * scale);
            qf[ks][3] = pack_h2(d2.x * scale, d2.y * scale);
        }
    }

    float outc[8][4];
#pragma unroll
    for (int nt = 0; nt < 8; nt++)
#pragma unroll
        for (int r = 0; r < 4; r++) outc[nt][r] = 0.f;

    const int lrow = tid >> 3;
    const int seg  = tid & 7;

    auto issue_tile = [&](int kbase, int valid, int st) {
        const uint32_t ksSt = ksBase  + (uint32_t)st * 8192;
        const uint32_t vtSt = vtsBase + (uint32_t)st * 8192;
#pragma unroll
        for (int p = 0; p < 2; p++) {
            const int r = lrow + p * 32;
            const int g = seg ^ (r & 7);
            const int srcsz = (r < valid) ? 16 : 0;
            const int gkey  = kbase + ((r < valid) ? r : 0);
            cp16z(ksSt + (uint32_t)(r * 128 + g * 16),
                  Kh + ((size_t)(b * TKc + gkey)) * Dc + h * HDc + seg * 8, srcsz);
        }
#pragma unroll
        for (int p = 0; p < 2; p++) {
            const int r = lrow + p * 32;
            const int g = seg ^ (r & 7);
            int srcsz = (valid - seg * 8) * 2;
            srcsz = srcsz < 0 ? 0 : (srcsz > 16 ? 16 : srcsz);
            cp16z(vtSt + (uint32_t)(r * 128 + g * 16),
                  Vt + ((size_t)((b * NHc + h) * HDc + r)) * TKc + kbase + seg * 8, srcsz);
        }
        cp_commit();
    };

    for (int segi = 0; segi < 2; segi++) {
        const int s_begin = segi ? na : 0;
        const int s_end   = segi ? TKc : na;
        const int s_cnt   = s_end - s_begin;
        if (s_cnt <= 0) continue;
        const float coef = (segi ? -1.f : 1.f) / sqrtf((float)s_cnt);

        float l0 = 0.f, l1 = 0.f;
        float o[8][4];
#pragma unroll
        for (int nt = 0; nt < 8; nt++)
#pragma unroll
            for (int r = 0; r < 4; r++) o[nt][r] = 0.f;

        const int ntiles = (s_cnt + TSa - 1) / TSa;
        issue_tile(s_begin, min(TSa, s_cnt), 0);

        for (int tile = 0; tile < ntiles; tile++) {
            const int kbase = s_begin + tile * TSa;
            const int valid = min(TSa, s_end - kbase);
            const bool partial = (valid < TSa);
            const int st = tile & 1;

            if (tile + 1 < ntiles) {
                const int kb2 = kbase + TSa;
                issue_tile(kb2, min(TSa, s_end - kb2), (tile + 1) & 1);
                cp_wait<1>();
            } else {
                cp_wait<0>();
            }
            __syncthreads();

            const uint32_t ksSt = ksBase  + (uint32_t)st * 8192;
            const uint32_t vtSt = vtsBase + (uint32_t)st * 8192;

            float sacc[8][4];
#pragma unroll
            for (int nt = 0; nt < 8; nt++)
#pragma unroll
                for (int r = 0; r < 4; r++) sacc[nt][r] = 0.f;
#pragma unroll
            for (int ks = 0; ks < 4; ks++) {
#pragma unroll
                for (int j = 0; j < 4; j++) {
                    const int n  = (2 * j + lmh) * 8 + lr;
                    const int lg = 2 * ks + lml;
                    uint32_t f0, f1, f2, f3;
                    ldsm_x4(f0, f1, f2, f3,
                            ksSt + (uint32_t)(n * 128 + ((lg ^ (n & 7)) << 4)));
                    mma_f16(sacc[2*j][0], sacc[2*j][1], sacc[2*j][2], sacc[2*j][3],
                            qf[ks][0], qf[ks][1], qf[ks][2], qf[ks][3], f0, f1);
                    mma_f16(sacc[2*j+1][0], sacc[2*j+1][1], sacc[2*j+1][2], sacc[2*j+1][3],
                            qf[ks][0], qf[ks][1], qf[ks][2], qf[ks][3], f2, f3);
                }
            }

            if (partial) {
#pragma unroll
                for (int nt = 0; nt < 8; nt++) {
                    const int col = nt * 8 + 2 * cc;
                    if (col     >= valid) { sacc[nt][0] = -INFINITY; sacc[nt][2] = -INFINITY; }
                    if (col + 1 >= valid) { sacc[nt][1] = -INFINITY; sacc[nt][3] = -INFINITY; }
                }
            }

            uint32_t ap[4][4];
#pragma unroll
            for (int nt = 0; nt < 8; nt++) {
                float p0 = __expf(sacc[nt][0]);
                float p1 = __expf(sacc[nt][1]);
                float p2 = __expf(sacc[nt][2]);
                float p3 = __expf(sacc[nt][3]);
                l0 += p0 + p1;
                l1 += p2 + p3;
                const int kt   = nt >> 1;
                const int half = nt & 1;
                ap[kt][half * 2]     = pack_h2(p0, p1);
                ap[kt][half * 2 + 1] = pack_h2(p2, p3);
            }

#pragma unroll
            for (int kt = 0; kt < 4; kt++) {
#pragma unroll
                for (int j = 0; j < 4; j++) {
                    const int n  = (2 * j + lmh) * 8 + lr;
                    const int lg = 2 * kt + lml;
                    uint32_t f0, f1, f2, f3;
                    ldsm_x4(f0, f1, f2, f3,
                            vtSt + (uint32_t)(n * 128 + ((lg ^ (n & 7)) << 4)));
                    mma_f16(o[2*j][0], o[2*j][1], o[2*j][2], o[2*j][3],
                            ap[kt][0], ap[kt][1], ap[kt][2], ap[kt][3], f0, f1);
                    mma_f16(o[2*j+1][0], o[2*j+1][1], o[2*j+1][2], o[2*j+1][3],
                            ap[kt][0], ap[kt][1], ap[kt][2], ap[kt][3], f2, f3);
                }
            }
            __syncthreads();
        }

        l0 += __shfl_xor_sync(0xffffffffu, l0, 1);
        l0 += __shfl_xor_sync(0xffffffffu, l0, 2);
        l1 += __shfl_xor_sync(0xffffffffu, l1, 1);
        l1 += __shfl_xor_sync(0xffffffffu, l1, 2);
        const float inv0 = coef / l0;
        const float inv1 = coef / l1;
#pragma unroll
        for (int nt = 0; nt < 8; nt++) {
            outc[nt][0] += o[nt][0] * inv0;
            outc[nt][1] += o[nt][1] * inv0;
            outc[nt][2] += o[nt][2] * inv1;
            outc[nt][3] += o[nt][3] * inv1;
        }
    }

    float* ob = At + ((size_t)(b * TQc + row0)) * Dc + h * HDc;
#pragma unroll
    for (int nt = 0; nt < 8; nt++) {
        const int col = nt * 8 + 2 * cc;
        *reinterpret_cast<float2*>(ob + col) = make_float2(outc[nt][0], outc[nt][1]);
        *reinterpret_cast<float2*>(ob + 8 * (size_t)Dc + col) = make_float2(outc[nt][2], outc[nt][3]);
    }
}

// ---------------------------------------------------------------------------
// kernel_launch
// ---------------------------------------------------------------------------
extern "C" void kernel_launch(void* const* d_in, const int* in_sizes, int n_in,
                              void* d_out, int out_size)
{
    const float* q    = (const float*)d_in[0];
    const float* kv   = (const float*)d_in[1];
    const float* Wq   = (const float*)d_in[2];
    const float* bq   = (const float*)d_in[3];
    const float* Wk   = (const float*)d_in[4];
    const float* bk   = (const float*)d_in[5];
    const float* Wv   = (const float*)d_in[6];
    const float* bv   = (const float*)d_in[7];
    const float* Wo   = (const float*)d_in[8];
    const float* bo   = (const float*)d_in[9];
    const float* abA  = (const float*)d_in[10];
    const float* abI  = (const float*)d_in[11];
    const float* logt = (const float*)d_in[12];
    const int*   pNA  = (const int*)d_in[13];
    float* out = (float*)d_out;

    void *pQp, *pA16, *pWk16, *pWv16, *pKh, *pVt, *pAt;
    cudaGetSymbolAddress(&pQp,   g_Qp);
    cudaGetSymbolAddress(&pA16,  g_A16);
    cudaGetSymbolAddress(&pWk16, g_Wk16);
    cudaGetSymbolAddress(&pWv16, g_Wv16);
    cudaGetSymbolAddress(&pKh,   g_Kh);
    cudaGetSymbolAddress(&pVt,   g_Vt);
    cudaGetSymbolAddress(&pAt,   g_At);

    // opt-in to >48KB dynamic smem for the pipelined kvgemm
    cudaFuncSetAttribute(kvgemm, cudaFuncAttributeMaxDynamicSharedMemorySize,
                         KV_SMEM_BYTES);

    const dim3 gblk(256);

    prep_kv<<<(Bc * TKc * Dc) / (256 * 8), gblk>>>(kv, abA, abI, pNA, (__half*)pA16);
    prep_w2<<<dim3((Dc * Dc) / (256 * 8), 2), gblk>>>(
        Wk, Wv, (__half*)pWk16, (__half*)pWv16);

    gemm16b<<<dim3(Dc / 128, (Bc * TQc) / 64), gblk>>>(
        q, Wq, bq, (float*)pQp, Bc * TQc, Dc, Dc);

    // cp.async 3-stage fused K+V projection (K row-major, V transposed)
    kvgemm<<<dim3(Dc / 128, (Bc * TKc) / 128), dim3(512), KV_SMEM_BYTES>>>(
        (const __half*)pA16, (const __half*)pWk16, (const __half*)pWv16,
        bk, bv, (__half*)pKh, (__half*)pVt);

    attn_f16<<<dim3(TQc / 128, NHc, Bc), gblk>>>(
        (const float*)pQp, (const __half*)pKh, (const __half*)pVt, (float*)pAt,
        logt, pNA);

    gemm16b<<<dim3(Dc / 128, (Bc * TQc) / 64), gblk>>>(
        (const float*)pAt, Wo, bo, out, Bc * TQc, Dc, Dc);
}